// round 2
// baseline (speedup 1.0000x reference)
#include <cuda_runtime.h>
#include <cuda_bf16.h>
#include <cstdint>
#include <cstddef>

typedef unsigned long long ull;

#define NA_MAX 300000
#define NP_MAX 150000
#define ND_MAX 80000
#define E_MAX  1000000

// ---------------- device scratch (no allocation allowed) ----------------
__device__ float g_hp[(size_t)NP_MAX * 128];
__device__ float g_hd[(size_t)ND_MAX * 128];
__device__ float g_as_pa[(size_t)NP_MAX * 8];
__device__ float g_as_da[(size_t)ND_MAX * 8];
__device__ float g_ad[(size_t)NA_MAX * 16];       // [n][t*8+h]
__device__ float g_s_pa[(size_t)NA_MAX * 8];
__device__ float g_s_da[(size_t)NA_MAX * 8];
__device__ float g_ev_pa[(size_t)E_MAX * 8];
__device__ float g_ev_da[(size_t)E_MAX * 8];
__device__ float g_o_pa[(size_t)NA_MAX * 128];
__device__ float g_o_da[(size_t)NA_MAX * 128];
__device__ float g_wpart[256];
__device__ float g_beta[2];
__device__ float g_weff_a[128 * 16];
__device__ float g_weff_p[64 * 8];
__device__ float g_weff_d[64 * 8];
__device__ float g_boff_a[16];
__device__ float g_boff_p[8];
__device__ float g_boff_d[8];

// ---------------- helpers ----------------
__device__ __forceinline__ ull pack2(float lo, float hi) {
    ull r; asm("mov.b64 %0, {%1,%2};" : "=l"(r) : "f"(lo), "f"(hi)); return r;
}
__device__ __forceinline__ void unpack2(ull v, float& lo, float& hi) {
    asm("mov.b64 {%0,%1}, %2;" : "=f"(lo), "=f"(hi) : "l"(v));
}
__device__ __forceinline__ void fma2(ull& d, ull a, ull b) {
    asm("fma.rn.f32x2 %0, %1, %2, %0;" : "+l"(d) : "l"(a), "l"(b));
}
__device__ __forceinline__ void red4(float* p, float a, float b, float c, float d) {
    asm volatile("red.global.add.v4.f32 [%0], {%1,%2,%3,%4};"
                 :: "l"(p), "f"(a), "f"(b), "f"(c), "f"(d) : "memory");
}
__device__ __forceinline__ float tanh_f(float x) {
    x = fminf(fmaxf(x, -12.f), 12.f);
    float t = __expf(2.f * x);
    return __fdividef(t - 1.f, t + 1.f);
}

// ---------------- K1: fold attention vectors into projection weights ----------------
__global__ void k_weff(const float* __restrict__ Wa, const float* __restrict__ ba,
                       const float* __restrict__ Wp, const float* __restrict__ bp,
                       const float* __restrict__ Wd, const float* __restrict__ bd,
                       const float* __restrict__ ats_pa, const float* __restrict__ atd_pa,
                       const float* __restrict__ ats_da, const float* __restrict__ atd_da) {
    int k = threadIdx.x;
    if (k < 128) {
        for (int t = 0; t < 2; t++) {
            const float* att = (t == 0) ? atd_pa : atd_da;
            for (int h = 0; h < 8; h++) {
                float s = 0.f;
                for (int d = 0; d < 16; d++) s += Wa[k * 128 + h * 16 + d] * att[h * 16 + d];
                g_weff_a[k * 16 + t * 8 + h] = s;
            }
        }
    }
    if (k < 64) {
        for (int h = 0; h < 8; h++) {
            float s = 0.f, s2 = 0.f;
            for (int d = 0; d < 16; d++) {
                s  += Wp[k * 128 + h * 16 + d] * ats_pa[h * 16 + d];
                s2 += Wd[k * 128 + h * 16 + d] * ats_da[h * 16 + d];
            }
            g_weff_p[k * 8 + h] = s;
            g_weff_d[k * 8 + h] = s2;
        }
    }
    if (k == 0) {
        for (int t = 0; t < 2; t++) {
            const float* att = (t == 0) ? atd_pa : atd_da;
            for (int h = 0; h < 8; h++) {
                float s = 0.f;
                for (int d = 0; d < 16; d++) s += ba[h * 16 + d] * att[h * 16 + d];
                g_boff_a[t * 8 + h] = s;
            }
        }
        for (int h = 0; h < 8; h++) {
            float s = 0.f, s2 = 0.f;
            for (int d = 0; d < 16; d++) {
                s  += bp[h * 16 + d] * ats_pa[h * 16 + d];
                s2 += bd[h * 16 + d] * ats_da[h * 16 + d];
            }
            g_boff_p[h] = s;
            g_boff_d[h] = s2;
        }
    }
}

// ---------------- K2: small-N GEMM (attention scalars) out[n,j] = x[n,:]@weff[:,j]+boff ----
template<int KD, int J>
__global__ __launch_bounds__(256) void k_smallgemm(
        const float* __restrict__ x, const float* __restrict__ weff,
        const float* __restrict__ boff, float* __restrict__ out, int N) {
    constexpr int KC = 32 / J;
    constexpr int KLEN = KD / KC;
    __shared__ float xs[8][KD];
    __shared__ float wt[J][KD];
    __shared__ float bo[J];
    int tid = threadIdx.x;
    for (int i = tid; i < J * KD; i += 256) {
        int j = i / KD, k = i % KD;
        wt[j][k] = weff[k * J + j];
    }
    if (tid < J) bo[tid] = boff[tid];
    __syncthreads();
    int w = tid >> 5, lane = tid & 31;
    int j = lane % J, kc = lane / J;
    int nwarps = (gridDim.x * 256) >> 5;
    for (int n = (blockIdx.x * 256 + tid) >> 5; n < N; n += nwarps) {
        if (lane < KD / 4)
            *(float4*)&xs[w][4 * lane] = *(const float4*)(x + (size_t)n * KD + 4 * lane);
        __syncwarp();
        float acc = 0.f;
        #pragma unroll
        for (int it = 0; it < KLEN / 4; it++) {
            int k = kc * KLEN + 4 * it;
            float4 xv = *(const float4*)&xs[w][k];
            float4 wv = *(const float4*)&wt[j][k];
            acc += xv.x * wv.x + xv.y * wv.y + xv.z * wv.z + xv.w * wv.w;
        }
        #pragma unroll
        for (int off = J; off < 32; off <<= 1)
            acc += __shfl_xor_sync(0xffffffffu, acc, off);
        if (lane < J) out[(size_t)n * J + lane] = acc + bo[lane];
        __syncwarp();
    }
}

// ---------------- K3: projection GEMM  h = x[N,64] @ W[64,128] + b ----------------
__global__ __launch_bounds__(256) void k_proj(
        const float* __restrict__ x, const float* __restrict__ W,
        const float* __restrict__ b, float* __restrict__ h, int N) {
    __shared__ float Ws[64][128];
    __shared__ float xs[32][64];
    __shared__ float bs[128];
    int tid = threadIdx.x;
    for (int i = tid; i < 2048; i += 256)
        *(float4*)&Ws[0][4 * i] = *(const float4*)&W[4 * i];
    if (tid < 128) bs[tid] = b[tid];
    int base = blockIdx.x * 32;
    for (int i = tid; i < 512; i += 256) {
        int r = (4 * i) / 64, c = (4 * i) % 64;
        float4 v = make_float4(0.f, 0.f, 0.f, 0.f);
        if (base + r < N) v = *(const float4*)&x[(size_t)(base + r) * 64 + c];
        *(float4*)&xs[r][c] = v;
    }
    __syncthreads();
    int rg = tid >> 4;          // rows 2rg, 2rg+1
    int cg = (tid & 15) * 8;    // 8 cols
    float acc0[8], acc1[8];
    #pragma unroll
    for (int c = 0; c < 8; c++) { acc0[c] = 0.f; acc1[c] = 0.f; }
    #pragma unroll 4
    for (int k = 0; k < 64; k++) {
        float x0 = xs[2 * rg][k], x1 = xs[2 * rg + 1][k];
        #pragma unroll
        for (int c = 0; c < 8; c++) {
            float w = Ws[k][cg + c];
            acc0[c] += x0 * w;
            acc1[c] += x1 * w;
        }
    }
    int r0 = base + 2 * rg;
    if (r0 < N) {
        #pragma unroll
        for (int c = 0; c < 8; c++) h[(size_t)r0 * 128 + cg + c] = acc0[c] + bs[cg + c];
    }
    if (r0 + 1 < N) {
        #pragma unroll
        for (int c = 0; c < 8; c++) h[(size_t)(r0 + 1) * 128 + cg + c] = acc1[c] + bs[cg + c];
    }
}

// ---------------- K4: edge pass A — exp(leaky(alpha)), accumulate denominators ----------
__global__ __launch_bounds__(256) void k_edgeA(
        const int* __restrict__ src, const int* __restrict__ dst,
        const float* __restrict__ as, const float* __restrict__ ad, int toff,
        float* __restrict__ ev, float* __restrict__ ssum, int E) {
    int e = blockIdx.x * 256 + threadIdx.x;
    if (e >= E) return;
    int s = src[e], d = dst[e];
    float4 a0 = *(const float4*)(as + (size_t)s * 8);
    float4 a1 = *(const float4*)(as + (size_t)s * 8 + 4);
    const float* adp = ad + (size_t)d * 16 + toff;
    float4 b0 = *(const float4*)(adp);
    float4 b1 = *(const float4*)(adp + 4);
    float v[8] = { a0.x + b0.x, a0.y + b0.y, a0.z + b0.z, a0.w + b0.w,
                   a1.x + b1.x, a1.y + b1.y, a1.z + b1.z, a1.w + b1.w };
    #pragma unroll
    for (int i = 0; i < 8; i++) {
        float a = v[i];
        a = (a >= 0.f) ? a : 0.2f * a;
        v[i] = __expf(a);
    }
    *(float4*)(ev + (size_t)e * 8)     = make_float4(v[0], v[1], v[2], v[3]);
    *(float4*)(ev + (size_t)e * 8 + 4) = make_float4(v[4], v[5], v[6], v[7]);
    red4(ssum + (size_t)d * 8,     v[0], v[1], v[2], v[3]);
    red4(ssum + (size_t)d * 8 + 4, v[4], v[5], v[6], v[7]);
}

// ---------------- K5: invert denominators ----------------
__global__ void k_inv(float* __restrict__ s0, float* __restrict__ s1, int n) {
    int i = blockIdx.x * 256 + threadIdx.x;
    if (i < n) {
        s0[i] = __fdividef(1.f, s0[i] + 1e-16f);
        s1[i] = __fdividef(1.f, s1[i] + 1e-16f);
    }
}

// ---------------- K6: edge pass B — weighted scatter of messages ----------------
__global__ __launch_bounds__(256) void k_edgeB(
        const int* __restrict__ src, const int* __restrict__ dst,
        const float* __restrict__ h, const float* __restrict__ ev,
        const float* __restrict__ sinv, float* __restrict__ o, int E) {
    int gw = (blockIdx.x * 256 + threadIdx.x) >> 5;
    if (gw >= E) return;
    int lane = threadIdx.x & 31;
    int s = src[gw], d = dst[gw];
    int head = lane >> 2;
    float a = ev[(size_t)gw * 8 + head] * sinv[(size_t)d * 8 + head];
    float4 m = *(const float4*)(h + (size_t)s * 128 + lane * 4);
    red4(o + (size_t)d * 128 + lane * 4, m.x * a, m.y * a, m.z * a, m.w * a);
}

// ---------------- K7: relu(o) in place + column sums of tanh(o@Wk+bk) ----------------
#define SEM_SMEM_FLOATS (16384 + 128 * 68 + 128 + 128)
__global__ __launch_bounds__(256) void k_sem(
        float* __restrict__ o, const float* __restrict__ Wk,
        const float* __restrict__ bk, float* __restrict__ wpart, int N) {
    extern __shared__ float sm[];
    float* Ws     = sm;               // 128*128
    float* rT     = sm + 16384;       // [128][68] transposed row tile
    float* bks    = rT + 128 * 68;    // 128
    float* colacc = bks + 128;        // 128
    int tid = threadIdx.x;
    for (int i = tid; i < 4096; i += 256)
        *(float4*)&Ws[4 * i] = *(const float4*)&Wk[4 * i];
    if (tid < 128) { bks[tid] = bk[tid]; colacc[tid] = 0.f; }
    int base = blockIdx.x * 64;
    for (int i = tid; i < 2048; i += 256) {
        int r = i >> 5, c4 = (i & 31) * 4;
        int gr = base + r;
        float4 v = make_float4(0.f, 0.f, 0.f, 0.f);
        if (gr < N) {
            v = *(const float4*)&o[(size_t)gr * 128 + c4];
            v.x = fmaxf(v.x, 0.f); v.y = fmaxf(v.y, 0.f);
            v.z = fmaxf(v.z, 0.f); v.w = fmaxf(v.w, 0.f);
            *(float4*)&o[(size_t)gr * 128 + c4] = v;
        }
        rT[(c4 + 0) * 68 + r] = v.x;
        rT[(c4 + 1) * 68 + r] = v.y;
        rT[(c4 + 2) * 68 + r] = v.z;
        rT[(c4 + 3) * 68 + r] = v.w;
    }
    __syncthreads();
    int rg = tid & 15;    // rows 4rg..4rg+3
    int cg = tid >> 4;    // cols cg*8..cg*8+7
    ull acc[4][4];
    #pragma unroll
    for (int r = 0; r < 4; r++)
        #pragma unroll
        for (int c = 0; c < 4; c++) acc[r][c] = pack2(0.f, 0.f);
    #pragma unroll 2
    for (int k = 0; k < 128; k++) {
        float4 rv = *(const float4*)&rT[k * 68 + 4 * rg];
        float4 w0 = *(const float4*)&Ws[k * 128 + cg * 8];
        float4 w1 = *(const float4*)&Ws[k * 128 + cg * 8 + 4];
        ull wp[4] = { pack2(w0.x, w0.y), pack2(w0.z, w0.w),
                      pack2(w1.x, w1.y), pack2(w1.z, w1.w) };
        ull rr[4] = { pack2(rv.x, rv.x), pack2(rv.y, rv.y),
                      pack2(rv.z, rv.z), pack2(rv.w, rv.w) };
        #pragma unroll
        for (int r = 0; r < 4; r++)
            #pragma unroll
            for (int c = 0; c < 4; c++) fma2(acc[r][c], rr[r], wp[c]);
    }
    float colsum[8];
    #pragma unroll
    for (int c = 0; c < 8; c++) colsum[c] = 0.f;
    #pragma unroll
    for (int r = 0; r < 4; r++) {
        if (base + 4 * rg + r < N) {
            #pragma unroll
            for (int cp = 0; cp < 4; cp++) {
                float y0, y1;
                unpack2(acc[r][cp], y0, y1);
                int col = cg * 8 + 2 * cp;
                colsum[2 * cp]     += tanh_f(y0 + bks[col]);
                colsum[2 * cp + 1] += tanh_f(y1 + bks[col + 1]);
            }
        }
    }
    #pragma unroll
    for (int c = 0; c < 8; c++) atomicAdd(&colacc[cg * 8 + c], colsum[c]);
    __syncthreads();
    if (tid < 128) atomicAdd(&wpart[tid], colacc[tid]);
}

// ---------------- K8: semantic softmax (beta) ----------------
__global__ void k_beta(const float* __restrict__ wpart, const float* __restrict__ q,
                       float invN, float* __restrict__ beta) {
    __shared__ float sh[8];
    int tid = threadIdx.x;  // 128
    float qv = q[tid];
    float v0 = wpart[tid] * invN * qv;
    float v1 = wpart[128 + tid] * invN * qv;
    #pragma unroll
    for (int o = 16; o; o >>= 1) {
        v0 += __shfl_xor_sync(0xffffffffu, v0, o);
        v1 += __shfl_xor_sync(0xffffffffu, v1, o);
    }
    int w = tid >> 5;
    if ((tid & 31) == 0) { sh[w] = v0; sh[4 + w] = v1; }
    __syncthreads();
    if (tid == 0) {
        float s0 = sh[0] + sh[1] + sh[2] + sh[3];
        float s1 = sh[4] + sh[5] + sh[6] + sh[7];
        float m = fmaxf(s0, s1);
        float e0 = __expf(s0 - m), e1 = __expf(s1 - m);
        float inv = 1.f / (e0 + e1);
        beta[0] = e0 * inv;
        beta[1] = e1 * inv;
    }
}

// ---------------- K9: combine + classifier + softmax ----------------
__global__ __launch_bounds__(256) void k_final(
        const float* __restrict__ opa, const float* __restrict__ oda,
        const float* __restrict__ Wl, const float* __restrict__ bl,
        const float* __restrict__ beta, float* __restrict__ out, int N) {
    __shared__ float w0s[128], w1s[128];
    int tid = threadIdx.x;
    if (tid < 128) { w0s[tid] = Wl[tid * 2]; w1s[tid] = Wl[tid * 2 + 1]; }
    __syncthreads();
    int n = (blockIdx.x * 256 + tid) >> 5;
    if (n >= N) return;
    int lane = tid & 31;
    float b0 = beta[0], b1 = beta[1];
    float4 pa = *(const float4*)(opa + (size_t)n * 128 + lane * 4);
    float4 da = *(const float4*)(oda + (size_t)n * 128 + lane * 4);
    float sx = b0 * pa.x + b1 * da.x;
    float sy = b0 * pa.y + b1 * da.y;
    float sz = b0 * pa.z + b1 * da.z;
    float sw = b0 * pa.w + b1 * da.w;
    int k = lane * 4;
    float l0 = sx * w0s[k] + sy * w0s[k + 1] + sz * w0s[k + 2] + sw * w0s[k + 3];
    float l1 = sx * w1s[k] + sy * w1s[k + 1] + sz * w1s[k + 2] + sw * w1s[k + 3];
    #pragma unroll
    for (int o = 16; o; o >>= 1) {
        l0 += __shfl_xor_sync(0xffffffffu, l0, o);
        l1 += __shfl_xor_sync(0xffffffffu, l1, o);
    }
    if (lane == 0) {
        l0 += bl[0];
        l1 += bl[1];
        float m = fmaxf(l0, l1);
        float e0 = __expf(l0 - m), e1 = __expf(l1 - m);
        float inv = 1.f / (e0 + e1);
        out[(size_t)n * 2]     = e0 * inv;
        out[(size_t)n * 2 + 1] = e1 * inv;
    }
}

// ---------------- launch ----------------
extern "C" void kernel_launch(void* const* d_in, const int* in_sizes, int n_in,
                              void* d_out, int out_size) {
    const float* x_adm  = (const float*)d_in[0];
    const float* x_pat  = (const float*)d_in[1];
    const float* x_diag = (const float*)d_in[2];
    const int* e_pa_src = (const int*)d_in[3];
    const int* e_pa_dst = (const int*)d_in[4];
    const int* e_da_src = (const int*)d_in[5];
    const int* e_da_dst = (const int*)d_in[6];
    const float* Wa = (const float*)d_in[7];
    const float* ba = (const float*)d_in[8];
    const float* Wp = (const float*)d_in[9];
    const float* bp = (const float*)d_in[10];
    const float* Wd = (const float*)d_in[11];
    const float* bd = (const float*)d_in[12];
    const float* ats_pa = (const float*)d_in[13];
    const float* atd_pa = (const float*)d_in[14];
    const float* ats_da = (const float*)d_in[15];
    const float* atd_da = (const float*)d_in[16];
    const float* Wk = (const float*)d_in[17];
    const float* bk = (const float*)d_in[18];
    const float* q  = (const float*)d_in[19];
    const float* Wl = (const float*)d_in[20];
    const float* bl = (const float*)d_in[21];
    float* out = (float*)d_out;

    int Na = in_sizes[0] / 128;
    int Np = in_sizes[1] / 64;
    int Nd = in_sizes[2] / 64;
    int E1 = in_sizes[3];
    int E2 = in_sizes[5];

    // symbol addresses
    void *p_hp, *p_hd, *p_as_pa, *p_as_da, *p_ad, *p_s_pa, *p_s_da;
    void *p_ev_pa, *p_ev_da, *p_o_pa, *p_o_da, *p_wpart, *p_beta;
    void *p_weff_a, *p_weff_p, *p_weff_d, *p_boff_a, *p_boff_p, *p_boff_d;
    cudaGetSymbolAddress(&p_hp, g_hp);
    cudaGetSymbolAddress(&p_hd, g_hd);
    cudaGetSymbolAddress(&p_as_pa, g_as_pa);
    cudaGetSymbolAddress(&p_as_da, g_as_da);
    cudaGetSymbolAddress(&p_ad, g_ad);
    cudaGetSymbolAddress(&p_s_pa, g_s_pa);
    cudaGetSymbolAddress(&p_s_da, g_s_da);
    cudaGetSymbolAddress(&p_ev_pa, g_ev_pa);
    cudaGetSymbolAddress(&p_ev_da, g_ev_da);
    cudaGetSymbolAddress(&p_o_pa, g_o_pa);
    cudaGetSymbolAddress(&p_o_da, g_o_da);
    cudaGetSymbolAddress(&p_wpart, g_wpart);
    cudaGetSymbolAddress(&p_beta, g_beta);
    cudaGetSymbolAddress(&p_weff_a, g_weff_a);
    cudaGetSymbolAddress(&p_weff_p, g_weff_p);
    cudaGetSymbolAddress(&p_weff_d, g_weff_d);
    cudaGetSymbolAddress(&p_boff_a, g_boff_a);
    cudaGetSymbolAddress(&p_boff_p, g_boff_p);
    cudaGetSymbolAddress(&p_boff_d, g_boff_d);

    // zero accumulators (graph-capturable async memsets, default stream)
    cudaMemsetAsync(p_s_pa, 0, (size_t)Na * 8 * sizeof(float));
    cudaMemsetAsync(p_s_da, 0, (size_t)Na * 8 * sizeof(float));
    cudaMemsetAsync(p_o_pa, 0, (size_t)Na * 128 * sizeof(float));
    cudaMemsetAsync(p_o_da, 0, (size_t)Na * 128 * sizeof(float));
    cudaMemsetAsync(p_wpart, 0, 256 * sizeof(float));

    // K1: fold weights
    k_weff<<<1, 128>>>(Wa, ba, Wp, bp, Wd, bd, ats_pa, atd_pa, ats_da, atd_da);

    // K2: attention scalars
    k_smallgemm<128, 16><<<(Na + 7) / 8, 256>>>(
        x_adm, (const float*)p_weff_a, (const float*)p_boff_a, (float*)p_ad, Na);
    k_smallgemm<64, 8><<<(Np + 7) / 8, 256>>>(
        x_pat, (const float*)p_weff_p, (const float*)p_boff_p, (float*)p_as_pa, Np);
    k_smallgemm<64, 8><<<(Nd + 7) / 8, 256>>>(
        x_diag, (const float*)p_weff_d, (const float*)p_boff_d, (float*)p_as_da, Nd);

    // K3: projections (source node types only)
    k_proj<<<(Np + 31) / 32, 256>>>(x_pat, Wp, bp, (float*)p_hp, Np);
    k_proj<<<(Nd + 31) / 32, 256>>>(x_diag, Wd, bd, (float*)p_hd, Nd);

    // K4: edge pass A
    k_edgeA<<<(E1 + 255) / 256, 256>>>(e_pa_src, e_pa_dst, (const float*)p_as_pa,
        (const float*)p_ad, 0, (float*)p_ev_pa, (float*)p_s_pa, E1);
    k_edgeA<<<(E2 + 255) / 256, 256>>>(e_da_src, e_da_dst, (const float*)p_as_da,
        (const float*)p_ad, 8, (float*)p_ev_da, (float*)p_s_da, E2);

    // K5: invert denominators
    k_inv<<<(Na * 8 + 255) / 256, 256>>>((float*)p_s_pa, (float*)p_s_da, Na * 8);

    // K6: edge pass B (warp per edge)
    k_edgeB<<<(E1 + 7) / 8, 256>>>(e_pa_src, e_pa_dst, (const float*)p_hp,
        (const float*)p_ev_pa, (const float*)p_s_pa, (float*)p_o_pa, E1);
    k_edgeB<<<(E2 + 7) / 8, 256>>>(e_da_src, e_da_dst, (const float*)p_hd,
        (const float*)p_ev_da, (const float*)p_s_da, (float*)p_o_da, E2);

    // K7: relu + semantic GEMM column sums
    size_t sem_smem = SEM_SMEM_FLOATS * sizeof(float);
    cudaFuncSetAttribute(k_sem, cudaFuncAttributeMaxDynamicSharedMemorySize, (int)sem_smem);
    k_sem<<<(Na + 63) / 64, 256, sem_smem>>>((float*)p_o_pa, Wk, bk, (float*)p_wpart, Na);
    k_sem<<<(Na + 63) / 64, 256, sem_smem>>>((float*)p_o_da, Wk, bk, ((float*)p_wpart) + 128, Na);

    // K8: beta
    k_beta<<<1, 128>>>((const float*)p_wpart, q, 1.0f / (float)Na, (float*)p_beta);

    // K9: final
    k_final<<<(Na + 7) / 8, 256>>>((const float*)p_o_pa, (const float*)p_o_da,
        Wl, bl, (const float*)p_beta, out, Na);
}

// round 3
// speedup vs baseline: 1.4621x; 1.4621x over previous
#include <cuda_runtime.h>
#include <cuda_bf16.h>
#include <cstdint>
#include <cstddef>

typedef unsigned long long ull;

#define NA_MAX 300000
#define NP_MAX 150000
#define ND_MAX 80000
#define E_MAX  1000000

// ---------------- device scratch ----------------
__device__ float g_hp[(size_t)NP_MAX * 128];
__device__ float g_hd[(size_t)ND_MAX * 128];
__device__ float g_as_pa[(size_t)NP_MAX * 8];
__device__ float g_as_da[(size_t)ND_MAX * 8];
__device__ float g_ad[(size_t)NA_MAX * 16];       // [n][t*8+h]
__device__ float g_o_pa[(size_t)NA_MAX * 128];
__device__ float g_o_da[(size_t)NA_MAX * 128];
__device__ float g_wpart[256];
__device__ float g_beta[2];
__device__ float g_weff_a[128 * 16];
__device__ float g_weff_p[64 * 8];
__device__ float g_weff_d[64 * 8];
__device__ float g_boff_a[16];
__device__ float g_boff_p[8];
__device__ float g_boff_d[8];
// CSR scratch (reused by both metapaths sequentially)
__device__ int g_deg[NA_MAX];
__device__ int g_part[NA_MAX];
__device__ int g_csum[512];
__device__ int g_off[NA_MAX];
__device__ int g_cur[NA_MAX];
__device__ int g_csr[E_MAX];

// ---------------- helpers ----------------
__device__ __forceinline__ ull pack2(float lo, float hi) {
    ull r; asm("mov.b64 %0, {%1,%2};" : "=l"(r) : "f"(lo), "f"(hi)); return r;
}
__device__ __forceinline__ void unpack2(ull v, float& lo, float& hi) {
    asm("mov.b64 {%0,%1}, %2;" : "=f"(lo), "=f"(hi) : "l"(v));
}
__device__ __forceinline__ void fma2(ull& d, ull a, ull b) {
    asm("fma.rn.f32x2 %0, %1, %2, %0;" : "+l"(d) : "l"(a), "l"(b));
}
__device__ __forceinline__ float tanh_f(float x) {
    x = fminf(fmaxf(x, -12.f), 12.f);
    float t = __expf(2.f * x);
    return __fdividef(t - 1.f, t + 1.f);
}

// ---------------- K1: fold attention vectors into projection weights ----------------
__global__ void k_weff(const float* __restrict__ Wa, const float* __restrict__ ba,
                       const float* __restrict__ Wp, const float* __restrict__ bp,
                       const float* __restrict__ Wd, const float* __restrict__ bd,
                       const float* __restrict__ ats_pa, const float* __restrict__ atd_pa,
                       const float* __restrict__ ats_da, const float* __restrict__ atd_da) {
    int k = threadIdx.x;
    if (k < 128) {
        for (int t = 0; t < 2; t++) {
            const float* att = (t == 0) ? atd_pa : atd_da;
            for (int h = 0; h < 8; h++) {
                float s = 0.f;
                for (int d = 0; d < 16; d++) s += Wa[k * 128 + h * 16 + d] * att[h * 16 + d];
                g_weff_a[k * 16 + t * 8 + h] = s;
            }
        }
    }
    if (k < 64) {
        for (int h = 0; h < 8; h++) {
            float s = 0.f, s2 = 0.f;
            for (int d = 0; d < 16; d++) {
                s  += Wp[k * 128 + h * 16 + d] * ats_pa[h * 16 + d];
                s2 += Wd[k * 128 + h * 16 + d] * ats_da[h * 16 + d];
            }
            g_weff_p[k * 8 + h] = s;
            g_weff_d[k * 8 + h] = s2;
        }
    }
    if (k == 0) {
        for (int t = 0; t < 2; t++) {
            const float* att = (t == 0) ? atd_pa : atd_da;
            for (int h = 0; h < 8; h++) {
                float s = 0.f;
                for (int d = 0; d < 16; d++) s += ba[h * 16 + d] * att[h * 16 + d];
                g_boff_a[t * 8 + h] = s;
            }
        }
        for (int h = 0; h < 8; h++) {
            float s = 0.f, s2 = 0.f;
            for (int d = 0; d < 16; d++) {
                s  += bp[h * 16 + d] * ats_pa[h * 16 + d];
                s2 += bd[h * 16 + d] * ats_da[h * 16 + d];
            }
            g_boff_p[h] = s;
            g_boff_d[h] = s2;
        }
    }
}

// ---------------- K2: small-N GEMM, 4 nodes per warp iteration (MLP=4) ----------------
template<int KD, int J>
__global__ __launch_bounds__(256) void k_smallgemm(
        const float* __restrict__ x, const float* __restrict__ weff,
        const float* __restrict__ boff, float* __restrict__ out, int N) {
    constexpr int KC = 32 / J;
    constexpr int KLEN = KD / KC;
    __shared__ float xs[8][4][KD];
    __shared__ float wt[J][KD];
    __shared__ float bo[J];
    int tid = threadIdx.x;
    for (int i = tid; i < J * KD; i += 256) {
        int j = i / KD, k = i % KD;
        wt[j][k] = weff[k * J + j];
    }
    if (tid < J) bo[tid] = boff[tid];
    __syncthreads();
    int w = tid >> 5, lane = tid & 31;
    int j = lane % J, kc = lane / J;
    int nwarps = (gridDim.x * 256) >> 5;
    for (int base = (((blockIdx.x * 256 + tid) >> 5)) * 4; base < N; base += nwarps * 4) {
        #pragma unroll
        for (int t = 0; t < 4; t++) {
            int n = base + t;
            if (n < N && lane < KD / 4)
                *(float4*)&xs[w][t][4 * lane] = *(const float4*)(x + (size_t)n * KD + 4 * lane);
        }
        __syncwarp();
        #pragma unroll
        for (int t = 0; t < 4; t++) {
            int n = base + t;
            if (n >= N) break;
            float acc = 0.f;
            #pragma unroll
            for (int it = 0; it < KLEN / 4; it++) {
                int k = kc * KLEN + 4 * it;
                float4 xv = *(const float4*)&xs[w][t][k];
                float4 wv = *(const float4*)&wt[j][k];
                acc += xv.x * wv.x + xv.y * wv.y + xv.z * wv.z + xv.w * wv.w;
            }
            #pragma unroll
            for (int off = J; off < 32; off <<= 1)
                acc += __shfl_xor_sync(0xffffffffu, acc, off);
            if (lane < J) out[(size_t)n * J + lane] = acc + bo[lane];
        }
        __syncwarp();
    }
}

// ---------------- K3: projection GEMM  h = x[N,64] @ W[64,128] + b ----------------
__global__ __launch_bounds__(256) void k_proj(
        const float* __restrict__ x, const float* __restrict__ W,
        const float* __restrict__ b, float* __restrict__ h, int N) {
    __shared__ float Ws[64][128];
    __shared__ float xs[32][64];
    __shared__ float bs[128];
    int tid = threadIdx.x;
    for (int i = tid; i < 2048; i += 256)
        *(float4*)&Ws[0][4 * i] = *(const float4*)&W[4 * i];
    if (tid < 128) bs[tid] = b[tid];
    int base = blockIdx.x * 32;
    for (int i = tid; i < 512; i += 256) {
        int r = (4 * i) / 64, c = (4 * i) % 64;
        float4 v = make_float4(0.f, 0.f, 0.f, 0.f);
        if (base + r < N) v = *(const float4*)&x[(size_t)(base + r) * 64 + c];
        *(float4*)&xs[r][c] = v;
    }
    __syncthreads();
    int rg = tid >> 4;
    int cg = (tid & 15) * 8;
    float acc0[8], acc1[8];
    #pragma unroll
    for (int c = 0; c < 8; c++) { acc0[c] = 0.f; acc1[c] = 0.f; }
    #pragma unroll 4
    for (int k = 0; k < 64; k++) {
        float x0 = xs[2 * rg][k], x1 = xs[2 * rg + 1][k];
        #pragma unroll
        for (int c = 0; c < 8; c++) {
            float w = Ws[k][cg + c];
            acc0[c] += x0 * w;
            acc1[c] += x1 * w;
        }
    }
    int r0 = base + 2 * rg;
    if (r0 < N) {
        #pragma unroll
        for (int c = 0; c < 8; c++) h[(size_t)r0 * 128 + cg + c] = acc0[c] + bs[cg + c];
    }
    if (r0 + 1 < N) {
        #pragma unroll
        for (int c = 0; c < 8; c++) h[(size_t)(r0 + 1) * 128 + cg + c] = acc1[c] + bs[cg + c];
    }
}

// ---------------- CSR build ----------------
__global__ void k_hist(const int* __restrict__ dst, int* __restrict__ deg, int E) {
    int e = blockIdx.x * 256 + threadIdx.x;
    if (e < E) atomicAdd(&deg[dst[e]], 1);
}

// block = 256 threads, chunk = 1024 elements (4/thread)
__global__ void k_scan_a(const int* __restrict__ deg, int* __restrict__ part,
                         int* __restrict__ csum, int n) {
    __shared__ int wsum[8];
    int tid = threadIdx.x;
    int base = blockIdx.x * 1024 + tid * 4;
    int v0 = 0, v1 = 0, v2 = 0, v3 = 0;
    if (base + 0 < n) v0 = deg[base + 0];
    if (base + 1 < n) v1 = deg[base + 1];
    if (base + 2 < n) v2 = deg[base + 2];
    if (base + 3 < n) v3 = deg[base + 3];
    int s = v0 + v1 + v2 + v3;
    int incl = s;
    #pragma unroll
    for (int o = 1; o < 32; o <<= 1) {
        int t = __shfl_up_sync(0xffffffffu, incl, o);
        if ((tid & 31) >= o) incl += t;
    }
    if ((tid & 31) == 31) wsum[tid >> 5] = incl;
    __syncthreads();
    if (tid < 8) {
        int w = wsum[tid];
        #pragma unroll
        for (int o = 1; o < 8; o <<= 1) {
            int t = __shfl_up_sync(0xffu, w, o);
            if (tid >= o) w += t;
        }
        wsum[tid] = w;
    }
    __syncthreads();
    int blockoff = (tid >= 32) ? wsum[(tid >> 5) - 1] : 0;
    int excl = blockoff + incl - s;
    if (base + 0 < n) part[base + 0] = excl;
    if (base + 1 < n) part[base + 1] = excl + v0;
    if (base + 2 < n) part[base + 2] = excl + v0 + v1;
    if (base + 3 < n) part[base + 3] = excl + v0 + v1 + v2;
    if (tid == 255) csum[blockIdx.x] = blockoff + incl;
}

// single block, 512 threads; scans csum[nc] -> exclusive, nc <= 512
__global__ void k_scan_b(int* __restrict__ csum, int nc) {
    __shared__ int ws[16];
    int tid = threadIdx.x;
    int v = (tid < nc) ? csum[tid] : 0;
    int incl = v;
    #pragma unroll
    for (int o = 1; o < 32; o <<= 1) {
        int t = __shfl_up_sync(0xffffffffu, incl, o);
        if ((tid & 31) >= o) incl += t;
    }
    if ((tid & 31) == 31) ws[tid >> 5] = incl;
    __syncthreads();
    if (tid < 16) {
        int w = ws[tid];
        #pragma unroll
        for (int o = 1; o < 16; o <<= 1) {
            int t = __shfl_up_sync(0xffffu, w, o);
            if (tid >= o) w += t;
        }
        ws[tid] = w;
    }
    __syncthreads();
    int add = (tid >= 32) ? ws[(tid >> 5) - 1] : 0;
    incl += add;
    if (tid < nc) csum[tid] = incl - v;   // exclusive
}

__global__ void k_scan_c(const int* __restrict__ part, const int* __restrict__ csum,
                         int* __restrict__ off, int* __restrict__ cur, int n) {
    int i = blockIdx.x * 256 + threadIdx.x;
    if (i < n) {
        int o = part[i] + csum[i >> 10];
        off[i] = o;
        cur[i] = o;
    }
}

__global__ void k_scatter(const int* __restrict__ src, const int* __restrict__ dst,
                          int* __restrict__ cur, int* __restrict__ csr, int E) {
    int e = blockIdx.x * 256 + threadIdx.x;
    if (e < E) {
        int pos = atomicAdd(&cur[dst[e]], 1);
        csr[pos] = src[e];
    }
}

// ---------------- K6: fused softmax + aggregation + relu (warp per dst) ----------------
__global__ __launch_bounds__(256) void k_agg(
        const int* __restrict__ csr, const int* __restrict__ off, const int* __restrict__ deg,
        const float* __restrict__ as, const float* __restrict__ ad, int toff,
        const float* __restrict__ h, float* __restrict__ o, int N) {
    int d = (blockIdx.x * 256 + threadIdx.x) >> 5;
    if (d >= N) return;
    int lane = threadIdx.x & 31;
    int head = lane >> 2;
    float adv = ad[(size_t)d * 16 + toff + head];
    int st = off[d], dg = deg[d];
    float ax = 0.f, ay = 0.f, az = 0.f, aw = 0.f, den = 0.f;
    for (int i = 0; i < dg; i++) {
        int s = csr[st + i];
        float a = as[(size_t)s * 8 + head] + adv;
        a = (a >= 0.f) ? a : 0.2f * a;
        float wv = __expf(a);
        den += wv;
        float4 hv = *(const float4*)(h + (size_t)s * 128 + lane * 4);
        ax += wv * hv.x; ay += wv * hv.y; az += wv * hv.z; aw += wv * hv.w;
    }
    float inv = __fdividef(1.f, den + 1e-16f);
    float4 r = make_float4(fmaxf(ax * inv, 0.f), fmaxf(ay * inv, 0.f),
                           fmaxf(az * inv, 0.f), fmaxf(aw * inv, 0.f));
    *(float4*)(o + (size_t)d * 128 + lane * 4) = r;
}

// ---------------- K7: column sums of tanh(o@Wk+bk) (o already relu'd) ----------------
#define SEM_SMEM_FLOATS (16384 + 128 * 68 + 128 + 128)
__global__ __launch_bounds__(256) void k_sem(
        const float* __restrict__ o, const float* __restrict__ Wk,
        const float* __restrict__ bk, float* __restrict__ wpart, int N) {
    extern __shared__ float sm[];
    float* Ws     = sm;               // 128*128
    float* rT     = sm + 16384;       // [128][68]
    float* bks    = rT + 128 * 68;
    float* colacc = bks + 128;
    int tid = threadIdx.x;
    for (int i = tid; i < 4096; i += 256)
        *(float4*)&Ws[4 * i] = *(const float4*)&Wk[4 * i];
    if (tid < 128) { bks[tid] = bk[tid]; colacc[tid] = 0.f; }
    int base = blockIdx.x * 64;
    for (int i = tid; i < 2048; i += 256) {
        int r = i >> 5, c4 = (i & 31) * 4;
        int gr = base + r;
        float4 v = make_float4(0.f, 0.f, 0.f, 0.f);
        if (gr < N) v = *(const float4*)&o[(size_t)gr * 128 + c4];
        rT[(c4 + 0) * 68 + r] = v.x;
        rT[(c4 + 1) * 68 + r] = v.y;
        rT[(c4 + 2) * 68 + r] = v.z;
        rT[(c4 + 3) * 68 + r] = v.w;
    }
    __syncthreads();
    int rg = tid & 15;
    int cg = tid >> 4;
    ull acc[4][4];
    #pragma unroll
    for (int r = 0; r < 4; r++)
        #pragma unroll
        for (int c = 0; c < 4; c++) acc[r][c] = pack2(0.f, 0.f);
    #pragma unroll 2
    for (int k = 0; k < 128; k++) {
        float4 rv = *(const float4*)&rT[k * 68 + 4 * rg];
        float4 w0 = *(const float4*)&Ws[k * 128 + cg * 8];
        float4 w1 = *(const float4*)&Ws[k * 128 + cg * 8 + 4];
        ull wp[4] = { pack2(w0.x, w0.y), pack2(w0.z, w0.w),
                      pack2(w1.x, w1.y), pack2(w1.z, w1.w) };
        ull rr[4] = { pack2(rv.x, rv.x), pack2(rv.y, rv.y),
                      pack2(rv.z, rv.z), pack2(rv.w, rv.w) };
        #pragma unroll
        for (int r = 0; r < 4; r++)
            #pragma unroll
            for (int c = 0; c < 4; c++) fma2(acc[r][c], rr[r], wp[c]);
    }
    float colsum[8];
    #pragma unroll
    for (int c = 0; c < 8; c++) colsum[c] = 0.f;
    #pragma unroll
    for (int r = 0; r < 4; r++) {
        if (base + 4 * rg + r < N) {
            #pragma unroll
            for (int cp = 0; cp < 4; cp++) {
                float y0, y1;
                unpack2(acc[r][cp], y0, y1);
                int col = cg * 8 + 2 * cp;
                colsum[2 * cp]     += tanh_f(y0 + bks[col]);
                colsum[2 * cp + 1] += tanh_f(y1 + bks[col + 1]);
            }
        }
    }
    #pragma unroll
    for (int c = 0; c < 8; c++) atomicAdd(&colacc[cg * 8 + c], colsum[c]);
    __syncthreads();
    if (tid < 128) atomicAdd(&wpart[tid], colacc[tid]);
}

// ---------------- K8: semantic softmax (beta) ----------------
__global__ void k_beta(const float* __restrict__ wpart, const float* __restrict__ q,
                       float invN, float* __restrict__ beta) {
    __shared__ float sh[8];
    int tid = threadIdx.x;  // 128
    float qv = q[tid];
    float v0 = wpart[tid] * invN * qv;
    float v1 = wpart[128 + tid] * invN * qv;
    #pragma unroll
    for (int o = 16; o; o >>= 1) {
        v0 += __shfl_xor_sync(0xffffffffu, v0, o);
        v1 += __shfl_xor_sync(0xffffffffu, v1, o);
    }
    int w = tid >> 5;
    if ((tid & 31) == 0) { sh[w] = v0; sh[4 + w] = v1; }
    __syncthreads();
    if (tid == 0) {
        float s0 = sh[0] + sh[1] + sh[2] + sh[3];
        float s1 = sh[4] + sh[5] + sh[6] + sh[7];
        float m = fmaxf(s0, s1);
        float e0 = __expf(s0 - m), e1 = __expf(s1 - m);
        float inv = 1.f / (e0 + e1);
        beta[0] = e0 * inv;
        beta[1] = e1 * inv;
    }
}

// ---------------- K9: combine + classifier + softmax ----------------
__global__ __launch_bounds__(256) void k_final(
        const float* __restrict__ opa, const float* __restrict__ oda,
        const float* __restrict__ Wl, const float* __restrict__ bl,
        const float* __restrict__ beta, float* __restrict__ out, int N) {
    __shared__ float w0s[128], w1s[128];
    int tid = threadIdx.x;
    if (tid < 128) { w0s[tid] = Wl[tid * 2]; w1s[tid] = Wl[tid * 2 + 1]; }
    __syncthreads();
    int n = (blockIdx.x * 256 + tid) >> 5;
    if (n >= N) return;
    int lane = tid & 31;
    float b0 = beta[0], b1 = beta[1];
    float4 pa = *(const float4*)(opa + (size_t)n * 128 + lane * 4);
    float4 da = *(const float4*)(oda + (size_t)n * 128 + lane * 4);
    float sx = b0 * pa.x + b1 * da.x;
    float sy = b0 * pa.y + b1 * da.y;
    float sz = b0 * pa.z + b1 * da.z;
    float sw = b0 * pa.w + b1 * da.w;
    int k = lane * 4;
    float l0 = sx * w0s[k] + sy * w0s[k + 1] + sz * w0s[k + 2] + sw * w0s[k + 3];
    float l1 = sx * w1s[k] + sy * w1s[k + 1] + sz * w1s[k + 2] + sw * w1s[k + 3];
    #pragma unroll
    for (int o = 16; o; o >>= 1) {
        l0 += __shfl_xor_sync(0xffffffffu, l0, o);
        l1 += __shfl_xor_sync(0xffffffffu, l1, o);
    }
    if (lane == 0) {
        l0 += bl[0];
        l1 += bl[1];
        float m = fmaxf(l0, l1);
        float e0 = __expf(l0 - m), e1 = __expf(l1 - m);
        float inv = 1.f / (e0 + e1);
        out[(size_t)n * 2]     = e0 * inv;
        out[(size_t)n * 2 + 1] = e1 * inv;
    }
}

// ---------------- launch ----------------
extern "C" void kernel_launch(void* const* d_in, const int* in_sizes, int n_in,
                              void* d_out, int out_size) {
    const float* x_adm  = (const float*)d_in[0];
    const float* x_pat  = (const float*)d_in[1];
    const float* x_diag = (const float*)d_in[2];
    const int* e_pa_src = (const int*)d_in[3];
    const int* e_pa_dst = (const int*)d_in[4];
    const int* e_da_src = (const int*)d_in[5];
    const int* e_da_dst = (const int*)d_in[6];
    const float* Wa = (const float*)d_in[7];
    const float* ba = (const float*)d_in[8];
    const float* Wp = (const float*)d_in[9];
    const float* bp = (const float*)d_in[10];
    const float* Wd = (const float*)d_in[11];
    const float* bd = (const float*)d_in[12];
    const float* ats_pa = (const float*)d_in[13];
    const float* atd_pa = (const float*)d_in[14];
    const float* ats_da = (const float*)d_in[15];
    const float* atd_da = (const float*)d_in[16];
    const float* Wk = (const float*)d_in[17];
    const float* bk = (const float*)d_in[18];
    const float* q  = (const float*)d_in[19];
    const float* Wl = (const float*)d_in[20];
    const float* bl = (const float*)d_in[21];
    float* out = (float*)d_out;

    int Na = in_sizes[0] / 128;
    int Np = in_sizes[1] / 64;
    int Nd = in_sizes[2] / 64;
    int E1 = in_sizes[3];
    int E2 = in_sizes[5];

    void *p_hp, *p_hd, *p_as_pa, *p_as_da, *p_ad, *p_o_pa, *p_o_da, *p_wpart, *p_beta;
    void *p_weff_a, *p_weff_p, *p_weff_d, *p_boff_a, *p_boff_p, *p_boff_d;
    void *p_deg, *p_part, *p_csum, *p_off, *p_cur, *p_csr;
    cudaGetSymbolAddress(&p_hp, g_hp);
    cudaGetSymbolAddress(&p_hd, g_hd);
    cudaGetSymbolAddress(&p_as_pa, g_as_pa);
    cudaGetSymbolAddress(&p_as_da, g_as_da);
    cudaGetSymbolAddress(&p_ad, g_ad);
    cudaGetSymbolAddress(&p_o_pa, g_o_pa);
    cudaGetSymbolAddress(&p_o_da, g_o_da);
    cudaGetSymbolAddress(&p_wpart, g_wpart);
    cudaGetSymbolAddress(&p_beta, g_beta);
    cudaGetSymbolAddress(&p_weff_a, g_weff_a);
    cudaGetSymbolAddress(&p_weff_p, g_weff_p);
    cudaGetSymbolAddress(&p_weff_d, g_weff_d);
    cudaGetSymbolAddress(&p_boff_a, g_boff_a);
    cudaGetSymbolAddress(&p_boff_p, g_boff_p);
    cudaGetSymbolAddress(&p_boff_d, g_boff_d);
    cudaGetSymbolAddress(&p_deg, g_deg);
    cudaGetSymbolAddress(&p_part, g_part);
    cudaGetSymbolAddress(&p_csum, g_csum);
    cudaGetSymbolAddress(&p_off, g_off);
    cudaGetSymbolAddress(&p_cur, g_cur);
    cudaGetSymbolAddress(&p_csr, g_csr);

    int nchunks = (Na + 1023) / 1024;

    cudaMemsetAsync(p_wpart, 0, 256 * sizeof(float));

    // K1: fold weights
    k_weff<<<1, 128>>>(Wa, ba, Wp, bp, Wd, bd, ats_pa, atd_pa, ats_da, atd_da);

    // K2: attention scalars
    k_smallgemm<128, 16><<<(Na + 31) / 32, 256>>>(
        x_adm, (const float*)p_weff_a, (const float*)p_boff_a, (float*)p_ad, Na);
    k_smallgemm<64, 8><<<(Np + 31) / 32, 256>>>(
        x_pat, (const float*)p_weff_p, (const float*)p_boff_p, (float*)p_as_pa, Np);
    k_smallgemm<64, 8><<<(Nd + 31) / 32, 256>>>(
        x_diag, (const float*)p_weff_d, (const float*)p_boff_d, (float*)p_as_da, Nd);

    // K3: projections (source node types only)
    k_proj<<<(Np + 31) / 32, 256>>>(x_pat, Wp, bp, (float*)p_hp, Np);
    k_proj<<<(Nd + 31) / 32, 256>>>(x_diag, Wd, bd, (float*)p_hd, Nd);

    // ---- metapath pa ----
    cudaMemsetAsync(p_deg, 0, (size_t)Na * sizeof(int));
    k_hist<<<(E1 + 255) / 256, 256>>>(e_pa_dst, (int*)p_deg, E1);
    k_scan_a<<<nchunks, 256>>>((const int*)p_deg, (int*)p_part, (int*)p_csum, Na);
    k_scan_b<<<1, 512>>>((int*)p_csum, nchunks);
    k_scan_c<<<(Na + 255) / 256, 256>>>((const int*)p_part, (const int*)p_csum,
                                        (int*)p_off, (int*)p_cur, Na);
    k_scatter<<<(E1 + 255) / 256, 256>>>(e_pa_src, e_pa_dst, (int*)p_cur, (int*)p_csr, E1);
    k_agg<<<(Na * 32 + 255) / 256, 256>>>((const int*)p_csr, (const int*)p_off,
        (const int*)p_deg, (const float*)p_as_pa, (const float*)p_ad, 0,
        (const float*)p_hp, (float*)p_o_pa, Na);

    // ---- metapath da ----
    cudaMemsetAsync(p_deg, 0, (size_t)Na * sizeof(int));
    k_hist<<<(E2 + 255) / 256, 256>>>(e_da_dst, (int*)p_deg, E2);
    k_scan_a<<<nchunks, 256>>>((const int*)p_deg, (int*)p_part, (int*)p_csum, Na);
    k_scan_b<<<1, 512>>>((int*)p_csum, nchunks);
    k_scan_c<<<(Na + 255) / 256, 256>>>((const int*)p_part, (const int*)p_csum,
                                        (int*)p_off, (int*)p_cur, Na);
    k_scatter<<<(E2 + 255) / 256, 256>>>(e_da_src, e_da_dst, (int*)p_cur, (int*)p_csr, E2);
    k_agg<<<(Na * 32 + 255) / 256, 256>>>((const int*)p_csr, (const int*)p_off,
        (const int*)p_deg, (const float*)p_as_da, (const float*)p_ad, 8,
        (const float*)p_hd, (float*)p_o_da, Na);

    // K7: semantic GEMM column sums
    size_t sem_smem = SEM_SMEM_FLOATS * sizeof(float);
    cudaFuncSetAttribute(k_sem, cudaFuncAttributeMaxDynamicSharedMemorySize, (int)sem_smem);
    k_sem<<<(Na + 63) / 64, 256, sem_smem>>>((const float*)p_o_pa, Wk, bk, (float*)p_wpart, Na);
    k_sem<<<(Na + 63) / 64, 256, sem_smem>>>((const float*)p_o_da, Wk, bk, ((float*)p_wpart) + 128, Na);

    // K8: beta
    k_beta<<<1, 128>>>((const float*)p_wpart, q, 1.0f / (float)Na, (float*)p_beta);

    // K9: final
    k_final<<<(Na + 7) / 8, 256>>>((const float*)p_o_pa, (const float*)p_o_da,
        Wl, bl, (const float*)p_beta, out, Na);
}

// round 4
// speedup vs baseline: 2.2828x; 1.5613x over previous
#include <cuda_runtime.h>
#include <cuda_bf16.h>
#include <mma.h>
#include <cstdint>
#include <cstddef>

using namespace nvcuda;
typedef unsigned long long ull;

#define NA_MAX 300000
#define NP_MAX 150000
#define ND_MAX 80000
#define E_MAX  1000000

// ---------------- device scratch ----------------
__device__ float g_hp[(size_t)NP_MAX * 128];
__device__ float g_hd[(size_t)ND_MAX * 128];
__device__ float g_as_pa[(size_t)NP_MAX * 8];
__device__ float g_as_da[(size_t)ND_MAX * 8];
__device__ float g_ad[(size_t)NA_MAX * 16];       // [n][t*8+h]
__device__ float g_o_pa[(size_t)NA_MAX * 128];
__device__ float g_o_da[(size_t)NA_MAX * 128];
__device__ __nv_bfloat16 g_opa_bf[(size_t)NA_MAX * 128];
__device__ __nv_bfloat16 g_oda_bf[(size_t)NA_MAX * 128];
__device__ __nv_bfloat16 g_wk_bf[128 * 128];
__device__ float g_wpart[256];
__device__ float g_beta[2];
__device__ float g_weff_a[128 * 16];
__device__ float g_weff_p[64 * 8];
__device__ float g_weff_d[64 * 8];
__device__ float g_boff_a[16];
__device__ float g_boff_p[8];
__device__ float g_boff_d[8];
// CSR scratch (reused by both metapaths sequentially)
__device__ int g_deg[NA_MAX];
__device__ int g_part[NA_MAX];
__device__ int g_csum[512];
__device__ int g_off[NA_MAX];
__device__ int g_cur[NA_MAX];
__device__ int g_csr[E_MAX];

// ---------------- helpers ----------------
__device__ __forceinline__ float tanh_f(float x) {
    x = fminf(fmaxf(x, -12.f), 12.f);
    float t = __expf(2.f * x);
    return __fdividef(t - 1.f, t + 1.f);
}
__device__ __forceinline__ float leaky_exp(float a) {
    a = (a >= 0.f) ? a : 0.2f * a;
    return __expf(a);
}

// ---------------- K1: fold attention vectors into projection weights ----------------
__global__ void k_weff(const float* __restrict__ Wa, const float* __restrict__ ba,
                       const float* __restrict__ Wp, const float* __restrict__ bp,
                       const float* __restrict__ Wd, const float* __restrict__ bd,
                       const float* __restrict__ ats_pa, const float* __restrict__ atd_pa,
                       const float* __restrict__ ats_da, const float* __restrict__ atd_da) {
    int k = threadIdx.x;
    if (k < 128) {
        for (int t = 0; t < 2; t++) {
            const float* att = (t == 0) ? atd_pa : atd_da;
            for (int h = 0; h < 8; h++) {
                float s = 0.f;
                for (int d = 0; d < 16; d++) s += Wa[k * 128 + h * 16 + d] * att[h * 16 + d];
                g_weff_a[k * 16 + t * 8 + h] = s;
            }
        }
    }
    if (k < 64) {
        for (int h = 0; h < 8; h++) {
            float s = 0.f, s2 = 0.f;
            for (int d = 0; d < 16; d++) {
                s  += Wp[k * 128 + h * 16 + d] * ats_pa[h * 16 + d];
                s2 += Wd[k * 128 + h * 16 + d] * ats_da[h * 16 + d];
            }
            g_weff_p[k * 8 + h] = s;
            g_weff_d[k * 8 + h] = s2;
        }
    }
    if (k == 0) {
        for (int t = 0; t < 2; t++) {
            const float* att = (t == 0) ? atd_pa : atd_da;
            for (int h = 0; h < 8; h++) {
                float s = 0.f;
                for (int d = 0; d < 16; d++) s += ba[h * 16 + d] * att[h * 16 + d];
                g_boff_a[t * 8 + h] = s;
            }
        }
        for (int h = 0; h < 8; h++) {
            float s = 0.f, s2 = 0.f;
            for (int d = 0; d < 16; d++) {
                s  += bp[h * 16 + d] * ats_pa[h * 16 + d];
                s2 += bd[h * 16 + d] * ats_da[h * 16 + d];
            }
            g_boff_p[h] = s;
            g_boff_d[h] = s2;
        }
    }
}

// ---------------- K1b: Wk -> bf16 ----------------
__global__ void k_wkprep(const float* __restrict__ Wk, __nv_bfloat16* __restrict__ wkbf) {
    int i = blockIdx.x * 256 + threadIdx.x;
    if (i < 16384) wkbf[i] = __float2bfloat16(Wk[i]);
}

// ---------------- K2: small-N GEMM, 8 nodes per warp (MLP=8) ----------------
template<int KD, int J>
__global__ __launch_bounds__(256) void k_smallgemm(
        const float* __restrict__ x, const float* __restrict__ weff,
        const float* __restrict__ boff, float* __restrict__ out, int N) {
    constexpr int KC = 32 / J;
    constexpr int KLEN = KD / KC;
    __shared__ float xs[8][8][KD];
    __shared__ float wt[J][KD];
    __shared__ float bo[J];
    int tid = threadIdx.x;
    for (int i = tid; i < J * KD; i += 256) {
        int j = i / KD, k = i % KD;
        wt[j][k] = weff[k * J + j];
    }
    if (tid < J) bo[tid] = boff[tid];
    __syncthreads();
    int w = tid >> 5, lane = tid & 31;
    int j = lane % J, kc = lane / J;
    int base = (blockIdx.x * 8 + w) * 8;
    if (base >= N) return;
    #pragma unroll
    for (int t = 0; t < 8; t++) {
        int n = base + t;
        if (n < N && lane < KD / 4)
            *(float4*)&xs[w][t][4 * lane] = *(const float4*)(x + (size_t)n * KD + 4 * lane);
    }
    __syncwarp();
    #pragma unroll
    for (int t = 0; t < 8; t++) {
        int n = base + t;
        if (n >= N) break;
        float acc = 0.f;
        #pragma unroll
        for (int it = 0; it < KLEN / 4; it++) {
            int k = kc * KLEN + 4 * it;
            float4 xv = *(const float4*)&xs[w][t][k];
            float4 wv = *(const float4*)&wt[j][k];
            acc += xv.x * wv.x + xv.y * wv.y + xv.z * wv.z + xv.w * wv.w;
        }
        #pragma unroll
        for (int off = J; off < 32; off <<= 1)
            acc += __shfl_xor_sync(0xffffffffu, acc, off);
        if (lane < J) out[(size_t)n * J + lane] = acc + bo[lane];
    }
}

// ---------------- K3: projection GEMM  h = x[N,64] @ W[64,128] + b ----------------
__global__ __launch_bounds__(256) void k_proj(
        const float* __restrict__ x, const float* __restrict__ W,
        const float* __restrict__ b, float* __restrict__ h, int N) {
    __shared__ float Ws[64][128];
    __shared__ float xs[32][64];
    __shared__ float bs[128];
    int tid = threadIdx.x;
    for (int i = tid; i < 2048; i += 256)
        *(float4*)&Ws[0][4 * i] = *(const float4*)&W[4 * i];
    if (tid < 128) bs[tid] = b[tid];
    int base = blockIdx.x * 32;
    for (int i = tid; i < 512; i += 256) {
        int r = (4 * i) / 64, c = (4 * i) % 64;
        float4 v = make_float4(0.f, 0.f, 0.f, 0.f);
        if (base + r < N) v = *(const float4*)&x[(size_t)(base + r) * 64 + c];
        *(float4*)&xs[r][c] = v;
    }
    __syncthreads();
    int rg = tid >> 4;
    int cg = (tid & 15) * 8;
    float acc0[8], acc1[8];
    #pragma unroll
    for (int c = 0; c < 8; c++) { acc0[c] = 0.f; acc1[c] = 0.f; }
    #pragma unroll 4
    for (int k = 0; k < 64; k++) {
        float x0 = xs[2 * rg][k], x1 = xs[2 * rg + 1][k];
        #pragma unroll
        for (int c = 0; c < 8; c++) {
            float w = Ws[k][cg + c];
            acc0[c] += x0 * w;
            acc1[c] += x1 * w;
        }
    }
    int r0 = base + 2 * rg;
    if (r0 < N) {
        #pragma unroll
        for (int c = 0; c < 8; c++) h[(size_t)r0 * 128 + cg + c] = acc0[c] + bs[cg + c];
    }
    if (r0 + 1 < N) {
        #pragma unroll
        for (int c = 0; c < 8; c++) h[(size_t)(r0 + 1) * 128 + cg + c] = acc1[c] + bs[cg + c];
    }
}

// ---------------- CSR build ----------------
__global__ void k_hist(const int* __restrict__ dst, int* __restrict__ deg, int E) {
    int e = blockIdx.x * 256 + threadIdx.x;
    if (e < E) atomicAdd(&deg[dst[e]], 1);
}

__global__ void k_scan_a(const int* __restrict__ deg, int* __restrict__ part,
                         int* __restrict__ csum, int n) {
    __shared__ int wsum[8];
    int tid = threadIdx.x;
    int base = blockIdx.x * 1024 + tid * 4;
    int v0 = 0, v1 = 0, v2 = 0, v3 = 0;
    if (base + 0 < n) v0 = deg[base + 0];
    if (base + 1 < n) v1 = deg[base + 1];
    if (base + 2 < n) v2 = deg[base + 2];
    if (base + 3 < n) v3 = deg[base + 3];
    int s = v0 + v1 + v2 + v3;
    int incl = s;
    #pragma unroll
    for (int o = 1; o < 32; o <<= 1) {
        int t = __shfl_up_sync(0xffffffffu, incl, o);
        if ((tid & 31) >= o) incl += t;
    }
    if ((tid & 31) == 31) wsum[tid >> 5] = incl;
    __syncthreads();
    if (tid < 8) {
        int w = wsum[tid];
        #pragma unroll
        for (int o = 1; o < 8; o <<= 1) {
            int t = __shfl_up_sync(0xffu, w, o);
            if (tid >= o) w += t;
        }
        wsum[tid] = w;
    }
    __syncthreads();
    int blockoff = (tid >= 32) ? wsum[(tid >> 5) - 1] : 0;
    int excl = blockoff + incl - s;
    if (base + 0 < n) part[base + 0] = excl;
    if (base + 1 < n) part[base + 1] = excl + v0;
    if (base + 2 < n) part[base + 2] = excl + v0 + v1;
    if (base + 3 < n) part[base + 3] = excl + v0 + v1 + v2;
    if (tid == 255) csum[blockIdx.x] = blockoff + incl;
}

__global__ void k_scan_b(int* __restrict__ csum, int nc) {
    __shared__ int ws[16];
    int tid = threadIdx.x;
    int v = (tid < nc) ? csum[tid] : 0;
    int incl = v;
    #pragma unroll
    for (int o = 1; o < 32; o <<= 1) {
        int t = __shfl_up_sync(0xffffffffu, incl, o);
        if ((tid & 31) >= o) incl += t;
    }
    if ((tid & 31) == 31) ws[tid >> 5] = incl;
    __syncthreads();
    if (tid < 16) {
        int w = ws[tid];
        #pragma unroll
        for (int o = 1; o < 16; o <<= 1) {
            int t = __shfl_up_sync(0xffffu, w, o);
            if (tid >= o) w += t;
        }
        ws[tid] = w;
    }
    __syncthreads();
    int add = (tid >= 32) ? ws[(tid >> 5) - 1] : 0;
    incl += add;
    if (tid < nc) csum[tid] = incl - v;
}

__global__ void k_scan_c(const int* __restrict__ part, const int* __restrict__ csum,
                         int* __restrict__ off, int* __restrict__ cur, int n) {
    int i = blockIdx.x * 256 + threadIdx.x;
    if (i < n) {
        int o = part[i] + csum[i >> 10];
        off[i] = o;
        cur[i] = o;
    }
}

__global__ void k_scatter(const int* __restrict__ src, const int* __restrict__ dst,
                          int* __restrict__ cur, int* __restrict__ csr, int E) {
    int e = blockIdx.x * 256 + threadIdx.x;
    if (e < E) {
        int pos = atomicAdd(&cur[dst[e]], 1);
        csr[pos] = src[e];
    }
}

// ---------------- K6: fused softmax + aggregation + relu (warp per dst, MLP=4) --------
__global__ __launch_bounds__(256) void k_agg(
        const int* __restrict__ csr, const int* __restrict__ off, const int* __restrict__ deg,
        const float* __restrict__ as, const float* __restrict__ ad, int toff,
        const float* __restrict__ h, float* __restrict__ o,
        __nv_bfloat16* __restrict__ obf, int N) {
    int d = (blockIdx.x * 256 + threadIdx.x) >> 5;
    if (d >= N) return;
    int lane = threadIdx.x & 31;
    int head = lane >> 2;
    float adv = ad[(size_t)d * 16 + toff + head];
    int st = off[d], dg = deg[d];
    float ax = 0.f, ay = 0.f, az = 0.f, aw = 0.f, den = 0.f;
    int i = 0;
    for (; i + 4 <= dg; i += 4) {
        int s0 = csr[st + i], s1 = csr[st + i + 1], s2 = csr[st + i + 2], s3 = csr[st + i + 3];
        float e0 = as[(size_t)s0 * 8 + head];
        float e1 = as[(size_t)s1 * 8 + head];
        float e2 = as[(size_t)s2 * 8 + head];
        float e3 = as[(size_t)s3 * 8 + head];
        float4 h0 = *(const float4*)(h + (size_t)s0 * 128 + lane * 4);
        float4 h1 = *(const float4*)(h + (size_t)s1 * 128 + lane * 4);
        float4 h2 = *(const float4*)(h + (size_t)s2 * 128 + lane * 4);
        float4 h3 = *(const float4*)(h + (size_t)s3 * 128 + lane * 4);
        float w0 = leaky_exp(e0 + adv), w1 = leaky_exp(e1 + adv);
        float w2 = leaky_exp(e2 + adv), w3 = leaky_exp(e3 + adv);
        den += (w0 + w1) + (w2 + w3);
        ax += w0 * h0.x + w1 * h1.x + w2 * h2.x + w3 * h3.x;
        ay += w0 * h0.y + w1 * h1.y + w2 * h2.y + w3 * h3.y;
        az += w0 * h0.z + w1 * h1.z + w2 * h2.z + w3 * h3.z;
        aw += w0 * h0.w + w1 * h1.w + w2 * h2.w + w3 * h3.w;
    }
    for (; i < dg; i++) {
        int s = csr[st + i];
        float wv = leaky_exp(as[(size_t)s * 8 + head] + adv);
        den += wv;
        float4 hv = *(const float4*)(h + (size_t)s * 128 + lane * 4);
        ax += wv * hv.x; ay += wv * hv.y; az += wv * hv.z; aw += wv * hv.w;
    }
    float inv = __fdividef(1.f, den + 1e-16f);
    float4 r = make_float4(fmaxf(ax * inv, 0.f), fmaxf(ay * inv, 0.f),
                           fmaxf(az * inv, 0.f), fmaxf(aw * inv, 0.f));
    *(float4*)(o + (size_t)d * 128 + lane * 4) = r;
    __nv_bfloat162 b01 = __floats2bfloat162_rn(r.x, r.y);
    __nv_bfloat162 b23 = __floats2bfloat162_rn(r.z, r.w);
    uint2 pk;
    pk.x = *(unsigned int*)&b01;
    pk.y = *(unsigned int*)&b23;
    *(uint2*)(obf + (size_t)d * 128 + lane * 4) = pk;
}

// ---------------- K7: WMMA bf16 semantic GEMM + tanh column sums ----------------
#define SEMW_SMEM_BYTES (69632 + 1024)
__global__ __launch_bounds__(256) void k_semw(
        const __nv_bfloat16* __restrict__ o0, const __nv_bfloat16* __restrict__ o1,
        const __nv_bfloat16* __restrict__ wkbf, const float* __restrict__ bk,
        float* __restrict__ wpart, int N) {
    extern __shared__ char smw[];
    __nv_bfloat16* sA = (__nv_bfloat16*)smw;            // 128 x 136
    __nv_bfloat16* sB = (__nv_bfloat16*)(smw + 34816);  // 128 x 136
    float* sC = (float*)smw;                             // 128 x 132 (reuse)
    float* colacc = (float*)(smw + 69632);               // 128
    const __nv_bfloat16* obf = blockIdx.y ? o1 : o0;
    int tid = threadIdx.x;
    int base = blockIdx.x * 128;
    if (tid < 128) colacc[tid] = 0.f;
    #pragma unroll
    for (int it = 0; it < 8; it++) {
        int chunk = tid + it * 256;
        int k = chunk >> 4, n8 = (chunk & 15) * 8;
        *(uint4*)&sB[k * 136 + n8] = *(const uint4*)&wkbf[k * 128 + n8];
    }
    #pragma unroll
    for (int it = 0; it < 8; it++) {
        int chunk = tid + it * 256;
        int r = chunk >> 4, c8 = (chunk & 15) * 8;
        uint4 v = make_uint4(0u, 0u, 0u, 0u);
        if (base + r < N) v = *(const uint4*)&obf[(size_t)(base + r) * 128 + c8];
        *(uint4*)&sA[r * 136 + c8] = v;
    }
    __syncthreads();
    int w = tid >> 5;
    wmma::fragment<wmma::accumulator, 16, 16, 16, float> acc[8];
    #pragma unroll
    for (int c = 0; c < 8; c++) wmma::fill_fragment(acc[c], 0.f);
    #pragma unroll
    for (int k = 0; k < 8; k++) {
        wmma::fragment<wmma::matrix_a, 16, 16, 16, __nv_bfloat16, wmma::row_major> af;
        wmma::load_matrix_sync(af, &sA[(w * 16) * 136 + k * 16], 136);
        #pragma unroll
        for (int c = 0; c < 8; c++) {
            wmma::fragment<wmma::matrix_b, 16, 16, 16, __nv_bfloat16, wmma::row_major> bf;
            wmma::load_matrix_sync(bf, &sB[(k * 16) * 136 + c * 16], 136);
            wmma::mma_sync(acc[c], af, bf, acc[c]);
        }
    }
    __syncthreads();
    #pragma unroll
    for (int c = 0; c < 8; c++)
        wmma::store_matrix_sync(&sC[(w * 16) * 132 + c * 16], acc[c], 132, wmma::mem_row_major);
    __syncthreads();
    int col = tid & 127;
    int rs = (tid >> 7) * 64;
    int valid = N - base; if (valid > 128) valid = 128;
    float bkv = bk[col];
    float sum = 0.f;
    int rend = rs + 64; if (rend > valid) rend = valid;
    for (int r = rs; r < rend; r++)
        sum += tanh_f(sC[r * 132 + col] + bkv);
    atomicAdd(&colacc[col], sum);
    __syncthreads();
    if (tid < 128) atomicAdd(&wpart[blockIdx.y * 128 + tid], colacc[tid]);
}

// ---------------- K8: semantic softmax (beta) ----------------
__global__ void k_beta(const float* __restrict__ wpart, const float* __restrict__ q,
                       float invN, float* __restrict__ beta) {
    __shared__ float sh[8];
    int tid = threadIdx.x;  // 128
    float qv = q[tid];
    float v0 = wpart[tid] * invN * qv;
    float v1 = wpart[128 + tid] * invN * qv;
    #pragma unroll
    for (int o = 16; o; o >>= 1) {
        v0 += __shfl_xor_sync(0xffffffffu, v0, o);
        v1 += __shfl_xor_sync(0xffffffffu, v1, o);
    }
    int w = tid >> 5;
    if ((tid & 31) == 0) { sh[w] = v0; sh[4 + w] = v1; }
    __syncthreads();
    if (tid == 0) {
        float s0 = sh[0] + sh[1] + sh[2] + sh[3];
        float s1 = sh[4] + sh[5] + sh[6] + sh[7];
        float m = fmaxf(s0, s1);
        float e0 = __expf(s0 - m), e1 = __expf(s1 - m);
        float inv = 1.f / (e0 + e1);
        beta[0] = e0 * inv;
        beta[1] = e1 * inv;
    }
}

// ---------------- K9: combine + classifier + softmax ----------------
__global__ __launch_bounds__(256) void k_final(
        const float* __restrict__ opa, const float* __restrict__ oda,
        const float* __restrict__ Wl, const float* __restrict__ bl,
        const float* __restrict__ beta, float* __restrict__ out, int N) {
    __shared__ float w0s[128], w1s[128];
    int tid = threadIdx.x;
    if (tid < 128) { w0s[tid] = Wl[tid * 2]; w1s[tid] = Wl[tid * 2 + 1]; }
    __syncthreads();
    int n = (blockIdx.x * 256 + tid) >> 5;
    if (n >= N) return;
    int lane = tid & 31;
    float b0 = beta[0], b1 = beta[1];
    float4 pa = *(const float4*)(opa + (size_t)n * 128 + lane * 4);
    float4 da = *(const float4*)(oda + (size_t)n * 128 + lane * 4);
    float sx = b0 * pa.x + b1 * da.x;
    float sy = b0 * pa.y + b1 * da.y;
    float sz = b0 * pa.z + b1 * da.z;
    float sw = b0 * pa.w + b1 * da.w;
    int k = lane * 4;
    float l0 = sx * w0s[k] + sy * w0s[k + 1] + sz * w0s[k + 2] + sw * w0s[k + 3];
    float l1 = sx * w1s[k] + sy * w1s[k + 1] + sz * w1s[k + 2] + sw * w1s[k + 3];
    #pragma unroll
    for (int o = 16; o; o >>= 1) {
        l0 += __shfl_xor_sync(0xffffffffu, l0, o);
        l1 += __shfl_xor_sync(0xffffffffu, l1, o);
    }
    if (lane == 0) {
        l0 += bl[0];
        l1 += bl[1];
        float m = fmaxf(l0, l1);
        float e0 = __expf(l0 - m), e1 = __expf(l1 - m);
        float inv = 1.f / (e0 + e1);
        out[(size_t)n * 2]     = e0 * inv;
        out[(size_t)n * 2 + 1] = e1 * inv;
    }
}

// ---------------- launch ----------------
extern "C" void kernel_launch(void* const* d_in, const int* in_sizes, int n_in,
                              void* d_out, int out_size) {
    const float* x_adm  = (const float*)d_in[0];
    const float* x_pat  = (const float*)d_in[1];
    const float* x_diag = (const float*)d_in[2];
    const int* e_pa_src = (const int*)d_in[3];
    const int* e_pa_dst = (const int*)d_in[4];
    const int* e_da_src = (const int*)d_in[5];
    const int* e_da_dst = (const int*)d_in[6];
    const float* Wa = (const float*)d_in[7];
    const float* ba = (const float*)d_in[8];
    const float* Wp = (const float*)d_in[9];
    const float* bp = (const float*)d_in[10];
    const float* Wd = (const float*)d_in[11];
    const float* bd = (const float*)d_in[12];
    const float* ats_pa = (const float*)d_in[13];
    const float* atd_pa = (const float*)d_in[14];
    const float* ats_da = (const float*)d_in[15];
    const float* atd_da = (const float*)d_in[16];
    const float* Wk = (const float*)d_in[17];
    const float* bk = (const float*)d_in[18];
    const float* q  = (const float*)d_in[19];
    const float* Wl = (const float*)d_in[20];
    const float* bl = (const float*)d_in[21];
    float* out = (float*)d_out;

    int Na = in_sizes[0] / 128;
    int Np = in_sizes[1] / 64;
    int Nd = in_sizes[2] / 64;
    int E1 = in_sizes[3];
    int E2 = in_sizes[5];

    void *p_hp, *p_hd, *p_as_pa, *p_as_da, *p_ad, *p_o_pa, *p_o_da, *p_wpart, *p_beta;
    void *p_opa_bf, *p_oda_bf, *p_wk_bf;
    void *p_weff_a, *p_weff_p, *p_weff_d, *p_boff_a, *p_boff_p, *p_boff_d;
    void *p_deg, *p_part, *p_csum, *p_off, *p_cur, *p_csr;
    cudaGetSymbolAddress(&p_hp, g_hp);
    cudaGetSymbolAddress(&p_hd, g_hd);
    cudaGetSymbolAddress(&p_as_pa, g_as_pa);
    cudaGetSymbolAddress(&p_as_da, g_as_da);
    cudaGetSymbolAddress(&p_ad, g_ad);
    cudaGetSymbolAddress(&p_o_pa, g_o_pa);
    cudaGetSymbolAddress(&p_o_da, g_o_da);
    cudaGetSymbolAddress(&p_opa_bf, g_opa_bf);
    cudaGetSymbolAddress(&p_oda_bf, g_oda_bf);
    cudaGetSymbolAddress(&p_wk_bf, g_wk_bf);
    cudaGetSymbolAddress(&p_wpart, g_wpart);
    cudaGetSymbolAddress(&p_beta, g_beta);
    cudaGetSymbolAddress(&p_weff_a, g_weff_a);
    cudaGetSymbolAddress(&p_weff_p, g_weff_p);
    cudaGetSymbolAddress(&p_weff_d, g_weff_d);
    cudaGetSymbolAddress(&p_boff_a, g_boff_a);
    cudaGetSymbolAddress(&p_boff_p, g_boff_p);
    cudaGetSymbolAddress(&p_boff_d, g_boff_d);
    cudaGetSymbolAddress(&p_deg, g_deg);
    cudaGetSymbolAddress(&p_part, g_part);
    cudaGetSymbolAddress(&p_csum, g_csum);
    cudaGetSymbolAddress(&p_off, g_off);
    cudaGetSymbolAddress(&p_cur, g_cur);
    cudaGetSymbolAddress(&p_csr, g_csr);

    int nchunks = (Na + 1023) / 1024;

    cudaMemsetAsync(p_wpart, 0, 256 * sizeof(float));

    // K1: fold weights, Wk -> bf16
    k_weff<<<1, 128>>>(Wa, ba, Wp, bp, Wd, bd, ats_pa, atd_pa, ats_da, atd_da);
    k_wkprep<<<64, 256>>>(Wk, (__nv_bfloat16*)p_wk_bf);

    // K2: attention scalars
    k_smallgemm<128, 16><<<(Na + 63) / 64, 256>>>(
        x_adm, (const float*)p_weff_a, (const float*)p_boff_a, (float*)p_ad, Na);
    k_smallgemm<64, 8><<<(Np + 63) / 64, 256>>>(
        x_pat, (const float*)p_weff_p, (const float*)p_boff_p, (float*)p_as_pa, Np);
    k_smallgemm<64, 8><<<(Nd + 63) / 64, 256>>>(
        x_diag, (const float*)p_weff_d, (const float*)p_boff_d, (float*)p_as_da, Nd);

    // K3: projections (source node types only)
    k_proj<<<(Np + 31) / 32, 256>>>(x_pat, Wp, bp, (float*)p_hp, Np);
    k_proj<<<(Nd + 31) / 32, 256>>>(x_diag, Wd, bd, (float*)p_hd, Nd);

    // ---- metapath pa ----
    cudaMemsetAsync(p_deg, 0, (size_t)Na * sizeof(int));
    k_hist<<<(E1 + 255) / 256, 256>>>(e_pa_dst, (int*)p_deg, E1);
    k_scan_a<<<nchunks, 256>>>((const int*)p_deg, (int*)p_part, (int*)p_csum, Na);
    k_scan_b<<<1, 512>>>((int*)p_csum, nchunks);
    k_scan_c<<<(Na + 255) / 256, 256>>>((const int*)p_part, (const int*)p_csum,
                                        (int*)p_off, (int*)p_cur, Na);
    k_scatter<<<(E1 + 255) / 256, 256>>>(e_pa_src, e_pa_dst, (int*)p_cur, (int*)p_csr, E1);
    k_agg<<<(Na * 32 + 255) / 256, 256>>>((const int*)p_csr, (const int*)p_off,
        (const int*)p_deg, (const float*)p_as_pa, (const float*)p_ad, 0,
        (const float*)p_hp, (float*)p_o_pa, (__nv_bfloat16*)p_opa_bf, Na);

    // ---- metapath da ----
    cudaMemsetAsync(p_deg, 0, (size_t)Na * sizeof(int));
    k_hist<<<(E2 + 255) / 256, 256>>>(e_da_dst, (int*)p_deg, E2);
    k_scan_a<<<nchunks, 256>>>((const int*)p_deg, (int*)p_part, (int*)p_csum, Na);
    k_scan_b<<<1, 512>>>((int*)p_csum, nchunks);
    k_scan_c<<<(Na + 255) / 256, 256>>>((const int*)p_part, (const int*)p_csum,
                                        (int*)p_off, (int*)p_cur, Na);
    k_scatter<<<(E2 + 255) / 256, 256>>>(e_da_src, e_da_dst, (int*)p_cur, (int*)p_csr, E2);
    k_agg<<<(Na * 32 + 255) / 256, 256>>>((const int*)p_csr, (const int*)p_off,
        (const int*)p_deg, (const float*)p_as_da, (const float*)p_ad, 8,
        (const float*)p_hd, (float*)p_o_da, (__nv_bfloat16*)p_oda_bf, Na);

    // K7: WMMA semantic GEMM column sums (both metapaths in one grid)
    cudaFuncSetAttribute(k_semw, cudaFuncAttributeMaxDynamicSharedMemorySize, SEMW_SMEM_BYTES);
    dim3 semgrid((Na + 127) / 128, 2);
    k_semw<<<semgrid, 256, SEMW_SMEM_BYTES>>>((const __nv_bfloat16*)p_opa_bf,
        (const __nv_bfloat16*)p_oda_bf, (const __nv_bfloat16*)p_wk_bf, bk,
        (float*)p_wpart, Na);

    // K8: beta
    k_beta<<<1, 128>>>((const float*)p_wpart, q, 1.0f / (float)Na, (float*)p_beta);

    // K9: final
    k_final<<<(Na + 7) / 8, 256>>>((const float*)p_o_pa, (const float*)p_o_da,
        Wl, bl, (const float*)p_beta, out, Na);
}

// round 5
// speedup vs baseline: 2.5732x; 1.1272x over previous
#include <cuda_runtime.h>
#include <cuda_bf16.h>
#include <mma.h>
#include <cstdint>
#include <cstddef>

using namespace nvcuda;
typedef unsigned long long ull;

#define NA_MAX 300000
#define NP_MAX 150000
#define ND_MAX 80000
#define E_MAX  1000000

// ---------------- device scratch ----------------
__device__ float g_hp[(size_t)NP_MAX * 128];
__device__ float g_hd[(size_t)ND_MAX * 128];
__device__ float g_as_pa[(size_t)NP_MAX * 8];
__device__ float g_as_da[(size_t)ND_MAX * 8];
__device__ float g_ad[(size_t)NA_MAX * 16];       // [n][t*8+h]
__device__ float g_o_pa[(size_t)NA_MAX * 128];
__device__ float g_o_da[(size_t)NA_MAX * 128];
__device__ __nv_bfloat16 g_opa_bf[(size_t)NA_MAX * 128];
__device__ __nv_bfloat16 g_oda_bf[(size_t)NA_MAX * 128];
__device__ __nv_bfloat16 g_wk_bf[128 * 128];
__device__ float g_wpart[256];
__device__ float g_beta[2];
__device__ float g_weff_a[128 * 16];
__device__ float g_weff_p[64 * 8];
__device__ float g_weff_d[64 * 8];
__device__ float g_boff_a[16];
__device__ float g_boff_p[8];
__device__ float g_boff_d[8];
// CSR scratch, both metapaths (index t*STRIDE + i)
__device__ int g_deg[2 * NA_MAX];
__device__ int g_part[2 * NA_MAX];
__device__ int g_csum[2 * 512];
__device__ int g_off[2 * NA_MAX];
__device__ int g_cur[2 * NA_MAX];
__device__ int g_csr[(size_t)2 * E_MAX];

// ---------------- helpers ----------------
__device__ __forceinline__ float tanh_f(float x) {
    x = fminf(fmaxf(x, -12.f), 12.f);
    float t = __expf(2.f * x);
    return __fdividef(t - 1.f, t + 1.f);
}
__device__ __forceinline__ float leaky_exp(float a) {
    a = (a >= 0.f) ? a : 0.2f * a;
    return __expf(a);
}

// ---------------- K1: fold attention vectors (parallel, thread-per-output) ----------
__global__ void k_weff2(const float* __restrict__ Wa, const float* __restrict__ ba,
                        const float* __restrict__ Wp, const float* __restrict__ bp,
                        const float* __restrict__ Wd, const float* __restrict__ bd,
                        const float* __restrict__ ats_pa, const float* __restrict__ atd_pa,
                        const float* __restrict__ ats_da, const float* __restrict__ atd_da) {
    int gid = blockIdx.x * 256 + threadIdx.x;
    if (gid < 2048) {                       // weff_a[k][t*8+h]
        int k = gid >> 4, rem = gid & 15;
        int h = rem & 7;
        const float* att = (rem < 8) ? atd_pa : atd_da;
        float s = 0.f;
        #pragma unroll
        for (int d = 0; d < 16; d++) s += Wa[k * 128 + h * 16 + d] * att[h * 16 + d];
        g_weff_a[k * 16 + rem] = s;
    } else if (gid < 2560) {                // weff_p
        int i = gid - 2048, k = i >> 3, h = i & 7;
        float s = 0.f;
        #pragma unroll
        for (int d = 0; d < 16; d++) s += Wp[k * 128 + h * 16 + d] * ats_pa[h * 16 + d];
        g_weff_p[i] = s;
    } else if (gid < 3072) {                // weff_d
        int i = gid - 2560, k = i >> 3, h = i & 7;
        float s = 0.f;
        #pragma unroll
        for (int d = 0; d < 16; d++) s += Wd[k * 128 + h * 16 + d] * ats_da[h * 16 + d];
        g_weff_d[i] = s;
    } else if (gid < 3088) {                // boff_a
        int i = gid - 3072, h = i & 7;
        const float* att = (i < 8) ? atd_pa : atd_da;
        float s = 0.f;
        #pragma unroll
        for (int d = 0; d < 16; d++) s += ba[h * 16 + d] * att[h * 16 + d];
        g_boff_a[i] = s;
    } else if (gid < 3096) {                // boff_p
        int h = gid - 3088;
        float s = 0.f;
        #pragma unroll
        for (int d = 0; d < 16; d++) s += bp[h * 16 + d] * ats_pa[h * 16 + d];
        g_boff_p[h] = s;
    } else if (gid < 3104) {                // boff_d
        int h = gid - 3096;
        float s = 0.f;
        #pragma unroll
        for (int d = 0; d < 16; d++) s += bd[h * 16 + d] * ats_da[h * 16 + d];
        g_boff_d[h] = s;
    }
}

// ---------------- K1b: Wk -> bf16 ----------------
__global__ void k_wkprep(const float* __restrict__ Wk, __nv_bfloat16* __restrict__ wkbf) {
    int i = blockIdx.x * 256 + threadIdx.x;
    if (i < 16384) wkbf[i] = __float2bfloat16(Wk[i]);
}

// ---------------- K2: small-N GEMM, BATCH nodes per warp, fused over grid.y ----------
template<int KD, int J, int BATCH>
__global__ __launch_bounds__(256) void k_smallgemm(
        const float* __restrict__ x0, const float* __restrict__ x1,
        const float* __restrict__ w0, const float* __restrict__ w1,
        const float* __restrict__ b0, const float* __restrict__ b1,
        float* __restrict__ out0, float* __restrict__ out1, int N0, int N1) {
    constexpr int KC = 32 / J;
    constexpr int KLEN = KD / KC;
    extern __shared__ float dyn[];
    float* xs = dyn;                         // [8][BATCH][KD]
    float* wt = dyn + 8 * BATCH * KD;        // [J][KD]
    float* bo = wt + J * KD;                 // [J]
    const float* x    = blockIdx.y ? x1 : x0;
    const float* weff = blockIdx.y ? w1 : w0;
    const float* boff = blockIdx.y ? b1 : b0;
    float* out        = blockIdx.y ? out1 : out0;
    int N             = blockIdx.y ? N1 : N0;
    int tid = threadIdx.x;
    for (int i = tid; i < J * KD; i += 256) {
        int j = i / KD, k = i % KD;
        wt[j * KD + k] = weff[k * J + j];
    }
    if (tid < J) bo[tid] = boff[tid];
    __syncthreads();
    int w = tid >> 5, lane = tid & 31;
    int j = lane % J, kc = lane / J;
    float* xw = xs + w * BATCH * KD;
    int base = (blockIdx.x * 8 + w) * BATCH;
    if (base >= N) return;
    #pragma unroll
    for (int t = 0; t < BATCH; t++) {
        int n = base + t;
        if (n < N && lane < KD / 4)
            *(float4*)&xw[t * KD + 4 * lane] = *(const float4*)(x + (size_t)n * KD + 4 * lane);
    }
    __syncwarp();
    #pragma unroll
    for (int t = 0; t < BATCH; t++) {
        int n = base + t;
        if (n >= N) break;
        float acc = 0.f;
        #pragma unroll
        for (int it = 0; it < KLEN / 4; it++) {
            int k = kc * KLEN + 4 * it;
            float4 xv = *(const float4*)&xw[t * KD + k];
            float4 wv = *(const float4*)&wt[j * KD + k];
            acc += xv.x * wv.x + xv.y * wv.y + xv.z * wv.z + xv.w * wv.w;
        }
        #pragma unroll
        for (int off = J; off < 32; off <<= 1)
            acc += __shfl_xor_sync(0xffffffffu, acc, off);
        if (lane < J) out[(size_t)n * J + lane] = acc + bo[lane];
    }
}

// ---------------- K3: projection GEMM (fused p/d via grid.y) ----------------
__global__ __launch_bounds__(256) void k_proj(
        const float* __restrict__ x0, const float* __restrict__ x1,
        const float* __restrict__ W0, const float* __restrict__ W1,
        const float* __restrict__ b0, const float* __restrict__ b1,
        float* __restrict__ h0, float* __restrict__ h1, int N0, int N1) {
    __shared__ float Ws[64][128];
    __shared__ float xs[32][64];
    __shared__ float bs[128];
    const float* x = blockIdx.y ? x1 : x0;
    const float* W = blockIdx.y ? W1 : W0;
    const float* b = blockIdx.y ? b1 : b0;
    float* h       = blockIdx.y ? h1 : h0;
    int N          = blockIdx.y ? N1 : N0;
    int base = blockIdx.x * 32;
    if (base >= N) return;
    int tid = threadIdx.x;
    for (int i = tid; i < 2048; i += 256)
        *(float4*)&Ws[0][4 * i] = *(const float4*)&W[4 * i];
    if (tid < 128) bs[tid] = b[tid];
    for (int i = tid; i < 512; i += 256) {
        int r = (4 * i) / 64, c = (4 * i) % 64;
        float4 v = make_float4(0.f, 0.f, 0.f, 0.f);
        if (base + r < N) v = *(const float4*)&x[(size_t)(base + r) * 64 + c];
        *(float4*)&xs[r][c] = v;
    }
    __syncthreads();
    int rg = tid >> 4;
    int cg = (tid & 15) * 8;
    float acc0[8], acc1[8];
    #pragma unroll
    for (int c = 0; c < 8; c++) { acc0[c] = 0.f; acc1[c] = 0.f; }
    #pragma unroll 4
    for (int k = 0; k < 64; k++) {
        float x0v = xs[2 * rg][k], x1v = xs[2 * rg + 1][k];
        #pragma unroll
        for (int c = 0; c < 8; c++) {
            float w = Ws[k][cg + c];
            acc0[c] += x0v * w;
            acc1[c] += x1v * w;
        }
    }
    int r0 = base + 2 * rg;
    if (r0 < N) {
        #pragma unroll
        for (int c = 0; c < 8; c++) h[(size_t)r0 * 128 + cg + c] = acc0[c] + bs[cg + c];
    }
    if (r0 + 1 < N) {
        #pragma unroll
        for (int c = 0; c < 8; c++) h[(size_t)(r0 + 1) * 128 + cg + c] = acc1[c] + bs[cg + c];
    }
}

// ---------------- CSR build (fused over both metapaths) ----------------
__global__ void k_hist(const int* __restrict__ dst1, const int* __restrict__ dst2,
                       int* __restrict__ deg, int E1, int E2) {
    int e = blockIdx.x * 256 + threadIdx.x;
    if (e < E1) atomicAdd(&deg[dst1[e]], 1);
    else if (e < E1 + E2) atomicAdd(&deg[NA_MAX + dst2[e - E1]], 1);
}

__global__ void k_scan_a(const int* __restrict__ degb, int* __restrict__ partb,
                         int* __restrict__ csumb, int n) {
    const int* deg = degb + blockIdx.y * NA_MAX;
    int* part = partb + blockIdx.y * NA_MAX;
    int* csum = csumb + blockIdx.y * 512;
    __shared__ int wsum[8];
    int tid = threadIdx.x;
    int base = blockIdx.x * 1024 + tid * 4;
    int v0 = 0, v1 = 0, v2 = 0, v3 = 0;
    if (base + 0 < n) v0 = deg[base + 0];
    if (base + 1 < n) v1 = deg[base + 1];
    if (base + 2 < n) v2 = deg[base + 2];
    if (base + 3 < n) v3 = deg[base + 3];
    int s = v0 + v1 + v2 + v3;
    int incl = s;
    #pragma unroll
    for (int o = 1; o < 32; o <<= 1) {
        int t = __shfl_up_sync(0xffffffffu, incl, o);
        if ((tid & 31) >= o) incl += t;
    }
    if ((tid & 31) == 31) wsum[tid >> 5] = incl;
    __syncthreads();
    if (tid < 8) {
        int w = wsum[tid];
        #pragma unroll
        for (int o = 1; o < 8; o <<= 1) {
            int t = __shfl_up_sync(0xffu, w, o);
            if (tid >= o) w += t;
        }
        wsum[tid] = w;
    }
    __syncthreads();
    int blockoff = (tid >= 32) ? wsum[(tid >> 5) - 1] : 0;
    int excl = blockoff + incl - s;
    if (base + 0 < n) part[base + 0] = excl;
    if (base + 1 < n) part[base + 1] = excl + v0;
    if (base + 2 < n) part[base + 2] = excl + v0 + v1;
    if (base + 3 < n) part[base + 3] = excl + v0 + v1 + v2;
    if (tid == 255) csum[blockIdx.x] = blockoff + incl;
}

__global__ void k_scan_b(int* __restrict__ csumb, int nc) {
    int* csum = csumb + blockIdx.x * 512;
    __shared__ int ws[16];
    int tid = threadIdx.x;
    int v = (tid < nc) ? csum[tid] : 0;
    int incl = v;
    #pragma unroll
    for (int o = 1; o < 32; o <<= 1) {
        int t = __shfl_up_sync(0xffffffffu, incl, o);
        if ((tid & 31) >= o) incl += t;
    }
    if ((tid & 31) == 31) ws[tid >> 5] = incl;
    __syncthreads();
    if (tid < 16) {
        int w = ws[tid];
        #pragma unroll
        for (int o = 1; o < 16; o <<= 1) {
            int t = __shfl_up_sync(0xffffu, w, o);
            if (tid >= o) w += t;
        }
        ws[tid] = w;
    }
    __syncthreads();
    int add = (tid >= 32) ? ws[(tid >> 5) - 1] : 0;
    incl += add;
    if (tid < nc) csum[tid] = incl - v;
}

__global__ void k_scan_c(const int* __restrict__ partb, const int* __restrict__ csumb,
                         int* __restrict__ offb, int* __restrict__ curb, int n) {
    int y = blockIdx.y;
    int i = blockIdx.x * 256 + threadIdx.x;
    if (i < n) {
        int o = partb[y * NA_MAX + i] + csumb[y * 512 + (i >> 10)];
        offb[y * NA_MAX + i] = o;
        curb[y * NA_MAX + i] = o;
    }
}

__global__ void k_scatter(const int* __restrict__ src1, const int* __restrict__ dst1,
                          const int* __restrict__ src2, const int* __restrict__ dst2,
                          int* __restrict__ cur, int* __restrict__ csr, int E1, int E2) {
    int e = blockIdx.x * 256 + threadIdx.x;
    if (e < E1) {
        int pos = atomicAdd(&cur[dst1[e]], 1);
        csr[pos] = src1[e];
    } else if (e < E1 + E2) {
        int i = e - E1;
        int pos = atomicAdd(&cur[NA_MAX + dst2[i]], 1);
        csr[(size_t)E_MAX + pos] = src2[i];
    }
}

// ---------------- K6: fused softmax+agg+relu, both metapaths (grid.y), MLP=4 ---------
__global__ __launch_bounds__(256) void k_agg(
        const int* __restrict__ csrb, const int* __restrict__ offb, const int* __restrict__ degb,
        const float* __restrict__ as0, const float* __restrict__ as1,
        const float* __restrict__ ad,
        const float* __restrict__ h0, const float* __restrict__ h1,
        float* __restrict__ o0, float* __restrict__ o1,
        __nv_bfloat16* __restrict__ obf0, __nv_bfloat16* __restrict__ obf1, int N) {
    int d = (blockIdx.x * 256 + threadIdx.x) >> 5;
    if (d >= N) return;
    int y = blockIdx.y;
    const int* csr = csrb + (size_t)y * E_MAX;
    const int* off = offb + y * NA_MAX;
    const int* deg = degb + y * NA_MAX;
    const float* as = y ? as1 : as0;
    const float* h  = y ? h1 : h0;
    float* o        = y ? o1 : o0;
    __nv_bfloat16* obf = y ? obf1 : obf0;
    int lane = threadIdx.x & 31;
    int head = lane >> 2;
    float adv = ad[(size_t)d * 16 + y * 8 + head];
    int st = off[d], dg = deg[d];
    float ax = 0.f, ay = 0.f, az = 0.f, aw = 0.f, den = 0.f;
    int i = 0;
    for (; i + 4 <= dg; i += 4) {
        int s0 = csr[st + i], s1 = csr[st + i + 1], s2 = csr[st + i + 2], s3 = csr[st + i + 3];
        float e0 = as[(size_t)s0 * 8 + head];
        float e1 = as[(size_t)s1 * 8 + head];
        float e2 = as[(size_t)s2 * 8 + head];
        float e3 = as[(size_t)s3 * 8 + head];
        float4 h0v = *(const float4*)(h + (size_t)s0 * 128 + lane * 4);
        float4 h1v = *(const float4*)(h + (size_t)s1 * 128 + lane * 4);
        float4 h2v = *(const float4*)(h + (size_t)s2 * 128 + lane * 4);
        float4 h3v = *(const float4*)(h + (size_t)s3 * 128 + lane * 4);
        float w0 = leaky_exp(e0 + adv), w1 = leaky_exp(e1 + adv);
        float w2 = leaky_exp(e2 + adv), w3 = leaky_exp(e3 + adv);
        den += (w0 + w1) + (w2 + w3);
        ax += w0 * h0v.x + w1 * h1v.x + w2 * h2v.x + w3 * h3v.x;
        ay += w0 * h0v.y + w1 * h1v.y + w2 * h2v.y + w3 * h3v.y;
        az += w0 * h0v.z + w1 * h1v.z + w2 * h2v.z + w3 * h3v.z;
        aw += w0 * h0v.w + w1 * h1v.w + w2 * h2v.w + w3 * h3v.w;
    }
    for (; i < dg; i++) {
        int s = csr[st + i];
        float wv = leaky_exp(as[(size_t)s * 8 + head] + adv);
        den += wv;
        float4 hv = *(const float4*)(h + (size_t)s * 128 + lane * 4);
        ax += wv * hv.x; ay += wv * hv.y; az += wv * hv.z; aw += wv * hv.w;
    }
    float inv = __fdividef(1.f, den + 1e-16f);
    float4 r = make_float4(fmaxf(ax * inv, 0.f), fmaxf(ay * inv, 0.f),
                           fmaxf(az * inv, 0.f), fmaxf(aw * inv, 0.f));
    *(float4*)(o + (size_t)d * 128 + lane * 4) = r;
    __nv_bfloat162 b01 = __floats2bfloat162_rn(r.x, r.y);
    __nv_bfloat162 b23 = __floats2bfloat162_rn(r.z, r.w);
    uint2 pk;
    pk.x = *(unsigned int*)&b01;
    pk.y = *(unsigned int*)&b23;
    *(uint2*)(obf + (size_t)d * 128 + lane * 4) = pk;
}

// ---------------- K7: WMMA bf16 semantic GEMM + tanh column sums ----------------
#define SEMW_SMEM_BYTES (69632 + 1024)
__global__ __launch_bounds__(256) void k_semw(
        const __nv_bfloat16* __restrict__ o0, const __nv_bfloat16* __restrict__ o1,
        const __nv_bfloat16* __restrict__ wkbf, const float* __restrict__ bk,
        float* __restrict__ wpart, int N) {
    extern __shared__ char smw[];
    __nv_bfloat16* sA = (__nv_bfloat16*)smw;            // 128 x 136
    __nv_bfloat16* sB = (__nv_bfloat16*)(smw + 34816);  // 128 x 136
    float* sC = (float*)smw;                             // 128 x 132 (reuse)
    float* colacc = (float*)(smw + 69632);               // 128
    const __nv_bfloat16* obf = blockIdx.y ? o1 : o0;
    int tid = threadIdx.x;
    int base = blockIdx.x * 128;
    if (tid < 128) colacc[tid] = 0.f;
    #pragma unroll
    for (int it = 0; it < 8; it++) {
        int chunk = tid + it * 256;
        int k = chunk >> 4, n8 = (chunk & 15) * 8;
        *(uint4*)&sB[k * 136 + n8] = *(const uint4*)&wkbf[k * 128 + n8];
    }
    #pragma unroll
    for (int it = 0; it < 8; it++) {
        int chunk = tid + it * 256;
        int r = chunk >> 4, c8 = (chunk & 15) * 8;
        uint4 v = make_uint4(0u, 0u, 0u, 0u);
        if (base + r < N) v = *(const uint4*)&obf[(size_t)(base + r) * 128 + c8];
        *(uint4*)&sA[r * 136 + c8] = v;
    }
    __syncthreads();
    int w = tid >> 5;
    wmma::fragment<wmma::accumulator, 16, 16, 16, float> acc[8];
    #pragma unroll
    for (int c = 0; c < 8; c++) wmma::fill_fragment(acc[c], 0.f);
    #pragma unroll
    for (int k = 0; k < 8; k++) {
        wmma::fragment<wmma::matrix_a, 16, 16, 16, __nv_bfloat16, wmma::row_major> af;
        wmma::load_matrix_sync(af, &sA[(w * 16) * 136 + k * 16], 136);
        #pragma unroll
        for (int c = 0; c < 8; c++) {
            wmma::fragment<wmma::matrix_b, 16, 16, 16, __nv_bfloat16, wmma::row_major> bf;
            wmma::load_matrix_sync(bf, &sB[(k * 16) * 136 + c * 16], 136);
            wmma::mma_sync(acc[c], af, bf, acc[c]);
        }
    }
    __syncthreads();
    #pragma unroll
    for (int c = 0; c < 8; c++)
        wmma::store_matrix_sync(&sC[(w * 16) * 132 + c * 16], acc[c], 132, wmma::mem_row_major);
    __syncthreads();
    int col = tid & 127;
    int rs = (tid >> 7) * 64;
    int valid = N - base; if (valid > 128) valid = 128;
    float bkv = bk[col];
    float sum = 0.f;
    int rend = rs + 64; if (rend > valid) rend = valid;
    for (int r = rs; r < rend; r++)
        sum += tanh_f(sC[r * 132 + col] + bkv);
    atomicAdd(&colacc[col], sum);
    __syncthreads();
    if (tid < 128) atomicAdd(&wpart[blockIdx.y * 128 + tid], colacc[tid]);
}

// ---------------- K8: semantic softmax (beta) ----------------
__global__ void k_beta(const float* __restrict__ wpart, const float* __restrict__ q,
                       float invN, float* __restrict__ beta) {
    __shared__ float sh[8];
    int tid = threadIdx.x;  // 128
    float qv = q[tid];
    float v0 = wpart[tid] * invN * qv;
    float v1 = wpart[128 + tid] * invN * qv;
    #pragma unroll
    for (int o = 16; o; o >>= 1) {
        v0 += __shfl_xor_sync(0xffffffffu, v0, o);
        v1 += __shfl_xor_sync(0xffffffffu, v1, o);
    }
    int w = tid >> 5;
    if ((tid & 31) == 0) { sh[w] = v0; sh[4 + w] = v1; }
    __syncthreads();
    if (tid == 0) {
        float s0 = sh[0] + sh[1] + sh[2] + sh[3];
        float s1 = sh[4] + sh[5] + sh[6] + sh[7];
        float m = fmaxf(s0, s1);
        float e0 = __expf(s0 - m), e1 = __expf(s1 - m);
        float inv = 1.f / (e0 + e1);
        beta[0] = e0 * inv;
        beta[1] = e1 * inv;
    }
}

// ---------------- K9: combine + classifier + softmax ----------------
__global__ __launch_bounds__(256) void k_final(
        const float* __restrict__ opa, const float* __restrict__ oda,
        const float* __restrict__ Wl, const float* __restrict__ bl,
        const float* __restrict__ beta, float* __restrict__ out, int N) {
    __shared__ float w0s[128], w1s[128];
    int tid = threadIdx.x;
    if (tid < 128) { w0s[tid] = Wl[tid * 2]; w1s[tid] = Wl[tid * 2 + 1]; }
    __syncthreads();
    int n = (blockIdx.x * 256 + tid) >> 5;
    if (n >= N) return;
    int lane = tid & 31;
    float b0 = beta[0], b1 = beta[1];
    float4 pa = *(const float4*)(opa + (size_t)n * 128 + lane * 4);
    float4 da = *(const float4*)(oda + (size_t)n * 128 + lane * 4);
    float sx = b0 * pa.x + b1 * da.x;
    float sy = b0 * pa.y + b1 * da.y;
    float sz = b0 * pa.z + b1 * da.z;
    float sw = b0 * pa.w + b1 * da.w;
    int k = lane * 4;
    float l0 = sx * w0s[k] + sy * w0s[k + 1] + sz * w0s[k + 2] + sw * w0s[k + 3];
    float l1 = sx * w1s[k] + sy * w1s[k + 1] + sz * w1s[k + 2] + sw * w1s[k + 3];
    #pragma unroll
    for (int o = 16; o; o >>= 1) {
        l0 += __shfl_xor_sync(0xffffffffu, l0, o);
        l1 += __shfl_xor_sync(0xffffffffu, l1, o);
    }
    if (lane == 0) {
        l0 += bl[0];
        l1 += bl[1];
        float m = fmaxf(l0, l1);
        float e0 = __expf(l0 - m), e1 = __expf(l1 - m);
        float inv = 1.f / (e0 + e1);
        out[(size_t)n * 2]     = e0 * inv;
        out[(size_t)n * 2 + 1] = e1 * inv;
    }
}

// ---------------- launch ----------------
extern "C" void kernel_launch(void* const* d_in, const int* in_sizes, int n_in,
                              void* d_out, int out_size) {
    const float* x_adm  = (const float*)d_in[0];
    const float* x_pat  = (const float*)d_in[1];
    const float* x_diag = (const float*)d_in[2];
    const int* e_pa_src = (const int*)d_in[3];
    const int* e_pa_dst = (const int*)d_in[4];
    const int* e_da_src = (const int*)d_in[5];
    const int* e_da_dst = (const int*)d_in[6];
    const float* Wa = (const float*)d_in[7];
    const float* ba = (const float*)d_in[8];
    const float* Wp = (const float*)d_in[9];
    const float* bp = (const float*)d_in[10];
    const float* Wd = (const float*)d_in[11];
    const float* bd = (const float*)d_in[12];
    const float* ats_pa = (const float*)d_in[13];
    const float* atd_pa = (const float*)d_in[14];
    const float* ats_da = (const float*)d_in[15];
    const float* atd_da = (const float*)d_in[16];
    const float* Wk = (const float*)d_in[17];
    const float* bk = (const float*)d_in[18];
    const float* q  = (const float*)d_in[19];
    const float* Wl = (const float*)d_in[20];
    const float* bl = (const float*)d_in[21];
    float* out = (float*)d_out;

    int Na = in_sizes[0] / 128;
    int Np = in_sizes[1] / 64;
    int Nd = in_sizes[2] / 64;
    int E1 = in_sizes[3];
    int E2 = in_sizes[5];

    void *p_hp, *p_hd, *p_as_pa, *p_as_da, *p_ad, *p_o_pa, *p_o_da, *p_wpart, *p_beta;
    void *p_opa_bf, *p_oda_bf, *p_wk_bf;
    void *p_weff_a, *p_weff_p, *p_weff_d, *p_boff_a, *p_boff_p, *p_boff_d;
    void *p_deg, *p_part, *p_csum, *p_off, *p_cur, *p_csr;
    cudaGetSymbolAddress(&p_hp, g_hp);
    cudaGetSymbolAddress(&p_hd, g_hd);
    cudaGetSymbolAddress(&p_as_pa, g_as_pa);
    cudaGetSymbolAddress(&p_as_da, g_as_da);
    cudaGetSymbolAddress(&p_ad, g_ad);
    cudaGetSymbolAddress(&p_o_pa, g_o_pa);
    cudaGetSymbolAddress(&p_o_da, g_o_da);
    cudaGetSymbolAddress(&p_opa_bf, g_opa_bf);
    cudaGetSymbolAddress(&p_oda_bf, g_oda_bf);
    cudaGetSymbolAddress(&p_wk_bf, g_wk_bf);
    cudaGetSymbolAddress(&p_wpart, g_wpart);
    cudaGetSymbolAddress(&p_beta, g_beta);
    cudaGetSymbolAddress(&p_weff_a, g_weff_a);
    cudaGetSymbolAddress(&p_weff_p, g_weff_p);
    cudaGetSymbolAddress(&p_weff_d, g_weff_d);
    cudaGetSymbolAddress(&p_boff_a, g_boff_a);
    cudaGetSymbolAddress(&p_boff_p, g_boff_p);
    cudaGetSymbolAddress(&p_boff_d, g_boff_d);
    cudaGetSymbolAddress(&p_deg, g_deg);
    cudaGetSymbolAddress(&p_part, g_part);
    cudaGetSymbolAddress(&p_csum, g_csum);
    cudaGetSymbolAddress(&p_off, g_off);
    cudaGetSymbolAddress(&p_cur, g_cur);
    cudaGetSymbolAddress(&p_csr, g_csr);

    int nchunks = (Na + 1023) / 1024;
    int maxPD = (Np > Nd) ? Np : Nd;

    cudaMemsetAsync(p_wpart, 0, 256 * sizeof(float));
    cudaMemsetAsync(p_deg, 0, (size_t)2 * NA_MAX * sizeof(int));

    // weights
    k_weff2<<<13, 256>>>(Wa, ba, Wp, bp, Wd, bd, ats_pa, atd_pa, ats_da, atd_da);
    k_wkprep<<<64, 256>>>(Wk, (__nv_bfloat16*)p_wk_bf);

    // attention scalars: adm (BATCH=16, dyn smem), then p+d fused
    {
        auto kfnA = k_smallgemm<128, 16, 16>;
        size_t smA = (size_t)(8 * 16 * 128 + 16 * 128 + 16) * sizeof(float);  // 73792
        cudaFuncSetAttribute(kfnA, cudaFuncAttributeMaxDynamicSharedMemorySize, (int)smA);
        dim3 gA((Na + 127) / 128, 1);
        kfnA<<<gA, 256, smA>>>(x_adm, x_adm,
            (const float*)p_weff_a, (const float*)p_weff_a,
            (const float*)p_boff_a, (const float*)p_boff_a,
            (float*)p_ad, (float*)p_ad, Na, Na);

        auto kfnPD = k_smallgemm<64, 8, 8>;
        size_t smPD = (size_t)(8 * 8 * 64 + 8 * 64 + 8) * sizeof(float);      // 18464
        dim3 gPD((maxPD + 63) / 64, 2);
        kfnPD<<<gPD, 256, smPD>>>(x_pat, x_diag,
            (const float*)p_weff_p, (const float*)p_weff_d,
            (const float*)p_boff_p, (const float*)p_boff_d,
            (float*)p_as_pa, (float*)p_as_da, Np, Nd);
    }

    // projections (fused)
    {
        dim3 gP((maxPD + 31) / 32, 2);
        k_proj<<<gP, 256>>>(x_pat, x_diag, Wp, Wd, bp, bd,
                            (float*)p_hp, (float*)p_hd, Np, Nd);
    }

    // CSR build (fused)
    k_hist<<<(E1 + E2 + 255) / 256, 256>>>(e_pa_dst, e_da_dst, (int*)p_deg, E1, E2);
    {
        dim3 gs(nchunks, 2);
        k_scan_a<<<gs, 256>>>((const int*)p_deg, (int*)p_part, (int*)p_csum, Na);
        k_scan_b<<<2, 512>>>((int*)p_csum, nchunks);
        dim3 gc((Na + 255) / 256, 2);
        k_scan_c<<<gc, 256>>>((const int*)p_part, (const int*)p_csum,
                              (int*)p_off, (int*)p_cur, Na);
    }
    k_scatter<<<(E1 + E2 + 255) / 256, 256>>>(e_pa_src, e_pa_dst, e_da_src, e_da_dst,
                                              (int*)p_cur, (int*)p_csr, E1, E2);

    // fused aggregation (both metapaths)
    {
        dim3 ga((Na * 32 + 255) / 256, 2);
        k_agg<<<ga, 256>>>((const int*)p_csr, (const int*)p_off, (const int*)p_deg,
            (const float*)p_as_pa, (const float*)p_as_da, (const float*)p_ad,
            (const float*)p_hp, (const float*)p_hd,
            (float*)p_o_pa, (float*)p_o_da,
            (__nv_bfloat16*)p_opa_bf, (__nv_bfloat16*)p_oda_bf, Na);
    }

    // semantic GEMM column sums
    cudaFuncSetAttribute(k_semw, cudaFuncAttributeMaxDynamicSharedMemorySize, SEMW_SMEM_BYTES);
    dim3 semgrid((Na + 127) / 128, 2);
    k_semw<<<semgrid, 256, SEMW_SMEM_BYTES>>>((const __nv_bfloat16*)p_opa_bf,
        (const __nv_bfloat16*)p_oda_bf, (const __nv_bfloat16*)p_wk_bf, bk,
        (float*)p_wpart, Na);

    // beta + final
    k_beta<<<1, 128>>>((const float*)p_wpart, q, 1.0f / (float)Na, (float*)p_beta);
    k_final<<<(Na + 7) / 8, 256>>>((const float*)p_o_pa, (const float*)p_o_da,
        Wl, bl, (const float*)p_beta, out, Na);
}

// round 6
// speedup vs baseline: 3.3163x; 1.2888x over previous
#include <cuda_runtime.h>
#include <cuda_fp16.h>
#include <mma.h>
#include <cstdint>
#include <cstddef>

using namespace nvcuda;
typedef unsigned long long ull;

#define NA_MAX 300000
#define NP_MAX 150000
#define ND_MAX 80000
#define E_MAX  1000000

// ---------------- device scratch ----------------
__device__ __half g_hp[(size_t)NP_MAX * 128];
__device__ __half g_hd[(size_t)ND_MAX * 128];
__device__ float g_as_pa[(size_t)NP_MAX * 8];
__device__ float g_as_da[(size_t)ND_MAX * 8];
__device__ float g_ad[(size_t)NA_MAX * 16];       // [n][t*8+h]
__device__ __half g_o_pa[(size_t)NA_MAX * 128];
__device__ __half g_o_da[(size_t)NA_MAX * 128];
__device__ __half g_wk_h[128 * 128];
__device__ float g_wpart[256];
__device__ float g_beta[2];
__device__ float g_weff_a[128 * 16];
__device__ float g_weff_p[64 * 8];
__device__ float g_weff_d[64 * 8];
__device__ float g_boff_a[16];
__device__ float g_boff_p[8];
__device__ float g_boff_d[8];
// CSR scratch, both metapaths
__device__ int g_deg[2 * NA_MAX];
__device__ int g_part[2 * NA_MAX];
__device__ int g_csum[2 * 512];
__device__ int g_off[2 * NA_MAX];
__device__ int g_cur[2 * NA_MAX];
__device__ int g_csr[(size_t)2 * E_MAX];

// ---------------- helpers ----------------
__device__ __forceinline__ float tanh_f(float x) {
    x = fminf(fmaxf(x, -12.f), 12.f);
    float t = __expf(2.f * x);
    return __fdividef(t - 1.f, t + 1.f);
}
__device__ __forceinline__ float leaky_exp(float a) {
    a = (a >= 0.f) ? a : 0.2f * a;
    return __expf(a);
}
// load 4 halves (8B) -> float4
__device__ __forceinline__ float4 ld_half4(const __half* p) {
    uint2 raw = *(const uint2*)p;
    __half2 h0 = *(__half2*)&raw.x;
    __half2 h1 = *(__half2*)&raw.y;
    float2 f0 = __half22float2(h0);
    float2 f1 = __half22float2(h1);
    return make_float4(f0.x, f0.y, f1.x, f1.y);
}
__device__ __forceinline__ void st_half4(__half* p, float a, float b, float c, float d) {
    __half2 h0 = __floats2half2_rn(a, b);
    __half2 h1 = __floats2half2_rn(c, d);
    uint2 raw;
    raw.x = *(unsigned int*)&h0;
    raw.y = *(unsigned int*)&h1;
    *(uint2*)p = raw;
}

// ---------------- K1: fold attention vectors (thread-per-output) ----------------
__global__ void k_weff2(const float* __restrict__ Wa, const float* __restrict__ ba,
                        const float* __restrict__ Wp, const float* __restrict__ bp,
                        const float* __restrict__ Wd, const float* __restrict__ bd,
                        const float* __restrict__ ats_pa, const float* __restrict__ atd_pa,
                        const float* __restrict__ ats_da, const float* __restrict__ atd_da) {
    int gid = blockIdx.x * 256 + threadIdx.x;
    if (gid < 2048) {
        int k = gid >> 4, rem = gid & 15;
        int h = rem & 7;
        const float* att = (rem < 8) ? atd_pa : atd_da;
        float s = 0.f;
        #pragma unroll
        for (int d = 0; d < 16; d++) s += Wa[k * 128 + h * 16 + d] * att[h * 16 + d];
        g_weff_a[k * 16 + rem] = s;
    } else if (gid < 2560) {
        int i = gid - 2048, k = i >> 3, h = i & 7;
        float s = 0.f;
        #pragma unroll
        for (int d = 0; d < 16; d++) s += Wp[k * 128 + h * 16 + d] * ats_pa[h * 16 + d];
        g_weff_p[i] = s;
    } else if (gid < 3072) {
        int i = gid - 2560, k = i >> 3, h = i & 7;
        float s = 0.f;
        #pragma unroll
        for (int d = 0; d < 16; d++) s += Wd[k * 128 + h * 16 + d] * ats_da[h * 16 + d];
        g_weff_d[i] = s;
    } else if (gid < 3088) {
        int i = gid - 3072, h = i & 7;
        const float* att = (i < 8) ? atd_pa : atd_da;
        float s = 0.f;
        #pragma unroll
        for (int d = 0; d < 16; d++) s += ba[h * 16 + d] * att[h * 16 + d];
        g_boff_a[i] = s;
    } else if (gid < 3096) {
        int h = gid - 3088;
        float s = 0.f;
        #pragma unroll
        for (int d = 0; d < 16; d++) s += bp[h * 16 + d] * ats_pa[h * 16 + d];
        g_boff_p[h] = s;
    } else if (gid < 3104) {
        int h = gid - 3096;
        float s = 0.f;
        #pragma unroll
        for (int d = 0; d < 16; d++) s += bd[h * 16 + d] * ats_da[h * 16 + d];
        g_boff_d[h] = s;
    }
}

// ---------------- K1b: Wk -> fp16 ----------------
__global__ void k_wkprep(const float* __restrict__ Wk, __half* __restrict__ wkh) {
    int i = blockIdx.x * 256 + threadIdx.x;
    if (i < 16384) wkh[i] = __float2half_rn(Wk[i]);
}

// ---------------- K2: small-N GEMM, BATCH nodes per warp ----------------
template<int KD, int J, int BATCH>
__global__ __launch_bounds__(256) void k_smallgemm(
        const float* __restrict__ x0, const float* __restrict__ x1,
        const float* __restrict__ w0, const float* __restrict__ w1,
        const float* __restrict__ b0, const float* __restrict__ b1,
        float* __restrict__ out0, float* __restrict__ out1, int N0, int N1) {
    constexpr int KC = 32 / J;
    constexpr int KLEN = KD / KC;
    extern __shared__ float dyn[];
    float* xs = dyn;
    float* wt = dyn + 8 * BATCH * KD;
    float* bo = wt + J * KD;
    const float* x    = blockIdx.y ? x1 : x0;
    const float* weff = blockIdx.y ? w1 : w0;
    const float* boff = blockIdx.y ? b1 : b0;
    float* out        = blockIdx.y ? out1 : out0;
    int N             = blockIdx.y ? N1 : N0;
    int tid = threadIdx.x;
    for (int i = tid; i < J * KD; i += 256) {
        int j = i / KD, k = i % KD;
        wt[j * KD + k] = weff[k * J + j];
    }
    if (tid < J) bo[tid] = boff[tid];
    __syncthreads();
    int w = tid >> 5, lane = tid & 31;
    int j = lane % J, kc = lane / J;
    float* xw = xs + w * BATCH * KD;
    int base = (blockIdx.x * 8 + w) * BATCH;
    if (base >= N) return;
    #pragma unroll
    for (int t = 0; t < BATCH; t++) {
        int n = base + t;
        if (n < N && lane < KD / 4)
            *(float4*)&xw[t * KD + 4 * lane] = *(const float4*)(x + (size_t)n * KD + 4 * lane);
    }
    __syncwarp();
    #pragma unroll
    for (int t = 0; t < BATCH; t++) {
        int n = base + t;
        if (n >= N) break;
        float acc = 0.f;
        #pragma unroll
        for (int it = 0; it < KLEN / 4; it++) {
            int k = kc * KLEN + 4 * it;
            float4 xv = *(const float4*)&xw[t * KD + k];
            float4 wv = *(const float4*)&wt[j * KD + k];
            acc += xv.x * wv.x + xv.y * wv.y + xv.z * wv.z + xv.w * wv.w;
        }
        #pragma unroll
        for (int off = J; off < 32; off <<= 1)
            acc += __shfl_xor_sync(0xffffffffu, acc, off);
        if (lane < J) out[(size_t)n * J + lane] = acc + bo[lane];
    }
}

// ---------------- K3: projection GEMM, fp16 output ----------------
__global__ __launch_bounds__(256) void k_proj(
        const float* __restrict__ x0, const float* __restrict__ x1,
        const float* __restrict__ W0, const float* __restrict__ W1,
        const float* __restrict__ b0, const float* __restrict__ b1,
        __half* __restrict__ h0, __half* __restrict__ h1, int N0, int N1) {
    __shared__ float Ws[64][128];
    __shared__ float xs[32][64];
    __shared__ float bs[128];
    const float* x = blockIdx.y ? x1 : x0;
    const float* W = blockIdx.y ? W1 : W0;
    const float* b = blockIdx.y ? b1 : b0;
    __half* h      = blockIdx.y ? h1 : h0;
    int N          = blockIdx.y ? N1 : N0;
    int base = blockIdx.x * 32;
    if (base >= N) return;
    int tid = threadIdx.x;
    for (int i = tid; i < 2048; i += 256)
        *(float4*)&Ws[0][4 * i] = *(const float4*)&W[4 * i];
    if (tid < 128) bs[tid] = b[tid];
    for (int i = tid; i < 512; i += 256) {
        int r = (4 * i) / 64, c = (4 * i) % 64;
        float4 v = make_float4(0.f, 0.f, 0.f, 0.f);
        if (base + r < N) v = *(const float4*)&x[(size_t)(base + r) * 64 + c];
        *(float4*)&xs[r][c] = v;
    }
    __syncthreads();
    int rg = tid >> 4;
    int cg = (tid & 15) * 8;
    float acc0[8], acc1[8];
    #pragma unroll
    for (int c = 0; c < 8; c++) { acc0[c] = 0.f; acc1[c] = 0.f; }
    #pragma unroll 4
    for (int k = 0; k < 64; k++) {
        float x0v = xs[2 * rg][k], x1v = xs[2 * rg + 1][k];
        #pragma unroll
        for (int c = 0; c < 8; c++) {
            float w = Ws[k][cg + c];
            acc0[c] += x0v * w;
            acc1[c] += x1v * w;
        }
    }
    int r0 = base + 2 * rg;
    if (r0 < N) {
        __align__(16) __half hv[8];
        #pragma unroll
        for (int c = 0; c < 8; c++) hv[c] = __float2half_rn(acc0[c] + bs[cg + c]);
        *(uint4*)&h[(size_t)r0 * 128 + cg] = *(uint4*)hv;
    }
    if (r0 + 1 < N) {
        __align__(16) __half hv[8];
        #pragma unroll
        for (int c = 0; c < 8; c++) hv[c] = __float2half_rn(acc1[c] + bs[cg + c]);
        *(uint4*)&h[(size_t)(r0 + 1) * 128 + cg] = *(uint4*)hv;
    }
}

// ---------------- CSR build (fused over both metapaths) ----------------
__global__ void k_hist(const int* __restrict__ dst1, const int* __restrict__ dst2,
                       int* __restrict__ deg, int E1, int E2) {
    int e = blockIdx.x * 256 + threadIdx.x;
    if (e < E1) atomicAdd(&deg[dst1[e]], 1);
    else if (e < E1 + E2) atomicAdd(&deg[NA_MAX + dst2[e - E1]], 1);
}

__global__ void k_scan_a(const int* __restrict__ degb, int* __restrict__ partb,
                         int* __restrict__ csumb, int n) {
    const int* deg = degb + blockIdx.y * NA_MAX;
    int* part = partb + blockIdx.y * NA_MAX;
    int* csum = csumb + blockIdx.y * 512;
    __shared__ int wsum[8];
    int tid = threadIdx.x;
    int base = blockIdx.x * 1024 + tid * 4;
    int v0 = 0, v1 = 0, v2 = 0, v3 = 0;
    if (base + 0 < n) v0 = deg[base + 0];
    if (base + 1 < n) v1 = deg[base + 1];
    if (base + 2 < n) v2 = deg[base + 2];
    if (base + 3 < n) v3 = deg[base + 3];
    int s = v0 + v1 + v2 + v3;
    int incl = s;
    #pragma unroll
    for (int o = 1; o < 32; o <<= 1) {
        int t = __shfl_up_sync(0xffffffffu, incl, o);
        if ((tid & 31) >= o) incl += t;
    }
    if ((tid & 31) == 31) wsum[tid >> 5] = incl;
    __syncthreads();
    if (tid < 8) {
        int w = wsum[tid];
        #pragma unroll
        for (int o = 1; o < 8; o <<= 1) {
            int t = __shfl_up_sync(0xffu, w, o);
            if (tid >= o) w += t;
        }
        wsum[tid] = w;
    }
    __syncthreads();
    int blockoff = (tid >= 32) ? wsum[(tid >> 5) - 1] : 0;
    int excl = blockoff + incl - s;
    if (base + 0 < n) part[base + 0] = excl;
    if (base + 1 < n) part[base + 1] = excl + v0;
    if (base + 2 < n) part[base + 2] = excl + v0 + v1;
    if (base + 3 < n) part[base + 3] = excl + v0 + v1 + v2;
    if (tid == 255) csum[blockIdx.x] = blockoff + incl;
}

__global__ void k_scan_b(int* __restrict__ csumb, int nc) {
    int* csum = csumb + blockIdx.x * 512;
    __shared__ int ws[16];
    int tid = threadIdx.x;
    int v = (tid < nc) ? csum[tid] : 0;
    int incl = v;
    #pragma unroll
    for (int o = 1; o < 32; o <<= 1) {
        int t = __shfl_up_sync(0xffffffffu, incl, o);
        if ((tid & 31) >= o) incl += t;
    }
    if ((tid & 31) == 31) ws[tid >> 5] = incl;
    __syncthreads();
    if (tid < 16) {
        int w = ws[tid];
        #pragma unroll
        for (int o = 1; o < 16; o <<= 1) {
            int t = __shfl_up_sync(0xffffu, w, o);
            if (tid >= o) w += t;
        }
        ws[tid] = w;
    }
    __syncthreads();
    int add = (tid >= 32) ? ws[(tid >> 5) - 1] : 0;
    incl += add;
    if (tid < nc) csum[tid] = incl - v;
}

__global__ void k_scan_c(const int* __restrict__ partb, const int* __restrict__ csumb,
                         int* __restrict__ offb, int* __restrict__ curb, int n) {
    int y = blockIdx.y;
    int i = blockIdx.x * 256 + threadIdx.x;
    if (i < n) {
        int o = partb[y * NA_MAX + i] + csumb[y * 512 + (i >> 10)];
        offb[y * NA_MAX + i] = o;
        curb[y * NA_MAX + i] = o;
    }
}

__global__ void k_scatter(const int* __restrict__ src1, const int* __restrict__ dst1,
                          const int* __restrict__ src2, const int* __restrict__ dst2,
                          int* __restrict__ cur, int* __restrict__ csr, int E1, int E2) {
    int e = blockIdx.x * 256 + threadIdx.x;
    if (e < E1) {
        int pos = atomicAdd(&cur[dst1[e]], 1);
        csr[pos] = src1[e];
    } else if (e < E1 + E2) {
        int i = e - E1;
        int pos = atomicAdd(&cur[NA_MAX + dst2[i]], 1);
        csr[(size_t)E_MAX + pos] = src2[i];
    }
}

// ---------------- K6: fused softmax+agg+relu, fp16 h/o, MLP=4 ----------------
__global__ __launch_bounds__(256) void k_agg(
        const int* __restrict__ csrb, const int* __restrict__ offb, const int* __restrict__ degb,
        const float* __restrict__ as0, const float* __restrict__ as1,
        const float* __restrict__ ad,
        const __half* __restrict__ h0, const __half* __restrict__ h1,
        __half* __restrict__ o0, __half* __restrict__ o1, int N) {
    int d = (blockIdx.x * 256 + threadIdx.x) >> 5;
    if (d >= N) return;
    int y = blockIdx.y;
    const int* csr = csrb + (size_t)y * E_MAX;
    const int* off = offb + y * NA_MAX;
    const int* deg = degb + y * NA_MAX;
    const float* as = y ? as1 : as0;
    const __half* h = y ? h1 : h0;
    __half* o       = y ? o1 : o0;
    int lane = threadIdx.x & 31;
    int head = lane >> 2;
    float adv = ad[(size_t)d * 16 + y * 8 + head];
    int st = off[d], dg = deg[d];
    float ax = 0.f, ay = 0.f, az = 0.f, aw = 0.f, den = 0.f;
    int i = 0;
    for (; i + 4 <= dg; i += 4) {
        int s0 = csr[st + i], s1 = csr[st + i + 1], s2 = csr[st + i + 2], s3 = csr[st + i + 3];
        float e0 = as[(size_t)s0 * 8 + head];
        float e1 = as[(size_t)s1 * 8 + head];
        float e2 = as[(size_t)s2 * 8 + head];
        float e3 = as[(size_t)s3 * 8 + head];
        float4 h0v = ld_half4(h + (size_t)s0 * 128 + lane * 4);
        float4 h1v = ld_half4(h + (size_t)s1 * 128 + lane * 4);
        float4 h2v = ld_half4(h + (size_t)s2 * 128 + lane * 4);
        float4 h3v = ld_half4(h + (size_t)s3 * 128 + lane * 4);
        float w0 = leaky_exp(e0 + adv), w1 = leaky_exp(e1 + adv);
        float w2 = leaky_exp(e2 + adv), w3 = leaky_exp(e3 + adv);
        den += (w0 + w1) + (w2 + w3);
        ax += w0 * h0v.x + w1 * h1v.x + w2 * h2v.x + w3 * h3v.x;
        ay += w0 * h0v.y + w1 * h1v.y + w2 * h2v.y + w3 * h3v.y;
        az += w0 * h0v.z + w1 * h1v.z + w2 * h2v.z + w3 * h3v.z;
        aw += w0 * h0v.w + w1 * h1v.w + w2 * h2v.w + w3 * h3v.w;
    }
    for (; i < dg; i++) {
        int s = csr[st + i];
        float wv = leaky_exp(as[(size_t)s * 8 + head] + adv);
        den += wv;
        float4 hv = ld_half4(h + (size_t)s * 128 + lane * 4);
        ax += wv * hv.x; ay += wv * hv.y; az += wv * hv.z; aw += wv * hv.w;
    }
    float inv = __fdividef(1.f, den + 1e-16f);
    st_half4(o + (size_t)d * 128 + lane * 4,
             fmaxf(ax * inv, 0.f), fmaxf(ay * inv, 0.f),
             fmaxf(az * inv, 0.f), fmaxf(aw * inv, 0.f));
}

// ---------------- K7: WMMA fp16 semantic GEMM + tanh column sums ----------------
#define SEMW_SMEM_BYTES (69632 + 1024)
__global__ __launch_bounds__(256) void k_semw(
        const __half* __restrict__ o0, const __half* __restrict__ o1,
        const __half* __restrict__ wkh, const float* __restrict__ bk,
        float* __restrict__ wpart, int N) {
    extern __shared__ char smw[];
    __half* sA = (__half*)smw;            // 128 x 136
    __half* sB = (__half*)(smw + 34816);  // 128 x 136
    float* sC = (float*)smw;               // 128 x 132 (reuse)
    float* colacc = (float*)(smw + 69632); // 128
    const __half* obf = blockIdx.y ? o1 : o0;
    int tid = threadIdx.x;
    int base = blockIdx.x * 128;
    if (tid < 128) colacc[tid] = 0.f;
    #pragma unroll
    for (int it = 0; it < 8; it++) {
        int chunk = tid + it * 256;
        int k = chunk >> 4, n8 = (chunk & 15) * 8;
        *(uint4*)&sB[k * 136 + n8] = *(const uint4*)&wkh[k * 128 + n8];
    }
    #pragma unroll
    for (int it = 0; it < 8; it++) {
        int chunk = tid + it * 256;
        int r = chunk >> 4, c8 = (chunk & 15) * 8;
        uint4 v = make_uint4(0u, 0u, 0u, 0u);
        if (base + r < N) v = *(const uint4*)&obf[(size_t)(base + r) * 128 + c8];
        *(uint4*)&sA[r * 136 + c8] = v;
    }
    __syncthreads();
    int w = tid >> 5;
    wmma::fragment<wmma::accumulator, 16, 16, 16, float> acc[8];
    #pragma unroll
    for (int c = 0; c < 8; c++) wmma::fill_fragment(acc[c], 0.f);
    #pragma unroll
    for (int k = 0; k < 8; k++) {
        wmma::fragment<wmma::matrix_a, 16, 16, 16, __half, wmma::row_major> af;
        wmma::load_matrix_sync(af, &sA[(w * 16) * 136 + k * 16], 136);
        #pragma unroll
        for (int c = 0; c < 8; c++) {
            wmma::fragment<wmma::matrix_b, 16, 16, 16, __half, wmma::row_major> bf;
            wmma::load_matrix_sync(bf, &sB[(k * 16) * 136 + c * 16], 136);
            wmma::mma_sync(acc[c], af, bf, acc[c]);
        }
    }
    __syncthreads();
    #pragma unroll
    for (int c = 0; c < 8; c++)
        wmma::store_matrix_sync(&sC[(w * 16) * 132 + c * 16], acc[c], 132, wmma::mem_row_major);
    __syncthreads();
    int col = tid & 127;
    int rs = (tid >> 7) * 64;
    int valid = N - base; if (valid > 128) valid = 128;
    float bkv = bk[col];
    float sum = 0.f;
    int rend = rs + 64; if (rend > valid) rend = valid;
    for (int r = rs; r < rend; r++)
        sum += tanh_f(sC[r * 132 + col] + bkv);
    atomicAdd(&colacc[col], sum);
    __syncthreads();
    if (tid < 128) atomicAdd(&wpart[blockIdx.y * 128 + tid], colacc[tid]);
}

// ---------------- K8: semantic softmax (beta) ----------------
__global__ void k_beta(const float* __restrict__ wpart, const float* __restrict__ q,
                       float invN, float* __restrict__ beta) {
    __shared__ float sh[8];
    int tid = threadIdx.x;  // 128
    float qv = q[tid];
    float v0 = wpart[tid] * invN * qv;
    float v1 = wpart[128 + tid] * invN * qv;
    #pragma unroll
    for (int o = 16; o; o >>= 1) {
        v0 += __shfl_xor_sync(0xffffffffu, v0, o);
        v1 += __shfl_xor_sync(0xffffffffu, v1, o);
    }
    int w = tid >> 5;
    if ((tid & 31) == 0) { sh[w] = v0; sh[4 + w] = v1; }
    __syncthreads();
    if (tid == 0) {
        float s0 = sh[0] + sh[1] + sh[2] + sh[3];
        float s1 = sh[4] + sh[5] + sh[6] + sh[7];
        float m = fmaxf(s0, s1);
        float e0 = __expf(s0 - m), e1 = __expf(s1 - m);
        float inv = 1.f / (e0 + e1);
        beta[0] = e0 * inv;
        beta[1] = e1 * inv;
    }
}

// ---------------- K9: combine + classifier + softmax (fp16 inputs) ----------------
__global__ __launch_bounds__(256) void k_final(
        const __half* __restrict__ opa, const __half* __restrict__ oda,
        const float* __restrict__ Wl, const float* __restrict__ bl,
        const float* __restrict__ beta, float* __restrict__ out, int N) {
    __shared__ float w0s[128], w1s[128];
    int tid = threadIdx.x;
    if (tid < 128) { w0s[tid] = Wl[tid * 2]; w1s[tid] = Wl[tid * 2 + 1]; }
    __syncthreads();
    int n = (blockIdx.x * 256 + tid) >> 5;
    if (n >= N) return;
    int lane = tid & 31;
    float b0 = beta[0], b1 = beta[1];
    float4 pa = ld_half4(opa + (size_t)n * 128 + lane * 4);
    float4 da = ld_half4(oda + (size_t)n * 128 + lane * 4);
    float sx = b0 * pa.x + b1 * da.x;
    float sy = b0 * pa.y + b1 * da.y;
    float sz = b0 * pa.z + b1 * da.z;
    float sw = b0 * pa.w + b1 * da.w;
    int k = lane * 4;
    float l0 = sx * w0s[k] + sy * w0s[k + 1] + sz * w0s[k + 2] + sw * w0s[k + 3];
    float l1 = sx * w1s[k] + sy * w1s[k + 1] + sz * w1s[k + 2] + sw * w1s[k + 3];
    #pragma unroll
    for (int o = 16; o; o >>= 1) {
        l0 += __shfl_xor_sync(0xffffffffu, l0, o);
        l1 += __shfl_xor_sync(0xffffffffu, l1, o);
    }
    if (lane == 0) {
        l0 += bl[0];
        l1 += bl[1];
        float m = fmaxf(l0, l1);
        float e0 = __expf(l0 - m), e1 = __expf(l1 - m);
        float inv = 1.f / (e0 + e1);
        out[(size_t)n * 2]     = e0 * inv;
        out[(size_t)n * 2 + 1] = e1 * inv;
    }
}

// ---------------- launch ----------------
extern "C" void kernel_launch(void* const* d_in, const int* in_sizes, int n_in,
                              void* d_out, int out_size) {
    const float* x_adm  = (const float*)d_in[0];
    const float* x_pat  = (const float*)d_in[1];
    const float* x_diag = (const float*)d_in[2];
    const int* e_pa_src = (const int*)d_in[3];
    const int* e_pa_dst = (const int*)d_in[4];
    const int* e_da_src = (const int*)d_in[5];
    const int* e_da_dst = (const int*)d_in[6];
    const float* Wa = (const float*)d_in[7];
    const float* ba = (const float*)d_in[8];
    const float* Wp = (const float*)d_in[9];
    const float* bp = (const float*)d_in[10];
    const float* Wd = (const float*)d_in[11];
    const float* bd = (const float*)d_in[12];
    const float* ats_pa = (const float*)d_in[13];
    const float* atd_pa = (const float*)d_in[14];
    const float* ats_da = (const float*)d_in[15];
    const float* atd_da = (const float*)d_in[16];
    const float* Wk = (const float*)d_in[17];
    const float* bk = (const float*)d_in[18];
    const float* q  = (const float*)d_in[19];
    const float* Wl = (const float*)d_in[20];
    const float* bl = (const float*)d_in[21];
    float* out = (float*)d_out;

    int Na = in_sizes[0] / 128;
    int Np = in_sizes[1] / 64;
    int Nd = in_sizes[2] / 64;
    int E1 = in_sizes[3];
    int E2 = in_sizes[5];

    void *p_hp, *p_hd, *p_as_pa, *p_as_da, *p_ad, *p_o_pa, *p_o_da, *p_wpart, *p_beta;
    void *p_wk_h;
    void *p_weff_a, *p_weff_p, *p_weff_d, *p_boff_a, *p_boff_p, *p_boff_d;
    void *p_deg, *p_part, *p_csum, *p_off, *p_cur, *p_csr;
    cudaGetSymbolAddress(&p_hp, g_hp);
    cudaGetSymbolAddress(&p_hd, g_hd);
    cudaGetSymbolAddress(&p_as_pa, g_as_pa);
    cudaGetSymbolAddress(&p_as_da, g_as_da);
    cudaGetSymbolAddress(&p_ad, g_ad);
    cudaGetSymbolAddress(&p_o_pa, g_o_pa);
    cudaGetSymbolAddress(&p_o_da, g_o_da);
    cudaGetSymbolAddress(&p_wk_h, g_wk_h);
    cudaGetSymbolAddress(&p_wpart, g_wpart);
    cudaGetSymbolAddress(&p_beta, g_beta);
    cudaGetSymbolAddress(&p_weff_a, g_weff_a);
    cudaGetSymbolAddress(&p_weff_p, g_weff_p);
    cudaGetSymbolAddress(&p_weff_d, g_weff_d);
    cudaGetSymbolAddress(&p_boff_a, g_boff_a);
    cudaGetSymbolAddress(&p_boff_p, g_boff_p);
    cudaGetSymbolAddress(&p_boff_d, g_boff_d);
    cudaGetSymbolAddress(&p_deg, g_deg);
    cudaGetSymbolAddress(&p_part, g_part);
    cudaGetSymbolAddress(&p_csum, g_csum);
    cudaGetSymbolAddress(&p_off, g_off);
    cudaGetSymbolAddress(&p_cur, g_cur);
    cudaGetSymbolAddress(&p_csr, g_csr);

    int nchunks = (Na + 1023) / 1024;
    int maxPD = (Np > Nd) ? Np : Nd;

    cudaMemsetAsync(p_wpart, 0, 256 * sizeof(float));
    cudaMemsetAsync(p_deg, 0, (size_t)2 * NA_MAX * sizeof(int));

    // weights
    k_weff2<<<13, 256>>>(Wa, ba, Wp, bp, Wd, bd, ats_pa, atd_pa, ats_da, atd_da);
    k_wkprep<<<64, 256>>>(Wk, (__half*)p_wk_h);

    // attention scalars
    {
        auto kfnA = k_smallgemm<128, 16, 16>;
        size_t smA = (size_t)(8 * 16 * 128 + 16 * 128 + 16) * sizeof(float);
        cudaFuncSetAttribute(kfnA, cudaFuncAttributeMaxDynamicSharedMemorySize, (int)smA);
        dim3 gA((Na + 127) / 128, 1);
        kfnA<<<gA, 256, smA>>>(x_adm, x_adm,
            (const float*)p_weff_a, (const float*)p_weff_a,
            (const float*)p_boff_a, (const float*)p_boff_a,
            (float*)p_ad, (float*)p_ad, Na, Na);

        auto kfnPD = k_smallgemm<64, 8, 8>;
        size_t smPD = (size_t)(8 * 8 * 64 + 8 * 64 + 8) * sizeof(float);
        dim3 gPD((maxPD + 63) / 64, 2);
        kfnPD<<<gPD, 256, smPD>>>(x_pat, x_diag,
            (const float*)p_weff_p, (const float*)p_weff_d,
            (const float*)p_boff_p, (const float*)p_boff_d,
            (float*)p_as_pa, (float*)p_as_da, Np, Nd);
    }

    // projections (fp16 out)
    {
        dim3 gP((maxPD + 31) / 32, 2);
        k_proj<<<gP, 256>>>(x_pat, x_diag, Wp, Wd, bp, bd,
                            (__half*)p_hp, (__half*)p_hd, Np, Nd);
    }

    // CSR build
    k_hist<<<(E1 + E2 + 255) / 256, 256>>>(e_pa_dst, e_da_dst, (int*)p_deg, E1, E2);
    {
        dim3 gs(nchunks, 2);
        k_scan_a<<<gs, 256>>>((const int*)p_deg, (int*)p_part, (int*)p_csum, Na);
        k_scan_b<<<2, 512>>>((int*)p_csum, nchunks);
        dim3 gc((Na + 255) / 256, 2);
        k_scan_c<<<gc, 256>>>((const int*)p_part, (const int*)p_csum,
                              (int*)p_off, (int*)p_cur, Na);
    }
    k_scatter<<<(E1 + E2 + 255) / 256, 256>>>(e_pa_src, e_pa_dst, e_da_src, e_da_dst,
                                              (int*)p_cur, (int*)p_csr, E1, E2);

    // fused aggregation (both metapaths), fp16 h/o
    {
        dim3 ga((Na * 32 + 255) / 256, 2);
        k_agg<<<ga, 256>>>((const int*)p_csr, (const int*)p_off, (const int*)p_deg,
            (const float*)p_as_pa, (const float*)p_as_da, (const float*)p_ad,
            (const __half*)p_hp, (const __half*)p_hd,
            (__half*)p_o_pa, (__half*)p_o_da, Na);
    }

    // semantic GEMM column sums (fp16 WMMA)
    cudaFuncSetAttribute(k_semw, cudaFuncAttributeMaxDynamicSharedMemorySize, SEMW_SMEM_BYTES);
    dim3 semgrid((Na + 127) / 128, 2);
    k_semw<<<semgrid, 256, SEMW_SMEM_BYTES>>>((const __half*)p_o_pa,
        (const __half*)p_o_da, (const __half*)p_wk_h, bk, (float*)p_wpart, Na);

    // beta + final
    k_beta<<<1, 128>>>((const float*)p_wpart, q, 1.0f / (float)Na, (float*)p_beta);
    k_final<<<(Na + 7) / 8, 256>>>((const __half*)p_o_pa, (const __half*)p_o_da,
        Wl, bl, (const float*)p_beta, out, Na);
}

// round 7
// speedup vs baseline: 3.5321x; 1.0651x over previous
#include <cuda_runtime.h>
#include <cuda_fp16.h>
#include <mma.h>
#include <cstdint>
#include <cstddef>

using namespace nvcuda;
typedef unsigned long long ull;

#define NA_MAX 300000
#define NP_MAX 150000
#define ND_MAX 80000
#define E_MAX  1000000

// ---------------- device scratch ----------------
__device__ __half g_hp[(size_t)NP_MAX * 128];
__device__ __half g_hd[(size_t)ND_MAX * 128];
__device__ float g_as_pa[(size_t)NP_MAX * 8];
__device__ float g_as_da[(size_t)ND_MAX * 8];
__device__ float g_ad[(size_t)NA_MAX * 16];       // [n][t*8+h]
__device__ __half g_o_pa[(size_t)NA_MAX * 128];
__device__ __half g_o_da[(size_t)NA_MAX * 128];
__device__ __half g_wk_h[128 * 128];
__device__ float g_la[2 * (size_t)NA_MAX * 2];    // [t][n][2] classifier projections
__device__ float g_wpart[256];
__device__ float g_beta[2];
__device__ float g_weff_a[128 * 16];
__device__ float g_boff_a[16];
// CSR scratch, both metapaths
__device__ int g_deg[2 * NA_MAX];
__device__ int g_part[2 * NA_MAX];
__device__ int g_csum[2 * 512];
__device__ int g_off[2 * NA_MAX];
__device__ int g_cur[2 * NA_MAX];
__device__ int g_csr[(size_t)2 * E_MAX];

// ---------------- helpers ----------------
__device__ __forceinline__ float tanh_f(float x) {
    x = fminf(fmaxf(x, -12.f), 12.f);
    float t = __expf(2.f * x);
    return __fdividef(t - 1.f, t + 1.f);
}
__device__ __forceinline__ float leaky_exp(float a) {
    a = (a >= 0.f) ? a : 0.2f * a;
    return __expf(a);
}
__device__ __forceinline__ float4 ld_half4(const __half* p) {
    uint2 raw = *(const uint2*)p;
    __half2 h0 = *(__half2*)&raw.x;
    __half2 h1 = *(__half2*)&raw.y;
    float2 f0 = __half22float2(h0);
    float2 f1 = __half22float2(h1);
    return make_float4(f0.x, f0.y, f1.x, f1.y);
}
__device__ __forceinline__ void st_half4(__half* p, float a, float b, float c, float d) {
    __half2 h0 = __floats2half2_rn(a, b);
    __half2 h1 = __floats2half2_rn(c, d);
    uint2 raw;
    raw.x = *(unsigned int*)&h0;
    raw.y = *(unsigned int*)&h1;
    *(uint2*)p = raw;
}

// ---------------- K1: fold atd into Wa (only adm scalars need weff now) -----------
__global__ void k_weff2(const float* __restrict__ Wa, const float* __restrict__ ba,
                        const float* __restrict__ atd_pa, const float* __restrict__ atd_da) {
    int gid = blockIdx.x * 256 + threadIdx.x;
    if (gid < 2048) {
        int k = gid >> 4, rem = gid & 15;
        int h = rem & 7;
        const float* att = (rem < 8) ? atd_pa : atd_da;
        float s = 0.f;
        #pragma unroll
        for (int d = 0; d < 16; d++) s += Wa[k * 128 + h * 16 + d] * att[h * 16 + d];
        g_weff_a[k * 16 + rem] = s;
    } else if (gid < 2064) {
        int i = gid - 2048, h = i & 7;
        const float* att = (i < 8) ? atd_pa : atd_da;
        float s = 0.f;
        #pragma unroll
        for (int d = 0; d < 16; d++) s += ba[h * 16 + d] * att[h * 16 + d];
        g_boff_a[i] = s;
    }
}

// ---------------- K1b: Wk -> fp16 ----------------
__global__ void k_wkprep(const float* __restrict__ Wk, __half* __restrict__ wkh) {
    int i = blockIdx.x * 256 + threadIdx.x;
    if (i < 16384) wkh[i] = __float2half_rn(Wk[i]);
}

// ---------------- K2: small-N GEMM (adm only), BATCH nodes per warp ----------------
template<int KD, int J, int BATCH>
__global__ __launch_bounds__(256) void k_smallgemm(
        const float* __restrict__ x, const float* __restrict__ weff,
        const float* __restrict__ boff, float* __restrict__ out, int N) {
    constexpr int KC = 32 / J;
    constexpr int KLEN = KD / KC;
    extern __shared__ float dyn[];
    float* xs = dyn;
    float* wt = dyn + 8 * BATCH * KD;
    float* bo = wt + J * KD;
    int tid = threadIdx.x;
    for (int i = tid; i < J * KD; i += 256) {
        int j = i / KD, k = i % KD;
        wt[j * KD + k] = weff[k * J + j];
    }
    if (tid < J) bo[tid] = boff[tid];
    __syncthreads();
    int w = tid >> 5, lane = tid & 31;
    int j = lane % J, kc = lane / J;
    float* xw = xs + w * BATCH * KD;
    int base = (blockIdx.x * 8 + w) * BATCH;
    if (base >= N) return;
    #pragma unroll
    for (int t = 0; t < BATCH; t++) {
        int n = base + t;
        if (n < N && lane < KD / 4)
            *(float4*)&xw[t * KD + 4 * lane] = *(const float4*)(x + (size_t)n * KD + 4 * lane);
    }
    __syncwarp();
    #pragma unroll
    for (int t = 0; t < BATCH; t++) {
        int n = base + t;
        if (n >= N) break;
        float acc = 0.f;
        #pragma unroll
        for (int it = 0; it < KLEN / 4; it++) {
            int k = kc * KLEN + 4 * it;
            float4 xv = *(const float4*)&xw[t * KD + k];
            float4 wv = *(const float4*)&wt[j * KD + k];
            acc += xv.x * wv.x + xv.y * wv.y + xv.z * wv.z + xv.w * wv.w;
        }
        #pragma unroll
        for (int off = J; off < 32; off <<= 1)
            acc += __shfl_xor_sync(0xffffffffu, acc, off);
        if (lane < J) out[(size_t)n * J + lane] = acc + bo[lane];
    }
}

// ---------------- K3: projection GEMM + fused a_s, fp16 h out ----------------
__global__ __launch_bounds__(256) void k_proj(
        const float* __restrict__ x0, const float* __restrict__ x1,
        const float* __restrict__ W0, const float* __restrict__ W1,
        const float* __restrict__ b0, const float* __restrict__ b1,
        const float* __restrict__ ats0, const float* __restrict__ ats1,
        __half* __restrict__ h0, __half* __restrict__ h1,
        float* __restrict__ as0, float* __restrict__ as1, int N0, int N1) {
    __shared__ float Ws[64][128];
    __shared__ float xs[32][64];
    __shared__ float bs[128];
    __shared__ float atts[128];
    const float* x   = blockIdx.y ? x1 : x0;
    const float* W   = blockIdx.y ? W1 : W0;
    const float* b   = blockIdx.y ? b1 : b0;
    const float* ats = blockIdx.y ? ats1 : ats0;
    __half* h        = blockIdx.y ? h1 : h0;
    float* as_out    = blockIdx.y ? as1 : as0;
    int N            = blockIdx.y ? N1 : N0;
    int base = blockIdx.x * 32;
    if (base >= N) return;
    int tid = threadIdx.x;
    for (int i = tid; i < 2048; i += 256)
        *(float4*)&Ws[0][4 * i] = *(const float4*)&W[4 * i];
    if (tid < 128) { bs[tid] = b[tid]; atts[tid] = ats[tid]; }
    for (int i = tid; i < 512; i += 256) {
        int r = (4 * i) / 64, c = (4 * i) % 64;
        float4 v = make_float4(0.f, 0.f, 0.f, 0.f);
        if (base + r < N) v = *(const float4*)&x[(size_t)(base + r) * 64 + c];
        *(float4*)&xs[r][c] = v;
    }
    __syncthreads();
    int rg = tid >> 4;
    int cg = (tid & 15) * 8;
    float acc0[8], acc1[8];
    #pragma unroll
    for (int c = 0; c < 8; c++) { acc0[c] = 0.f; acc1[c] = 0.f; }
    #pragma unroll 4
    for (int k = 0; k < 64; k++) {
        float x0v = xs[2 * rg][k], x1v = xs[2 * rg + 1][k];
        #pragma unroll
        for (int c = 0; c < 8; c++) {
            float w = Ws[k][cg + c];
            acc0[c] += x0v * w;
            acc1[c] += x1v * w;
        }
    }
    // bias + fp16 store + fused a_s partials
    float p0 = 0.f, p1 = 0.f;
    int r0 = base + 2 * rg;
    {
        __align__(16) __half hv[8];
        #pragma unroll
        for (int c = 0; c < 8; c++) {
            float v = acc0[c] + bs[cg + c];
            hv[c] = __float2half_rn(v);
            p0 += v * atts[cg + c];
        }
        if (r0 < N) *(uint4*)&h[(size_t)r0 * 128 + cg] = *(uint4*)hv;
    }
    {
        __align__(16) __half hv[8];
        #pragma unroll
        for (int c = 0; c < 8; c++) {
            float v = acc1[c] + bs[cg + c];
            hv[c] = __float2half_rn(v);
            p1 += v * atts[cg + c];
        }
        if (r0 + 1 < N) *(uint4*)&h[(size_t)(r0 + 1) * 128 + cg] = *(uint4*)hv;
    }
    // combine the two half-head partials (tid ^ 1 shares rg, adjacent cg)
    p0 += __shfl_xor_sync(0xffffffffu, p0, 1);
    p1 += __shfl_xor_sync(0xffffffffu, p1, 1);
    if ((tid & 1) == 0) {
        int head = (tid & 15) >> 1;
        if (r0 < N)     as_out[(size_t)r0 * 8 + head] = p0;
        if (r0 + 1 < N) as_out[(size_t)(r0 + 1) * 8 + head] = p1;
    }
}

// ---------------- CSR build (fused over both metapaths) ----------------
__global__ void k_hist(const int* __restrict__ dst1, const int* __restrict__ dst2,
                       int* __restrict__ deg, int E1, int E2) {
    int e = blockIdx.x * 256 + threadIdx.x;
    if (e < E1) atomicAdd(&deg[dst1[e]], 1);
    else if (e < E1 + E2) atomicAdd(&deg[NA_MAX + dst2[e - E1]], 1);
}

__global__ void k_scan_a(const int* __restrict__ degb, int* __restrict__ partb,
                         int* __restrict__ csumb, int n) {
    const int* deg = degb + blockIdx.y * NA_MAX;
    int* part = partb + blockIdx.y * NA_MAX;
    int* csum = csumb + blockIdx.y * 512;
    __shared__ int wsum[8];
    int tid = threadIdx.x;
    int base = blockIdx.x * 1024 + tid * 4;
    int v0 = 0, v1 = 0, v2 = 0, v3 = 0;
    if (base + 0 < n) v0 = deg[base + 0];
    if (base + 1 < n) v1 = deg[base + 1];
    if (base + 2 < n) v2 = deg[base + 2];
    if (base + 3 < n) v3 = deg[base + 3];
    int s = v0 + v1 + v2 + v3;
    int incl = s;
    #pragma unroll
    for (int o = 1; o < 32; o <<= 1) {
        int t = __shfl_up_sync(0xffffffffu, incl, o);
        if ((tid & 31) >= o) incl += t;
    }
    if ((tid & 31) == 31) wsum[tid >> 5] = incl;
    __syncthreads();
    if (tid < 8) {
        int w = wsum[tid];
        #pragma unroll
        for (int o = 1; o < 8; o <<= 1) {
            int t = __shfl_up_sync(0xffu, w, o);
            if (tid >= o) w += t;
        }
        wsum[tid] = w;
    }
    __syncthreads();
    int blockoff = (tid >= 32) ? wsum[(tid >> 5) - 1] : 0;
    int excl = blockoff + incl - s;
    if (base + 0 < n) part[base + 0] = excl;
    if (base + 1 < n) part[base + 1] = excl + v0;
    if (base + 2 < n) part[base + 2] = excl + v0 + v1;
    if (base + 3 < n) part[base + 3] = excl + v0 + v1 + v2;
    if (tid == 255) csum[blockIdx.x] = blockoff + incl;
}

__global__ void k_scan_b(int* __restrict__ csumb, int nc) {
    int* csum = csumb + blockIdx.x * 512;
    __shared__ int ws[16];
    int tid = threadIdx.x;
    int v = (tid < nc) ? csum[tid] : 0;
    int incl = v;
    #pragma unroll
    for (int o = 1; o < 32; o <<= 1) {
        int t = __shfl_up_sync(0xffffffffu, incl, o);
        if ((tid & 31) >= o) incl += t;
    }
    if ((tid & 31) == 31) ws[tid >> 5] = incl;
    __syncthreads();
    if (tid < 16) {
        int w = ws[tid];
        #pragma unroll
        for (int o = 1; o < 16; o <<= 1) {
            int t = __shfl_up_sync(0xffffu, w, o);
            if (tid >= o) w += t;
        }
        ws[tid] = w;
    }
    __syncthreads();
    int add = (tid >= 32) ? ws[(tid >> 5) - 1] : 0;
    incl += add;
    if (tid < nc) csum[tid] = incl - v;
}

__global__ void k_scan_c(const int* __restrict__ partb, const int* __restrict__ csumb,
                         int* __restrict__ offb, int* __restrict__ curb, int n) {
    int y = blockIdx.y;
    int i = blockIdx.x * 256 + threadIdx.x;
    if (i < n) {
        int o = partb[y * NA_MAX + i] + csumb[y * 512 + (i >> 10)];
        offb[y * NA_MAX + i] = o;
        curb[y * NA_MAX + i] = o;
    }
}

__global__ void k_scatter(const int* __restrict__ src1, const int* __restrict__ dst1,
                          const int* __restrict__ src2, const int* __restrict__ dst2,
                          int* __restrict__ cur, int* __restrict__ csr, int E1, int E2) {
    int e = blockIdx.x * 256 + threadIdx.x;
    if (e < E1) {
        int pos = atomicAdd(&cur[dst1[e]], 1);
        csr[pos] = src1[e];
    } else if (e < E1 + E2) {
        int i = e - E1;
        int pos = atomicAdd(&cur[NA_MAX + dst2[i]], 1);
        csr[(size_t)E_MAX + pos] = src2[i];
    }
}

// ---------------- K6: fused softmax+agg+relu, fp16 h/o, MLP=4 ----------------
__global__ __launch_bounds__(256) void k_agg(
        const int* __restrict__ csrb, const int* __restrict__ offb, const int* __restrict__ degb,
        const float* __restrict__ as0, const float* __restrict__ as1,
        const float* __restrict__ ad,
        const __half* __restrict__ h0, const __half* __restrict__ h1,
        __half* __restrict__ o0, __half* __restrict__ o1, int N) {
    int d = (blockIdx.x * 256 + threadIdx.x) >> 5;
    if (d >= N) return;
    int y = blockIdx.y;
    const int* csr = csrb + (size_t)y * E_MAX;
    const int* off = offb + y * NA_MAX;
    const int* deg = degb + y * NA_MAX;
    const float* as = y ? as1 : as0;
    const __half* h = y ? h1 : h0;
    __half* o       = y ? o1 : o0;
    int lane = threadIdx.x & 31;
    int head = lane >> 2;
    float adv = ad[(size_t)d * 16 + y * 8 + head];
    int st = off[d], dg = deg[d];
    float ax = 0.f, ay = 0.f, az = 0.f, aw = 0.f, den = 0.f;
    int i = 0;
    for (; i + 4 <= dg; i += 4) {
        int s0 = csr[st + i], s1 = csr[st + i + 1], s2 = csr[st + i + 2], s3 = csr[st + i + 3];
        float e0 = as[(size_t)s0 * 8 + head];
        float e1 = as[(size_t)s1 * 8 + head];
        float e2 = as[(size_t)s2 * 8 + head];
        float e3 = as[(size_t)s3 * 8 + head];
        float4 h0v = ld_half4(h + (size_t)s0 * 128 + lane * 4);
        float4 h1v = ld_half4(h + (size_t)s1 * 128 + lane * 4);
        float4 h2v = ld_half4(h + (size_t)s2 * 128 + lane * 4);
        float4 h3v = ld_half4(h + (size_t)s3 * 128 + lane * 4);
        float w0 = leaky_exp(e0 + adv), w1 = leaky_exp(e1 + adv);
        float w2 = leaky_exp(e2 + adv), w3 = leaky_exp(e3 + adv);
        den += (w0 + w1) + (w2 + w3);
        ax += w0 * h0v.x + w1 * h1v.x + w2 * h2v.x + w3 * h3v.x;
        ay += w0 * h0v.y + w1 * h1v.y + w2 * h2v.y + w3 * h3v.y;
        az += w0 * h0v.z + w1 * h1v.z + w2 * h2v.z + w3 * h3v.z;
        aw += w0 * h0v.w + w1 * h1v.w + w2 * h2v.w + w3 * h3v.w;
    }
    for (; i < dg; i++) {
        int s = csr[st + i];
        float wv = leaky_exp(as[(size_t)s * 8 + head] + adv);
        den += wv;
        float4 hv = ld_half4(h + (size_t)s * 128 + lane * 4);
        ax += wv * hv.x; ay += wv * hv.y; az += wv * hv.z; aw += wv * hv.w;
    }
    float inv = __fdividef(1.f, den + 1e-16f);
    st_half4(o + (size_t)d * 128 + lane * 4,
             fmaxf(ax * inv, 0.f), fmaxf(ay * inv, 0.f),
             fmaxf(az * inv, 0.f), fmaxf(aw * inv, 0.f));
}

// ---------------- K7: WMMA fp16 semantic GEMM + tanh colsums + la = o@Wl ----------
#define SEMW_SMEM_BYTES (69632 + 512 + 1024)
__global__ __launch_bounds__(256) void k_semw(
        const __half* __restrict__ o0, const __half* __restrict__ o1,
        const __half* __restrict__ wkh, const float* __restrict__ bk,
        const float* __restrict__ Wl,
        float* __restrict__ wpart, float* __restrict__ la, int N) {
    extern __shared__ char smw[];
    __half* sA = (__half*)smw;            // 128 x 136
    __half* sB = (__half*)(smw + 34816);  // 128 x 136
    float* sC = (float*)smw;               // 128 x 132 (reuses sA/sB region)
    float* colacc = (float*)(smw + 69632); // 128
    float* Wls = (float*)(smw + 69632 + 512); // 256
    const __half* obf = blockIdx.y ? o1 : o0;
    float* lap = la + (size_t)blockIdx.y * NA_MAX * 2;
    int tid = threadIdx.x;
    int base = blockIdx.x * 128;
    if (tid < 128) colacc[tid] = 0.f;
    if (tid >= 128 && tid < 128 + 128) {
        int c = tid - 128;
        Wls[c * 2] = Wl[c * 2];
        Wls[c * 2 + 1] = Wl[c * 2 + 1];
    }
    #pragma unroll
    for (int it = 0; it < 8; it++) {
        int chunk = tid + it * 256;
        int k = chunk >> 4, n8 = (chunk & 15) * 8;
        *(uint4*)&sB[k * 136 + n8] = *(const uint4*)&wkh[k * 128 + n8];
    }
    #pragma unroll
    for (int it = 0; it < 8; it++) {
        int chunk = tid + it * 256;
        int r = chunk >> 4, c8 = (chunk & 15) * 8;
        uint4 v = make_uint4(0u, 0u, 0u, 0u);
        if (base + r < N) v = *(const uint4*)&obf[(size_t)(base + r) * 128 + c8];
        *(uint4*)&sA[r * 136 + c8] = v;
    }
    __syncthreads();
    int w = tid >> 5;
    wmma::fragment<wmma::accumulator, 16, 16, 16, float> acc[8];
    #pragma unroll
    for (int c = 0; c < 8; c++) wmma::fill_fragment(acc[c], 0.f);
    #pragma unroll
    for (int k = 0; k < 8; k++) {
        wmma::fragment<wmma::matrix_a, 16, 16, 16, __half, wmma::row_major> af;
        wmma::load_matrix_sync(af, &sA[(w * 16) * 136 + k * 16], 136);
        #pragma unroll
        for (int c = 0; c < 8; c++) {
            wmma::fragment<wmma::matrix_b, 16, 16, 16, __half, wmma::row_major> bf;
            wmma::load_matrix_sync(bf, &sB[(k * 16) * 136 + c * 16], 136);
            wmma::mma_sync(acc[c], af, bf, acc[c]);
        }
    }
    __syncthreads();
    // la = o @ Wl while sA still holds the o tile (2 threads per row)
    {
        int r = tid >> 1, half = tid & 1;
        float s0 = 0.f, s1 = 0.f;
        int c0 = half * 64;
        #pragma unroll 16
        for (int c = c0; c < c0 + 64; c++) {
            float a = __half2float(sA[r * 136 + c]);
            s0 += a * Wls[c * 2];
            s1 += a * Wls[c * 2 + 1];
        }
        s0 += __shfl_xor_sync(0xffffffffu, s0, 1);
        s1 += __shfl_xor_sync(0xffffffffu, s1, 1);
        if (half == 0 && base + r < N) {
            lap[(size_t)(base + r) * 2]     = s0;
            lap[(size_t)(base + r) * 2 + 1] = s1;
        }
    }
    __syncthreads();
    #pragma unroll
    for (int c = 0; c < 8; c++)
        wmma::store_matrix_sync(&sC[(w * 16) * 132 + c * 16], acc[c], 132, wmma::mem_row_major);
    __syncthreads();
    int col = tid & 127;
    int rs = (tid >> 7) * 64;
    int valid = N - base; if (valid > 128) valid = 128;
    float bkv = bk[col];
    float sum = 0.f;
    int rend = rs + 64; if (rend > valid) rend = valid;
    for (int r = rs; r < rend; r++)
        sum += tanh_f(sC[r * 132 + col] + bkv);
    atomicAdd(&colacc[col], sum);
    __syncthreads();
    if (tid < 128) atomicAdd(&wpart[blockIdx.y * 128 + tid], colacc[tid]);
}

// ---------------- K8: semantic softmax (beta) ----------------
__global__ void k_beta(const float* __restrict__ wpart, const float* __restrict__ q,
                       float invN, float* __restrict__ beta) {
    __shared__ float sh[8];
    int tid = threadIdx.x;  // 128
    float qv = q[tid];
    float v0 = wpart[tid] * invN * qv;
    float v1 = wpart[128 + tid] * invN * qv;
    #pragma unroll
    for (int o = 16; o; o >>= 1) {
        v0 += __shfl_xor_sync(0xffffffffu, v0, o);
        v1 += __shfl_xor_sync(0xffffffffu, v1, o);
    }
    int w = tid >> 5;
    if ((tid & 31) == 0) { sh[w] = v0; sh[4 + w] = v1; }
    __syncthreads();
    if (tid == 0) {
        float s0 = sh[0] + sh[1] + sh[2] + sh[3];
        float s1 = sh[4] + sh[5] + sh[6] + sh[7];
        float m = fmaxf(s0, s1);
        float e0 = __expf(s0 - m), e1 = __expf(s1 - m);
        float inv = 1.f / (e0 + e1);
        beta[0] = e0 * inv;
        beta[1] = e1 * inv;
    }
}

// ---------------- K9: combine la + bias + softmax (thread per node) ----------------
__global__ __launch_bounds__(256) void k_final(
        const float* __restrict__ la, const float* __restrict__ bl,
        const float* __restrict__ beta, float* __restrict__ out, int N) {
    int n = blockIdx.x * 256 + threadIdx.x;
    if (n >= N) return;
    float b0 = beta[0], b1 = beta[1];
    float2 lp = *(const float2*)(la + (size_t)n * 2);
    float2 ld = *(const float2*)(la + (size_t)NA_MAX * 2 + (size_t)n * 2);
    float l0 = b0 * lp.x + b1 * ld.x + bl[0];
    float l1 = b0 * lp.y + b1 * ld.y + bl[1];
    float m = fmaxf(l0, l1);
    float e0 = __expf(l0 - m), e1 = __expf(l1 - m);
    float inv = 1.f / (e0 + e1);
    out[(size_t)n * 2]     = e0 * inv;
    out[(size_t)n * 2 + 1] = e1 * inv;
}

// ---------------- launch ----------------
extern "C" void kernel_launch(void* const* d_in, const int* in_sizes, int n_in,
                              void* d_out, int out_size) {
    const float* x_adm  = (const float*)d_in[0];
    const float* x_pat  = (const float*)d_in[1];
    const float* x_diag = (const float*)d_in[2];
    const int* e_pa_src = (const int*)d_in[3];
    const int* e_pa_dst = (const int*)d_in[4];
    const int* e_da_src = (const int*)d_in[5];
    const int* e_da_dst = (const int*)d_in[6];
    const float* Wa = (const float*)d_in[7];
    const float* ba = (const float*)d_in[8];
    const float* Wp = (const float*)d_in[9];
    const float* bp = (const float*)d_in[10];
    const float* Wd = (const float*)d_in[11];
    const float* bd = (const float*)d_in[12];
    const float* ats_pa = (const float*)d_in[13];
    const float* atd_pa = (const float*)d_in[14];
    const float* ats_da = (const float*)d_in[15];
    const float* atd_da = (const float*)d_in[16];
    const float* Wk = (const float*)d_in[17];
    const float* bk = (const float*)d_in[18];
    const float* q  = (const float*)d_in[19];
    const float* Wl = (const float*)d_in[20];
    const float* bl = (const float*)d_in[21];
    float* out = (float*)d_out;

    int Na = in_sizes[0] / 128;
    int Np = in_sizes[1] / 64;
    int Nd = in_sizes[2] / 64;
    int E1 = in_sizes[3];
    int E2 = in_sizes[5];

    void *p_hp, *p_hd, *p_as_pa, *p_as_da, *p_ad, *p_o_pa, *p_o_da, *p_wpart, *p_beta;
    void *p_wk_h, *p_la;
    void *p_weff_a, *p_boff_a;
    void *p_deg, *p_part, *p_csum, *p_off, *p_cur, *p_csr;
    cudaGetSymbolAddress(&p_hp, g_hp);
    cudaGetSymbolAddress(&p_hd, g_hd);
    cudaGetSymbolAddress(&p_as_pa, g_as_pa);
    cudaGetSymbolAddress(&p_as_da, g_as_da);
    cudaGetSymbolAddress(&p_ad, g_ad);
    cudaGetSymbolAddress(&p_o_pa, g_o_pa);
    cudaGetSymbolAddress(&p_o_da, g_o_da);
    cudaGetSymbolAddress(&p_wk_h, g_wk_h);
    cudaGetSymbolAddress(&p_la, g_la);
    cudaGetSymbolAddress(&p_wpart, g_wpart);
    cudaGetSymbolAddress(&p_beta, g_beta);
    cudaGetSymbolAddress(&p_weff_a, g_weff_a);
    cudaGetSymbolAddress(&p_boff_a, g_boff_a);
    cudaGetSymbolAddress(&p_deg, g_deg);
    cudaGetSymbolAddress(&p_part, g_part);
    cudaGetSymbolAddress(&p_csum, g_csum);
    cudaGetSymbolAddress(&p_off, g_off);
    cudaGetSymbolAddress(&p_cur, g_cur);
    cudaGetSymbolAddress(&p_csr, g_csr);

    int nchunks = (Na + 1023) / 1024;
    int maxPD = (Np > Nd) ? Np : Nd;

    cudaMemsetAsync(p_wpart, 0, 256 * sizeof(float));
    cudaMemsetAsync(p_deg, 0, (size_t)2 * NA_MAX * sizeof(int));

    // weights
    k_weff2<<<9, 256>>>(Wa, ba, atd_pa, atd_da);
    k_wkprep<<<64, 256>>>(Wk, (__half*)p_wk_h);

    // adm attention scalars
    {
        auto kfnA = k_smallgemm<128, 16, 16>;
        size_t smA = (size_t)(8 * 16 * 128 + 16 * 128 + 16) * sizeof(float);
        cudaFuncSetAttribute(kfnA, cudaFuncAttributeMaxDynamicSharedMemorySize, (int)smA);
        kfnA<<<(Na + 127) / 128, 256, smA>>>(x_adm,
            (const float*)p_weff_a, (const float*)p_boff_a, (float*)p_ad, Na);
    }

    // projections + fused a_s (fp16 h out)
    {
        dim3 gP((maxPD + 31) / 32, 2);
        k_proj<<<gP, 256>>>(x_pat, x_diag, Wp, Wd, bp, bd, ats_pa, ats_da,
                            (__half*)p_hp, (__half*)p_hd,
                            (float*)p_as_pa, (float*)p_as_da, Np, Nd);
    }

    // CSR build
    k_hist<<<(E1 + E2 + 255) / 256, 256>>>(e_pa_dst, e_da_dst, (int*)p_deg, E1, E2);
    {
        dim3 gs(nchunks, 2);
        k_scan_a<<<gs, 256>>>((const int*)p_deg, (int*)p_part, (int*)p_csum, Na);
        k_scan_b<<<2, 512>>>((int*)p_csum, nchunks);
        dim3 gc((Na + 255) / 256, 2);
        k_scan_c<<<gc, 256>>>((const int*)p_part, (const int*)p_csum,
                              (int*)p_off, (int*)p_cur, Na);
    }
    k_scatter<<<(E1 + E2 + 255) / 256, 256>>>(e_pa_src, e_pa_dst, e_da_src, e_da_dst,
                                              (int*)p_cur, (int*)p_csr, E1, E2);

    // fused aggregation (both metapaths)
    {
        dim3 ga((Na * 32 + 255) / 256, 2);
        k_agg<<<ga, 256>>>((const int*)p_csr, (const int*)p_off, (const int*)p_deg,
            (const float*)p_as_pa, (const float*)p_as_da, (const float*)p_ad,
            (const __half*)p_hp, (const __half*)p_hd,
            (__half*)p_o_pa, (__half*)p_o_da, Na);
    }

    // semantic GEMM + la projection
    cudaFuncSetAttribute(k_semw, cudaFuncAttributeMaxDynamicSharedMemorySize, SEMW_SMEM_BYTES);
    dim3 semgrid((Na + 127) / 128, 2);
    k_semw<<<semgrid, 256, SEMW_SMEM_BYTES>>>((const __half*)p_o_pa,
        (const __half*)p_o_da, (const __half*)p_wk_h, bk, Wl,
        (float*)p_wpart, (float*)p_la, Na);

    // beta + final
    k_beta<<<1, 128>>>((const float*)p_wpart, q, 1.0f / (float)Na, (float*)p_beta);
    k_final<<<(Na + 255) / 256, 256>>>((const float*)p_la, bl,
        (const float*)p_beta, out, Na);
}

// round 8
// speedup vs baseline: 4.5754x; 1.2954x over previous
#include <cuda_runtime.h>
#include <cuda_fp16.h>
#include <mma.h>
#include <cstdint>
#include <cstddef>

using namespace nvcuda;
typedef unsigned long long ull;

#define NA_MAX 300000
#define NP_MAX 150000
#define ND_MAX 80000
#define E_MAX  1000000

// ---------------- device scratch ----------------
__device__ __half g_hp[(size_t)NP_MAX * 128];
__device__ __half g_hd[(size_t)ND_MAX * 128];
__device__ float g_as_pa[(size_t)NP_MAX * 8];
__device__ float g_as_da[(size_t)ND_MAX * 8];
__device__ float g_ad[(size_t)NA_MAX * 16];       // [n][t*8+h]
__device__ __half g_o_pa[(size_t)NA_MAX * 128];
__device__ __half g_o_da[(size_t)NA_MAX * 128];
__device__ __half g_wk_h[128 * 128];
__device__ __half g_wp_h[64 * 128];
__device__ __half g_wd_h[64 * 128];
__device__ float g_la[2 * (size_t)NA_MAX * 2];    // [t][n][2]
__device__ float g_wpart[256];
__device__ float g_beta[2];
__device__ float g_weff_a[128 * 16];
__device__ float g_boff_a[16];
// CSR scratch, both metapaths
__device__ int g_deg[2 * NA_MAX];
__device__ int g_part[2 * NA_MAX];
__device__ int g_csum[2 * 512];
__device__ int g_off[2 * NA_MAX];
__device__ int g_cur[2 * NA_MAX];
__device__ int g_csr[(size_t)2 * E_MAX];

// ---------------- helpers ----------------
__device__ __forceinline__ float tanh_f(float x) {
    x = fminf(fmaxf(x, -12.f), 12.f);
    float t = __expf(2.f * x);
    return __fdividef(t - 1.f, t + 1.f);
}
__device__ __forceinline__ float leaky_exp(float a) {
    a = (a >= 0.f) ? a : 0.2f * a;
    return __expf(a);
}
__device__ __forceinline__ float4 ld_half4(const __half* p) {
    uint2 raw = *(const uint2*)p;
    __half2 h0 = *(__half2*)&raw.x;
    __half2 h1 = *(__half2*)&raw.y;
    float2 f0 = __half22float2(h0);
    float2 f1 = __half22float2(h1);
    return make_float4(f0.x, f0.y, f1.x, f1.y);
}
__device__ __forceinline__ void st_half4(__half* p, float a, float b, float c, float d) {
    __half2 h0 = __floats2half2_rn(a, b);
    __half2 h1 = __floats2half2_rn(c, d);
    uint2 raw;
    raw.x = *(unsigned int*)&h0;
    raw.y = *(unsigned int*)&h1;
    *(uint2*)p = raw;
}

// ---------------- K1: fold atd into Wa ----------------
__global__ void k_weff2(const float* __restrict__ Wa, const float* __restrict__ ba,
                        const float* __restrict__ atd_pa, const float* __restrict__ atd_da) {
    int gid = blockIdx.x * 256 + threadIdx.x;
    if (gid < 2048) {
        int k = gid >> 4, rem = gid & 15;
        int h = rem & 7;
        const float* att = (rem < 8) ? atd_pa : atd_da;
        float s = 0.f;
        #pragma unroll
        for (int d = 0; d < 16; d++) s += Wa[k * 128 + h * 16 + d] * att[h * 16 + d];
        g_weff_a[k * 16 + rem] = s;
    } else if (gid < 2064) {
        int i = gid - 2048, h = i & 7;
        const float* att = (i < 8) ? atd_pa : atd_da;
        float s = 0.f;
        #pragma unroll
        for (int d = 0; d < 16; d++) s += ba[h * 16 + d] * att[h * 16 + d];
        g_boff_a[i] = s;
    }
}

// ---------------- K1b: Wk, Wp, Wd -> fp16 ----------------
__global__ void k_wprep(const float* __restrict__ Wk, const float* __restrict__ Wp,
                        const float* __restrict__ Wd) {
    int i = blockIdx.x * 256 + threadIdx.x;
    if (i < 16384) g_wk_h[i] = __float2half_rn(Wk[i]);
    else if (i < 24576) g_wp_h[i - 16384] = __float2half_rn(Wp[i - 16384]);
    else if (i < 32768) g_wd_h[i - 24576] = __float2half_rn(Wd[i - 24576]);
}

// ---------------- K2: small-N GEMM (adm), BATCH per warp ----------------
template<int KD, int J, int BATCH>
__global__ __launch_bounds__(256) void k_smallgemm(
        const float* __restrict__ x, const float* __restrict__ weff,
        const float* __restrict__ boff, float* __restrict__ out, int N) {
    constexpr int KC = 32 / J;
    constexpr int KLEN = KD / KC;
    extern __shared__ float dyn[];
    float* xs = dyn;
    float* wt = dyn + 8 * BATCH * KD;
    float* bo = wt + J * KD;
    int tid = threadIdx.x;
    for (int i = tid; i < J * KD; i += 256) {
        int j = i / KD, k = i % KD;
        wt[j * KD + k] = weff[k * J + j];
    }
    if (tid < J) bo[tid] = boff[tid];
    __syncthreads();
    int w = tid >> 5, lane = tid & 31;
    int j = lane % J, kc = lane / J;
    float* xw = xs + w * BATCH * KD;
    int base = (blockIdx.x * 8 + w) * BATCH;
    if (base >= N) return;
    #pragma unroll
    for (int t = 0; t < BATCH; t++) {
        int n = base + t;
        if (n < N && lane < KD / 4)
            *(float4*)&xw[t * KD + 4 * lane] = *(const float4*)(x + (size_t)n * KD + 4 * lane);
    }
    __syncwarp();
    #pragma unroll
    for (int t = 0; t < BATCH; t++) {
        int n = base + t;
        if (n >= N) break;
        float acc = 0.f;
        #pragma unroll
        for (int it = 0; it < KLEN / 4; it++) {
            int k = kc * KLEN + 4 * it;
            float4 xv = *(const float4*)&xw[t * KD + k];
            float4 wv = *(const float4*)&wt[j * KD + k];
            acc += xv.x * wv.x + xv.y * wv.y + xv.z * wv.z + xv.w * wv.w;
        }
        #pragma unroll
        for (int off = J; off < 32; off <<= 1)
            acc += __shfl_xor_sync(0xffffffffu, acc, off);
        if (lane < J) out[(size_t)n * J + lane] = acc + bo[lane];
    }
}

// ---------------- K3: WMMA projection + fused a_s ----------------
// block: 64 rows x 128 cols, K=64. 8 warps: rows (w&3)*16, cols (w>>2)*64.
#define PROJW_SMEM (33792 + 512 + 512)
__global__ __launch_bounds__(256) void k_projw(
        const float* __restrict__ x0, const float* __restrict__ x1,
        const __half* __restrict__ W0h, const __half* __restrict__ W1h,
        const float* __restrict__ b0, const float* __restrict__ b1,
        const float* __restrict__ ats0, const float* __restrict__ ats1,
        __half* __restrict__ h0, __half* __restrict__ h1,
        float* __restrict__ as0, float* __restrict__ as1, int N0, int N1) {
    extern __shared__ char sm[];
    __half* sW = (__half*)sm;             // 64 x 136 fp16 = 17408 B
    __half* sX = (__half*)(sm + 17408);   // 64 x 72 fp16 = 9216 B
    float* sC  = (float*)sm;              // 64 x 132 fp32 = 33792 B (reuse after MMA)
    float* bias = (float*)(sm + 33792);   // 128
    float* atts = (float*)(sm + 33792 + 512); // 128
    const float* x    = blockIdx.y ? x1 : x0;
    const __half* Wh  = blockIdx.y ? W1h : W0h;
    const float* b    = blockIdx.y ? b1 : b0;
    const float* ats  = blockIdx.y ? ats1 : ats0;
    __half* h         = blockIdx.y ? h1 : h0;
    float* as_out     = blockIdx.y ? as1 : as0;
    int N             = blockIdx.y ? N1 : N0;
    int base = blockIdx.x * 64;
    if (base >= N) return;
    int tid = threadIdx.x;
    if (tid < 128) { bias[tid] = b[tid]; atts[tid] = ats[tid]; }
    // stage W (64x128 fp16)
    #pragma unroll
    for (int it = 0; it < 4; it++) {
        int chunk = tid + it * 256;                 // 1024 chunks of 8 halves
        int k = chunk >> 4, c8 = (chunk & 15) * 8;
        *(uint4*)&sW[k * 136 + c8] = *(const uint4*)&Wh[k * 128 + c8];
    }
    // stage x (64x64 fp32 -> fp16)
    #pragma unroll
    for (int it = 0; it < 4; it++) {
        int chunk = tid + it * 256;                 // 1024 chunks of 4 floats
        int r = chunk >> 4, c4 = (chunk & 15) * 4;
        float4 v = make_float4(0.f, 0.f, 0.f, 0.f);
        if (base + r < N) v = *(const float4*)&x[(size_t)(base + r) * 64 + c4];
        __half2 pa = __floats2half2_rn(v.x, v.y);
        __half2 pb = __floats2half2_rn(v.z, v.w);
        uint2 pk;
        pk.x = *(unsigned int*)&pa;
        pk.y = *(unsigned int*)&pb;
        *(uint2*)&sX[r * 72 + c4] = pk;
    }
    __syncthreads();
    int w = tid >> 5;
    int rB = (w & 3) * 16;
    int cB = (w >> 2) * 64;
    wmma::fragment<wmma::accumulator, 16, 16, 16, float> acc[4];
    #pragma unroll
    for (int c = 0; c < 4; c++) wmma::fill_fragment(acc[c], 0.f);
    #pragma unroll
    for (int k = 0; k < 4; k++) {
        wmma::fragment<wmma::matrix_a, 16, 16, 16, __half, wmma::row_major> af;
        wmma::load_matrix_sync(af, &sX[rB * 72 + k * 16], 72);
        #pragma unroll
        for (int c = 0; c < 4; c++) {
            wmma::fragment<wmma::matrix_b, 16, 16, 16, __half, wmma::row_major> bf;
            wmma::load_matrix_sync(bf, &sW[(k * 16) * 136 + cB + c * 16], 136);
            wmma::mma_sync(acc[c], af, bf, acc[c]);
        }
    }
    __syncthreads();
    #pragma unroll
    for (int c = 0; c < 4; c++)
        wmma::store_matrix_sync(&sC[rB * 132 + cB + c * 16], acc[c], 132, wmma::mem_row_major);
    __syncthreads();
    // epilogue: 4 threads per row, each covers 32 cols = heads 2q, 2q+1
    int r = tid >> 2, q = tid & 3;
    int gr = base + r;
    if (gr < N) {
        int c0 = q * 32;
        float p0 = 0.f, p1 = 0.f;
        __align__(16) __half hbuf[32];
        #pragma unroll
        for (int c = 0; c < 16; c++) {
            float v = sC[r * 132 + c0 + c] + bias[c0 + c];
            hbuf[c] = __float2half_rn(v);
            p0 += v * atts[c0 + c];
        }
        #pragma unroll
        for (int c = 16; c < 32; c++) {
            float v = sC[r * 132 + c0 + c] + bias[c0 + c];
            hbuf[c] = __float2half_rn(v);
            p1 += v * atts[c0 + c];
        }
        uint4* dst = (uint4*)&h[(size_t)gr * 128 + c0];
        const uint4* srcb = (const uint4*)hbuf;
        dst[0] = srcb[0]; dst[1] = srcb[1]; dst[2] = srcb[2]; dst[3] = srcb[3];
        as_out[(size_t)gr * 8 + 2 * q]     = p0;
        as_out[(size_t)gr * 8 + 2 * q + 1] = p1;
    }
}

// ---------------- CSR build ----------------
__global__ void k_hist(const int* __restrict__ dst1, const int* __restrict__ dst2,
                       int* __restrict__ deg, int E1, int E2) {
    int e = blockIdx.x * 256 + threadIdx.x;
    if (e < E1) atomicAdd(&deg[dst1[e]], 1);
    else if (e < E1 + E2) atomicAdd(&deg[NA_MAX + dst2[e - E1]], 1);
}

__global__ void k_scan_a(const int* __restrict__ degb, int* __restrict__ partb,
                         int* __restrict__ csumb, int n) {
    const int* deg = degb + blockIdx.y * NA_MAX;
    int* part = partb + blockIdx.y * NA_MAX;
    int* csum = csumb + blockIdx.y * 512;
    __shared__ int wsum[8];
    int tid = threadIdx.x;
    int base = blockIdx.x * 1024 + tid * 4;
    int v0 = 0, v1 = 0, v2 = 0, v3 = 0;
    if (base + 0 < n) v0 = deg[base + 0];
    if (base + 1 < n) v1 = deg[base + 1];
    if (base + 2 < n) v2 = deg[base + 2];
    if (base + 3 < n) v3 = deg[base + 3];
    int s = v0 + v1 + v2 + v3;
    int incl = s;
    #pragma unroll
    for (int o = 1; o < 32; o <<= 1) {
        int t = __shfl_up_sync(0xffffffffu, incl, o);
        if ((tid & 31) >= o) incl += t;
    }
    if ((tid & 31) == 31) wsum[tid >> 5] = incl;
    __syncthreads();
    if (tid < 8) {
        int w = wsum[tid];
        #pragma unroll
        for (int o = 1; o < 8; o <<= 1) {
            int t = __shfl_up_sync(0xffu, w, o);
            if (tid >= o) w += t;
        }
        wsum[tid] = w;
    }
    __syncthreads();
    int blockoff = (tid >= 32) ? wsum[(tid >> 5) - 1] : 0;
    int excl = blockoff + incl - s;
    if (base + 0 < n) part[base + 0] = excl;
    if (base + 1 < n) part[base + 1] = excl + v0;
    if (base + 2 < n) part[base + 2] = excl + v0 + v1;
    if (base + 3 < n) part[base + 3] = excl + v0 + v1 + v2;
    if (tid == 255) csum[blockIdx.x] = blockoff + incl;
}

__global__ void k_scan_b(int* __restrict__ csumb, int nc) {
    int* csum = csumb + blockIdx.x * 512;
    __shared__ int ws[16];
    int tid = threadIdx.x;
    int v = (tid < nc) ? csum[tid] : 0;
    int incl = v;
    #pragma unroll
    for (int o = 1; o < 32; o <<= 1) {
        int t = __shfl_up_sync(0xffffffffu, incl, o);
        if ((tid & 31) >= o) incl += t;
    }
    if ((tid & 31) == 31) ws[tid >> 5] = incl;
    __syncthreads();
    if (tid < 16) {
        int w = ws[tid];
        #pragma unroll
        for (int o = 1; o < 16; o <<= 1) {
            int t = __shfl_up_sync(0xffffu, w, o);
            if (tid >= o) w += t;
        }
        ws[tid] = w;
    }
    __syncthreads();
    int add = (tid >= 32) ? ws[(tid >> 5) - 1] : 0;
    incl += add;
    if (tid < nc) csum[tid] = incl - v;
}

__global__ void k_scan_c(const int* __restrict__ partb, const int* __restrict__ csumb,
                         int* __restrict__ offb, int* __restrict__ curb, int n) {
    int y = blockIdx.y;
    int i = blockIdx.x * 256 + threadIdx.x;
    if (i < n) {
        int o = partb[y * NA_MAX + i] + csumb[y * 512 + (i >> 10)];
        offb[y * NA_MAX + i] = o;
        curb[y * NA_MAX + i] = o;
    }
}

__global__ void k_scatter(const int* __restrict__ src1, const int* __restrict__ dst1,
                          const int* __restrict__ src2, const int* __restrict__ dst2,
                          int* __restrict__ cur, int* __restrict__ csr, int E1, int E2) {
    int e = blockIdx.x * 256 + threadIdx.x;
    if (e < E1) {
        int pos = atomicAdd(&cur[dst1[e]], 1);
        csr[pos] = src1[e];
    } else if (e < E1 + E2) {
        int i = e - E1;
        int pos = atomicAdd(&cur[NA_MAX + dst2[i]], 1);
        csr[(size_t)E_MAX + pos] = src2[i];
    }
}

// ---------------- K6: fused softmax+agg+relu ----------------
__global__ __launch_bounds__(256) void k_agg(
        const int* __restrict__ csrb, const int* __restrict__ offb, const int* __restrict__ degb,
        const float* __restrict__ as0, const float* __restrict__ as1,
        const float* __restrict__ ad,
        const __half* __restrict__ h0, const __half* __restrict__ h1,
        __half* __restrict__ o0, __half* __restrict__ o1, int N) {
    int d = (blockIdx.x * 256 + threadIdx.x) >> 5;
    if (d >= N) return;
    int y = blockIdx.y;
    const int* csr = csrb + (size_t)y * E_MAX;
    const int* off = offb + y * NA_MAX;
    const int* deg = degb + y * NA_MAX;
    const float* as = y ? as1 : as0;
    const __half* h = y ? h1 : h0;
    __half* o       = y ? o1 : o0;
    int lane = threadIdx.x & 31;
    int head = lane >> 2;
    float adv = ad[(size_t)d * 16 + y * 8 + head];
    int st = off[d], dg = deg[d];
    float ax = 0.f, ay = 0.f, az = 0.f, aw = 0.f, den = 0.f;
    int i = 0;
    for (; i + 4 <= dg; i += 4) {
        int s0 = csr[st + i], s1 = csr[st + i + 1], s2 = csr[st + i + 2], s3 = csr[st + i + 3];
        float e0 = as[(size_t)s0 * 8 + head];
        float e1 = as[(size_t)s1 * 8 + head];
        float e2 = as[(size_t)s2 * 8 + head];
        float e3 = as[(size_t)s3 * 8 + head];
        float4 h0v = ld_half4(h + (size_t)s0 * 128 + lane * 4);
        float4 h1v = ld_half4(h + (size_t)s1 * 128 + lane * 4);
        float4 h2v = ld_half4(h + (size_t)s2 * 128 + lane * 4);
        float4 h3v = ld_half4(h + (size_t)s3 * 128 + lane * 4);
        float w0 = leaky_exp(e0 + adv), w1 = leaky_exp(e1 + adv);
        float w2 = leaky_exp(e2 + adv), w3 = leaky_exp(e3 + adv);
        den += (w0 + w1) + (w2 + w3);
        ax += w0 * h0v.x + w1 * h1v.x + w2 * h2v.x + w3 * h3v.x;
        ay += w0 * h0v.y + w1 * h1v.y + w2 * h2v.y + w3 * h3v.y;
        az += w0 * h0v.z + w1 * h1v.z + w2 * h2v.z + w3 * h3v.z;
        aw += w0 * h0v.w + w1 * h1v.w + w2 * h2v.w + w3 * h3v.w;
    }
    for (; i < dg; i++) {
        int s = csr[st + i];
        float wv = leaky_exp(as[(size_t)s * 8 + head] + adv);
        den += wv;
        float4 hv = ld_half4(h + (size_t)s * 128 + lane * 4);
        ax += wv * hv.x; ay += wv * hv.y; az += wv * hv.z; aw += wv * hv.w;
    }
    float inv = __fdividef(1.f, den + 1e-16f);
    st_half4(o + (size_t)d * 128 + lane * 4,
             fmaxf(ax * inv, 0.f), fmaxf(ay * inv, 0.f),
             fmaxf(az * inv, 0.f), fmaxf(aw * inv, 0.f));
}

// ---------------- K7: WMMA semantic GEMM + tanh colsums + la ----------------
#define SEMW_SMEM_BYTES (69632 + 512 + 1024)
__global__ __launch_bounds__(256) void k_semw(
        const __half* __restrict__ o0, const __half* __restrict__ o1,
        const __half* __restrict__ wkh, const float* __restrict__ bk,
        const float* __restrict__ Wl,
        float* __restrict__ wpart, float* __restrict__ la, int N) {
    extern __shared__ char smw[];
    __half* sA = (__half*)smw;            // 128 x 136
    __half* sB = (__half*)(smw + 34816);  // 128 x 136
    float* sC = (float*)smw;               // 128 x 132 (reuse)
    float* colacc = (float*)(smw + 69632); // 128
    float* Wls = (float*)(smw + 69632 + 512); // 256
    const __half* obf = blockIdx.y ? o1 : o0;
    float* lap = la + (size_t)blockIdx.y * NA_MAX * 2;
    int tid = threadIdx.x;
    int base = blockIdx.x * 128;
    if (tid < 128) colacc[tid] = 0.f;
    if (tid >= 128 && tid < 256) {
        int c = tid - 128;
        Wls[c * 2] = Wl[c * 2];
        Wls[c * 2 + 1] = Wl[c * 2 + 1];
    }
    #pragma unroll
    for (int it = 0; it < 8; it++) {
        int chunk = tid + it * 256;
        int k = chunk >> 4, n8 = (chunk & 15) * 8;
        *(uint4*)&sB[k * 136 + n8] = *(const uint4*)&wkh[k * 128 + n8];
    }
    #pragma unroll
    for (int it = 0; it < 8; it++) {
        int chunk = tid + it * 256;
        int r = chunk >> 4, c8 = (chunk & 15) * 8;
        uint4 v = make_uint4(0u, 0u, 0u, 0u);
        if (base + r < N) v = *(const uint4*)&obf[(size_t)(base + r) * 128 + c8];
        *(uint4*)&sA[r * 136 + c8] = v;
    }
    __syncthreads();
    int w = tid >> 5;
    wmma::fragment<wmma::accumulator, 16, 16, 16, float> acc[8];
    #pragma unroll
    for (int c = 0; c < 8; c++) wmma::fill_fragment(acc[c], 0.f);
    #pragma unroll
    for (int k = 0; k < 8; k++) {
        wmma::fragment<wmma::matrix_a, 16, 16, 16, __half, wmma::row_major> af;
        wmma::load_matrix_sync(af, &sA[(w * 16) * 136 + k * 16], 136);
        #pragma unroll
        for (int c = 0; c < 8; c++) {
            wmma::fragment<wmma::matrix_b, 16, 16, 16, __half, wmma::row_major> bf;
            wmma::load_matrix_sync(bf, &sB[(k * 16) * 136 + c * 16], 136);
            wmma::mma_sync(acc[c], af, bf, acc[c]);
        }
    }
    __syncthreads();
    // la = o @ Wl while sA still holds the tile
    {
        int r = tid >> 1, half = tid & 1;
        float s0 = 0.f, s1 = 0.f;
        int c0 = half * 64;
        #pragma unroll 16
        for (int c = c0; c < c0 + 64; c++) {
            float a = __half2float(sA[r * 136 + c]);
            s0 += a * Wls[c * 2];
            s1 += a * Wls[c * 2 + 1];
        }
        s0 += __shfl_xor_sync(0xffffffffu, s0, 1);
        s1 += __shfl_xor_sync(0xffffffffu, s1, 1);
        if (half == 0 && base + r < N) {
            lap[(size_t)(base + r) * 2]     = s0;
            lap[(size_t)(base + r) * 2 + 1] = s1;
        }
    }
    __syncthreads();
    #pragma unroll
    for (int c = 0; c < 8; c++)
        wmma::store_matrix_sync(&sC[(w * 16) * 132 + c * 16], acc[c], 132, wmma::mem_row_major);
    __syncthreads();
    int col = tid & 127;
    int rs = (tid >> 7) * 64;
    int valid = N - base; if (valid > 128) valid = 128;
    float bkv = bk[col];
    float sum = 0.f;
    int rend = rs + 64; if (rend > valid) rend = valid;
    for (int r = rs; r < rend; r++)
        sum += tanh_f(sC[r * 132 + col] + bkv);
    atomicAdd(&colacc[col], sum);
    __syncthreads();
    if (tid < 128) atomicAdd(&wpart[blockIdx.y * 128 + tid], colacc[tid]);
}

// ---------------- K8: beta ----------------
__global__ void k_beta(const float* __restrict__ wpart, const float* __restrict__ q,
                       float invN, float* __restrict__ beta) {
    __shared__ float sh[8];
    int tid = threadIdx.x;
    float qv = q[tid];
    float v0 = wpart[tid] * invN * qv;
    float v1 = wpart[128 + tid] * invN * qv;
    #pragma unroll
    for (int o = 16; o; o >>= 1) {
        v0 += __shfl_xor_sync(0xffffffffu, v0, o);
        v1 += __shfl_xor_sync(0xffffffffu, v1, o);
    }
    int w = tid >> 5;
    if ((tid & 31) == 0) { sh[w] = v0; sh[4 + w] = v1; }
    __syncthreads();
    if (tid == 0) {
        float s0 = sh[0] + sh[1] + sh[2] + sh[3];
        float s1 = sh[4] + sh[5] + sh[6] + sh[7];
        float m = fmaxf(s0, s1);
        float e0 = __expf(s0 - m), e1 = __expf(s1 - m);
        float inv = 1.f / (e0 + e1);
        beta[0] = e0 * inv;
        beta[1] = e1 * inv;
    }
}

// ---------------- K9: final ----------------
__global__ __launch_bounds__(256) void k_final(
        const float* __restrict__ la, const float* __restrict__ bl,
        const float* __restrict__ beta, float* __restrict__ out, int N) {
    int n = blockIdx.x * 256 + threadIdx.x;
    if (n >= N) return;
    float b0 = beta[0], b1 = beta[1];
    float2 lp = *(const float2*)(la + (size_t)n * 2);
    float2 ld = *(const float2*)(la + (size_t)NA_MAX * 2 + (size_t)n * 2);
    float l0 = b0 * lp.x + b1 * ld.x + bl[0];
    float l1 = b0 * lp.y + b1 * ld.y + bl[1];
    float m = fmaxf(l0, l1);
    float e0 = __expf(l0 - m), e1 = __expf(l1 - m);
    float inv = 1.f / (e0 + e1);
    out[(size_t)n * 2]     = e0 * inv;
    out[(size_t)n * 2 + 1] = e1 * inv;
}

// ---------------- launch ----------------
extern "C" void kernel_launch(void* const* d_in, const int* in_sizes, int n_in,
                              void* d_out, int out_size) {
    const float* x_adm  = (const float*)d_in[0];
    const float* x_pat  = (const float*)d_in[1];
    const float* x_diag = (const float*)d_in[2];
    const int* e_pa_src = (const int*)d_in[3];
    const int* e_pa_dst = (const int*)d_in[4];
    const int* e_da_src = (const int*)d_in[5];
    const int* e_da_dst = (const int*)d_in[6];
    const float* Wa = (const float*)d_in[7];
    const float* ba = (const float*)d_in[8];
    const float* Wp = (const float*)d_in[9];
    const float* bp = (const float*)d_in[10];
    const float* Wd = (const float*)d_in[11];
    const float* bd = (const float*)d_in[12];
    const float* ats_pa = (const float*)d_in[13];
    const float* atd_pa = (const float*)d_in[14];
    const float* ats_da = (const float*)d_in[15];
    const float* atd_da = (const float*)d_in[16];
    const float* Wk = (const float*)d_in[17];
    const float* bk = (const float*)d_in[18];
    const float* q  = (const float*)d_in[19];
    const float* Wl = (const float*)d_in[20];
    const float* bl = (const float*)d_in[21];
    float* out = (float*)d_out;

    int Na = in_sizes[0] / 128;
    int Np = in_sizes[1] / 64;
    int Nd = in_sizes[2] / 64;
    int E1 = in_sizes[3];
    int E2 = in_sizes[5];

    void *p_hp, *p_hd, *p_as_pa, *p_as_da, *p_ad, *p_o_pa, *p_o_da, *p_wpart, *p_beta;
    void *p_wk_h, *p_wp_h, *p_wd_h, *p_la;
    void *p_weff_a, *p_boff_a;
    void *p_deg, *p_part, *p_csum, *p_off, *p_cur, *p_csr;
    cudaGetSymbolAddress(&p_hp, g_hp);
    cudaGetSymbolAddress(&p_hd, g_hd);
    cudaGetSymbolAddress(&p_as_pa, g_as_pa);
    cudaGetSymbolAddress(&p_as_da, g_as_da);
    cudaGetSymbolAddress(&p_ad, g_ad);
    cudaGetSymbolAddress(&p_o_pa, g_o_pa);
    cudaGetSymbolAddress(&p_o_da, g_o_da);
    cudaGetSymbolAddress(&p_wk_h, g_wk_h);
    cudaGetSymbolAddress(&p_wp_h, g_wp_h);
    cudaGetSymbolAddress(&p_wd_h, g_wd_h);
    cudaGetSymbolAddress(&p_la, g_la);
    cudaGetSymbolAddress(&p_wpart, g_wpart);
    cudaGetSymbolAddress(&p_beta, g_beta);
    cudaGetSymbolAddress(&p_weff_a, g_weff_a);
    cudaGetSymbolAddress(&p_boff_a, g_boff_a);
    cudaGetSymbolAddress(&p_deg, g_deg);
    cudaGetSymbolAddress(&p_part, g_part);
    cudaGetSymbolAddress(&p_csum, g_csum);
    cudaGetSymbolAddress(&p_off, g_off);
    cudaGetSymbolAddress(&p_cur, g_cur);
    cudaGetSymbolAddress(&p_csr, g_csr);

    int nchunks = (Na + 1023) / 1024;
    int maxPD = (Np > Nd) ? Np : Nd;

    cudaMemsetAsync(p_wpart, 0, 256 * sizeof(float));
    cudaMemsetAsync(p_deg, 0, (size_t)2 * NA_MAX * sizeof(int));

    // weights
    k_weff2<<<9, 256>>>(Wa, ba, atd_pa, atd_da);
    k_wprep<<<128, 256>>>(Wk, Wp, Wd);

    // adm attention scalars
    {
        auto kfnA = k_smallgemm<128, 16, 16>;
        size_t smA = (size_t)(8 * 16 * 128 + 16 * 128 + 16) * sizeof(float);
        cudaFuncSetAttribute(kfnA, cudaFuncAttributeMaxDynamicSharedMemorySize, (int)smA);
        kfnA<<<(Na + 127) / 128, 256, smA>>>(x_adm,
            (const float*)p_weff_a, (const float*)p_boff_a, (float*)p_ad, Na);
    }

    // WMMA projections + fused a_s
    {
        cudaFuncSetAttribute(k_projw, cudaFuncAttributeMaxDynamicSharedMemorySize, PROJW_SMEM);
        dim3 gP((maxPD + 63) / 64, 2);
        k_projw<<<gP, 256, PROJW_SMEM>>>(x_pat, x_diag,
            (const __half*)p_wp_h, (const __half*)p_wd_h, bp, bd, ats_pa, ats_da,
            (__half*)p_hp, (__half*)p_hd,
            (float*)p_as_pa, (float*)p_as_da, Np, Nd);
    }

    // CSR build
    k_hist<<<(E1 + E2 + 255) / 256, 256>>>(e_pa_dst, e_da_dst, (int*)p_deg, E1, E2);
    {
        dim3 gs(nchunks, 2);
        k_scan_a<<<gs, 256>>>((const int*)p_deg, (int*)p_part, (int*)p_csum, Na);
        k_scan_b<<<2, 512>>>((int*)p_csum, nchunks);
        dim3 gc((Na + 255) / 256, 2);
        k_scan_c<<<gc, 256>>>((const int*)p_part, (const int*)p_csum,
                              (int*)p_off, (int*)p_cur, Na);
    }
    k_scatter<<<(E1 + E2 + 255) / 256, 256>>>(e_pa_src, e_pa_dst, e_da_src, e_da_dst,
                                              (int*)p_cur, (int*)p_csr, E1, E2);

    // fused aggregation
    {
        dim3 ga((Na * 32 + 255) / 256, 2);
        k_agg<<<ga, 256>>>((const int*)p_csr, (const int*)p_off, (const int*)p_deg,
            (const float*)p_as_pa, (const float*)p_as_da, (const float*)p_ad,
            (const __half*)p_hp, (const __half*)p_hd,
            (__half*)p_o_pa, (__half*)p_o_da, Na);
    }

    // semantic GEMM + la projection
    cudaFuncSetAttribute(k_semw, cudaFuncAttributeMaxDynamicSharedMemorySize, SEMW_SMEM_BYTES);
    dim3 semgrid((Na + 127) / 128, 2);
    k_semw<<<semgrid, 256, SEMW_SMEM_BYTES>>>((const __half*)p_o_pa,
        (const __half*)p_o_da, (const __half*)p_wk_h, bk, Wl,
        (float*)p_wpart, (float*)p_la, Na);

    // beta + final
    k_beta<<<1, 128>>>((const float*)p_wpart, q, 1.0f / (float)Na, (float*)p_beta);
    k_final<<<(Na + 255) / 256, 256>>>((const float*)p_la, bl,
        (const float*)p_beta, out, Na);
}

// round 9
// speedup vs baseline: 5.0216x; 1.0975x over previous
#include <cuda_runtime.h>
#include <cuda_fp16.h>
#include <mma.h>
#include <cstdint>
#include <cstddef>

using namespace nvcuda;
typedef unsigned long long ull;

#define NA_MAX 300000
#define NP_MAX 150000
#define ND_MAX 80000
#define E_MAX  1000000

// ---------------- device scratch ----------------
__device__ __half g_hp[(size_t)NP_MAX * 128];
__device__ __half g_hd[(size_t)ND_MAX * 128];
__device__ float g_as_pa[(size_t)NP_MAX * 8];
__device__ float g_as_da[(size_t)ND_MAX * 8];
__device__ float g_ad[(size_t)NA_MAX * 16];       // [n][t*8+h]
__device__ __half g_o_pa[(size_t)NA_MAX * 128];
__device__ __half g_o_da[(size_t)NA_MAX * 128];
__device__ __half g_wk_h[128 * 128];
__device__ __half g_wp_h[64 * 128];
__device__ __half g_wd_h[64 * 128];
__device__ float g_la[2 * (size_t)NA_MAX * 2];    // [t][n][2]
__device__ float g_wpart[256];
__device__ float g_beta[2];
__device__ __half g_weff_ah[128 * 16];
__device__ float g_boff_a[16];
// CSR scratch, both metapaths
__device__ int g_deg[2 * NA_MAX];
__device__ int g_part[2 * NA_MAX];
__device__ int g_csum[2 * 512];
__device__ int g_off[2 * NA_MAX];
__device__ int g_cur[2 * NA_MAX];
__device__ int g_csr[(size_t)2 * E_MAX];

// ---------------- helpers ----------------
__device__ __forceinline__ float tanh_f(float x) {
    x = fminf(fmaxf(x, -12.f), 12.f);
    float t = __expf(2.f * x);
    return __fdividef(t - 1.f, t + 1.f);
}
__device__ __forceinline__ float leaky_exp(float a) {
    a = (a >= 0.f) ? a : 0.2f * a;
    return __expf(a);
}
__device__ __forceinline__ float4 ld_half4(const __half* p) {
    uint2 raw = *(const uint2*)p;
    __half2 h0 = *(__half2*)&raw.x;
    __half2 h1 = *(__half2*)&raw.y;
    float2 f0 = __half22float2(h0);
    float2 f1 = __half22float2(h1);
    return make_float4(f0.x, f0.y, f1.x, f1.y);
}
__device__ __forceinline__ void st_half4(__half* p, float a, float b, float c, float d) {
    __half2 h0 = __floats2half2_rn(a, b);
    __half2 h1 = __floats2half2_rn(c, d);
    uint2 raw;
    raw.x = *(unsigned int*)&h0;
    raw.y = *(unsigned int*)&h1;
    *(uint2*)p = raw;
}

// ---------------- K1: fold atd into Wa (fp16 out for WMMA) ----------------
__global__ void k_weff2(const float* __restrict__ Wa, const float* __restrict__ ba,
                        const float* __restrict__ atd_pa, const float* __restrict__ atd_da) {
    int gid = blockIdx.x * 256 + threadIdx.x;
    if (gid < 2048) {
        int k = gid >> 4, rem = gid & 15;
        int h = rem & 7;
        const float* att = (rem < 8) ? atd_pa : atd_da;
        float s = 0.f;
        #pragma unroll
        for (int d = 0; d < 16; d++) s += Wa[k * 128 + h * 16 + d] * att[h * 16 + d];
        g_weff_ah[k * 16 + rem] = __float2half_rn(s);
    } else if (gid < 2064) {
        int i = gid - 2048, h = i & 7;
        const float* att = (i < 8) ? atd_pa : atd_da;
        float s = 0.f;
        #pragma unroll
        for (int d = 0; d < 16; d++) s += ba[h * 16 + d] * att[h * 16 + d];
        g_boff_a[i] = s;
    }
}

// ---------------- K1b: Wk, Wp, Wd -> fp16 ----------------
__global__ void k_wprep(const float* __restrict__ Wk, const float* __restrict__ Wp,
                        const float* __restrict__ Wd) {
    int i = blockIdx.x * 256 + threadIdx.x;
    if (i < 16384) g_wk_h[i] = __float2half_rn(Wk[i]);
    else if (i < 24576) g_wp_h[i - 16384] = __float2half_rn(Wp[i - 16384]);
    else if (i < 32768) g_wd_h[i - 24576] = __float2half_rn(Wd[i - 24576]);
}

// ---------------- K2: WMMA adm scalars  ad[128 rows][16] = x[128][128] @ weff[128][16] ----
#define ADW_SMEM (34816 + 6144 + 10240 + 64)
__global__ __launch_bounds__(256) void k_adw(
        const float* __restrict__ x, const __half* __restrict__ weffh,
        const float* __restrict__ boff, float* __restrict__ ad, int N) {
    extern __shared__ char sma[];
    __half* sX = (__half*)sma;                     // 128 x 136
    __half* sW = (__half*)(sma + 34816);           // 128 x 24
    float*  sC = (float*)(sma + 34816 + 6144);     // 128 x 20
    float*  bo = (float*)(sma + 34816 + 6144 + 10240); // 16
    int tid = threadIdx.x;
    int base = blockIdx.x * 128;
    if (tid < 16) bo[tid] = boff[tid];
    // stage weff (128x16)
    {
        int k = tid >> 1, c8 = (tid & 1) * 8;
        *(uint4*)&sW[k * 24 + c8] = *(const uint4*)&weffh[k * 16 + c8];
    }
    // stage x (128x128 fp32 -> fp16)
    #pragma unroll
    for (int it = 0; it < 16; it++) {
        int chunk = tid + it * 256;
        int r = chunk >> 5, c4 = (chunk & 31) * 4;
        float4 v = make_float4(0.f, 0.f, 0.f, 0.f);
        if (base + r < N) v = *(const float4*)&x[(size_t)(base + r) * 128 + c4];
        __half2 pa = __floats2half2_rn(v.x, v.y);
        __half2 pb = __floats2half2_rn(v.z, v.w);
        uint2 pk;
        pk.x = *(unsigned int*)&pa;
        pk.y = *(unsigned int*)&pb;
        *(uint2*)&sX[r * 136 + c4] = pk;
    }
    __syncthreads();
    int w = tid >> 5;
    wmma::fragment<wmma::accumulator, 16, 16, 16, float> acc;
    wmma::fill_fragment(acc, 0.f);
    #pragma unroll
    for (int k = 0; k < 8; k++) {
        wmma::fragment<wmma::matrix_a, 16, 16, 16, __half, wmma::row_major> af;
        wmma::load_matrix_sync(af, &sX[(w * 16) * 136 + k * 16], 136);
        wmma::fragment<wmma::matrix_b, 16, 16, 16, __half, wmma::row_major> bf;
        wmma::load_matrix_sync(bf, &sW[(k * 16) * 24], 24);
        wmma::mma_sync(acc, af, bf, acc);
    }
    wmma::store_matrix_sync(&sC[(w * 16) * 20], acc, 20, wmma::mem_row_major);
    __syncthreads();
    // epilogue: 2 threads per row
    int r = tid >> 1, half = tid & 1;
    int gr = base + r;
    if (gr < N) {
        int c0 = half * 8;
        float4 v0, v1;
        v0.x = sC[r * 20 + c0 + 0] + bo[c0 + 0];
        v0.y = sC[r * 20 + c0 + 1] + bo[c0 + 1];
        v0.z = sC[r * 20 + c0 + 2] + bo[c0 + 2];
        v0.w = sC[r * 20 + c0 + 3] + bo[c0 + 3];
        v1.x = sC[r * 20 + c0 + 4] + bo[c0 + 4];
        v1.y = sC[r * 20 + c0 + 5] + bo[c0 + 5];
        v1.z = sC[r * 20 + c0 + 6] + bo[c0 + 6];
        v1.w = sC[r * 20 + c0 + 7] + bo[c0 + 7];
        *(float4*)&ad[(size_t)gr * 16 + c0]     = v0;
        *(float4*)&ad[(size_t)gr * 16 + c0 + 4] = v1;
    }
}

// ---------------- K3: WMMA projection + fused a_s ----------------
#define PROJW_SMEM (33792 + 512 + 512)
__global__ __launch_bounds__(256) void k_projw(
        const float* __restrict__ x0, const float* __restrict__ x1,
        const __half* __restrict__ W0h, const __half* __restrict__ W1h,
        const float* __restrict__ b0, const float* __restrict__ b1,
        const float* __restrict__ ats0, const float* __restrict__ ats1,
        __half* __restrict__ h0, __half* __restrict__ h1,
        float* __restrict__ as0, float* __restrict__ as1, int N0, int N1) {
    extern __shared__ char sm[];
    __half* sW = (__half*)sm;             // 64 x 136
    __half* sX = (__half*)(sm + 17408);   // 64 x 72
    float* sC  = (float*)sm;              // 64 x 132 (reuse after MMA)
    float* bias = (float*)(sm + 33792);
    float* atts = (float*)(sm + 33792 + 512);
    const float* x    = blockIdx.y ? x1 : x0;
    const __half* Wh  = blockIdx.y ? W1h : W0h;
    const float* b    = blockIdx.y ? b1 : b0;
    const float* ats  = blockIdx.y ? ats1 : ats0;
    __half* h         = blockIdx.y ? h1 : h0;
    float* as_out     = blockIdx.y ? as1 : as0;
    int N             = blockIdx.y ? N1 : N0;
    int base = blockIdx.x * 64;
    if (base >= N) return;
    int tid = threadIdx.x;
    if (tid < 128) { bias[tid] = b[tid]; atts[tid] = ats[tid]; }
    #pragma unroll
    for (int it = 0; it < 4; it++) {
        int chunk = tid + it * 256;
        int k = chunk >> 4, c8 = (chunk & 15) * 8;
        *(uint4*)&sW[k * 136 + c8] = *(const uint4*)&Wh[k * 128 + c8];
    }
    #pragma unroll
    for (int it = 0; it < 4; it++) {
        int chunk = tid + it * 256;
        int r = chunk >> 4, c4 = (chunk & 15) * 4;
        float4 v = make_float4(0.f, 0.f, 0.f, 0.f);
        if (base + r < N) v = *(const float4*)&x[(size_t)(base + r) * 64 + c4];
        __half2 pa = __floats2half2_rn(v.x, v.y);
        __half2 pb = __floats2half2_rn(v.z, v.w);
        uint2 pk;
        pk.x = *(unsigned int*)&pa;
        pk.y = *(unsigned int*)&pb;
        *(uint2*)&sX[r * 72 + c4] = pk;
    }
    __syncthreads();
    int w = tid >> 5;
    int rB = (w & 3) * 16;
    int cB = (w >> 2) * 64;
    wmma::fragment<wmma::accumulator, 16, 16, 16, float> acc[4];
    #pragma unroll
    for (int c = 0; c < 4; c++) wmma::fill_fragment(acc[c], 0.f);
    #pragma unroll
    for (int k = 0; k < 4; k++) {
        wmma::fragment<wmma::matrix_a, 16, 16, 16, __half, wmma::row_major> af;
        wmma::load_matrix_sync(af, &sX[rB * 72 + k * 16], 72);
        #pragma unroll
        for (int c = 0; c < 4; c++) {
            wmma::fragment<wmma::matrix_b, 16, 16, 16, __half, wmma::row_major> bf;
            wmma::load_matrix_sync(bf, &sW[(k * 16) * 136 + cB + c * 16], 136);
            wmma::mma_sync(acc[c], af, bf, acc[c]);
        }
    }
    __syncthreads();
    #pragma unroll
    for (int c = 0; c < 4; c++)
        wmma::store_matrix_sync(&sC[rB * 132 + cB + c * 16], acc[c], 132, wmma::mem_row_major);
    __syncthreads();
    int r = tid >> 2, q = tid & 3;
    int gr = base + r;
    if (gr < N) {
        int c0 = q * 32;
        float p0 = 0.f, p1 = 0.f;
        __align__(16) __half hbuf[32];
        #pragma unroll
        for (int c = 0; c < 16; c++) {
            float v = sC[r * 132 + c0 + c] + bias[c0 + c];
            hbuf[c] = __float2half_rn(v);
            p0 += v * atts[c0 + c];
        }
        #pragma unroll
        for (int c = 16; c < 32; c++) {
            float v = sC[r * 132 + c0 + c] + bias[c0 + c];
            hbuf[c] = __float2half_rn(v);
            p1 += v * atts[c0 + c];
        }
        uint4* dst = (uint4*)&h[(size_t)gr * 128 + c0];
        const uint4* srcb = (const uint4*)hbuf;
        dst[0] = srcb[0]; dst[1] = srcb[1]; dst[2] = srcb[2]; dst[3] = srcb[3];
        as_out[(size_t)gr * 8 + 2 * q]     = p0;
        as_out[(size_t)gr * 8 + 2 * q + 1] = p1;
    }
}

// ---------------- CSR build ----------------
__global__ void k_hist(const int* __restrict__ dst1, const int* __restrict__ dst2,
                       int* __restrict__ deg, int E1, int E2) {
    int e = blockIdx.x * 256 + threadIdx.x;
    if (e < E1) atomicAdd(&deg[dst1[e]], 1);
    else if (e < E1 + E2) atomicAdd(&deg[NA_MAX + dst2[e - E1]], 1);
}

__global__ void k_scan_a(const int* __restrict__ degb, int* __restrict__ partb,
                         int* __restrict__ csumb, int n) {
    const int* deg = degb + blockIdx.y * NA_MAX;
    int* part = partb + blockIdx.y * NA_MAX;
    int* csum = csumb + blockIdx.y * 512;
    __shared__ int wsum[8];
    int tid = threadIdx.x;
    int base = blockIdx.x * 1024 + tid * 4;
    int v0 = 0, v1 = 0, v2 = 0, v3 = 0;
    if (base + 0 < n) v0 = deg[base + 0];
    if (base + 1 < n) v1 = deg[base + 1];
    if (base + 2 < n) v2 = deg[base + 2];
    if (base + 3 < n) v3 = deg[base + 3];
    int s = v0 + v1 + v2 + v3;
    int incl = s;
    #pragma unroll
    for (int o = 1; o < 32; o <<= 1) {
        int t = __shfl_up_sync(0xffffffffu, incl, o);
        if ((tid & 31) >= o) incl += t;
    }
    if ((tid & 31) == 31) wsum[tid >> 5] = incl;
    __syncthreads();
    if (tid < 8) {
        int w = wsum[tid];
        #pragma unroll
        for (int o = 1; o < 8; o <<= 1) {
            int t = __shfl_up_sync(0xffu, w, o);
            if (tid >= o) w += t;
        }
        wsum[tid] = w;
    }
    __syncthreads();
    int blockoff = (tid >= 32) ? wsum[(tid >> 5) - 1] : 0;
    int excl = blockoff + incl - s;
    if (base + 0 < n) part[base + 0] = excl;
    if (base + 1 < n) part[base + 1] = excl + v0;
    if (base + 2 < n) part[base + 2] = excl + v0 + v1;
    if (base + 3 < n) part[base + 3] = excl + v0 + v1 + v2;
    if (tid == 255) csum[blockIdx.x] = blockoff + incl;
}

__global__ void k_scan_b(int* __restrict__ csumb, int nc) {
    int* csum = csumb + blockIdx.x * 512;
    __shared__ int ws[16];
    int tid = threadIdx.x;
    int v = (tid < nc) ? csum[tid] : 0;
    int incl = v;
    #pragma unroll
    for (int o = 1; o < 32; o <<= 1) {
        int t = __shfl_up_sync(0xffffffffu, incl, o);
        if ((tid & 31) >= o) incl += t;
    }
    if ((tid & 31) == 31) ws[tid >> 5] = incl;
    __syncthreads();
    if (tid < 16) {
        int w = ws[tid];
        #pragma unroll
        for (int o = 1; o < 16; o <<= 1) {
            int t = __shfl_up_sync(0xffffu, w, o);
            if (tid >= o) w += t;
        }
        ws[tid] = w;
    }
    __syncthreads();
    int add = (tid >= 32) ? ws[(tid >> 5) - 1] : 0;
    incl += add;
    if (tid < nc) csum[tid] = incl - v;
}

__global__ void k_scan_c(const int* __restrict__ partb, const int* __restrict__ csumb,
                         int* __restrict__ offb, int* __restrict__ curb, int n) {
    int y = blockIdx.y;
    int i = blockIdx.x * 256 + threadIdx.x;
    if (i < n) {
        int o = partb[y * NA_MAX + i] + csumb[y * 512 + (i >> 10)];
        offb[y * NA_MAX + i] = o;
        curb[y * NA_MAX + i] = o;
    }
}

__global__ void k_scatter(const int* __restrict__ src1, const int* __restrict__ dst1,
                          const int* __restrict__ src2, const int* __restrict__ dst2,
                          int* __restrict__ cur, int* __restrict__ csr, int E1, int E2) {
    int e = blockIdx.x * 256 + threadIdx.x;
    if (e < E1) {
        int pos = atomicAdd(&cur[dst1[e]], 1);
        csr[pos] = src1[e];
    } else if (e < E1 + E2) {
        int i = e - E1;
        int pos = atomicAdd(&cur[NA_MAX + dst2[i]], 1);
        csr[(size_t)E_MAX + pos] = src2[i];
    }
}

// ---------------- K6: fused softmax+agg+relu, predicated MLP tail ----------------
__global__ __launch_bounds__(256) void k_agg(
        const int* __restrict__ csrb, const int* __restrict__ offb, const int* __restrict__ degb,
        const float* __restrict__ as0, const float* __restrict__ as1,
        const float* __restrict__ ad,
        const __half* __restrict__ h0, const __half* __restrict__ h1,
        __half* __restrict__ o0, __half* __restrict__ o1, int N) {
    int d = (blockIdx.x * 256 + threadIdx.x) >> 5;
    if (d >= N) return;
    int y = blockIdx.y;
    const int* csr = csrb + (size_t)y * E_MAX;
    const int* off = offb + y * NA_MAX;
    const int* deg = degb + y * NA_MAX;
    const float* as = y ? as1 : as0;
    const __half* h = y ? h1 : h0;
    __half* o       = y ? o1 : o0;
    int lane = threadIdx.x & 31;
    int head = lane >> 2;
    float adv = ad[(size_t)d * 16 + y * 8 + head];
    int st = off[d], dg = deg[d];
    float ax = 0.f, ay = 0.f, az = 0.f, aw = 0.f, den = 0.f;
    int i = 0;
    int full = dg & ~3;
    for (; i < full; i += 4) {
        int s0 = csr[st + i], s1 = csr[st + i + 1], s2 = csr[st + i + 2], s3 = csr[st + i + 3];
        float e0 = as[(size_t)s0 * 8 + head];
        float e1 = as[(size_t)s1 * 8 + head];
        float e2 = as[(size_t)s2 * 8 + head];
        float e3 = as[(size_t)s3 * 8 + head];
        float4 h0v = ld_half4(h + (size_t)s0 * 128 + lane * 4);
        float4 h1v = ld_half4(h + (size_t)s1 * 128 + lane * 4);
        float4 h2v = ld_half4(h + (size_t)s2 * 128 + lane * 4);
        float4 h3v = ld_half4(h + (size_t)s3 * 128 + lane * 4);
        float w0 = leaky_exp(e0 + adv), w1 = leaky_exp(e1 + adv);
        float w2 = leaky_exp(e2 + adv), w3 = leaky_exp(e3 + adv);
        den += (w0 + w1) + (w2 + w3);
        ax += w0 * h0v.x + w1 * h1v.x + w2 * h2v.x + w3 * h3v.x;
        ay += w0 * h0v.y + w1 * h1v.y + w2 * h2v.y + w3 * h3v.y;
        az += w0 * h0v.z + w1 * h1v.z + w2 * h2v.z + w3 * h3v.z;
        aw += w0 * h0v.w + w1 * h1v.w + w2 * h2v.w + w3 * h3v.w;
    }
    int rem = dg - i;
    if (rem > 0) {
        // predicated 3-wide tail: invalid slots alias edge 0 (cache hit), weight 0
        int s0 = csr[st + i];
        int s1 = (rem > 1) ? csr[st + i + 1] : s0;
        int s2 = (rem > 2) ? csr[st + i + 2] : s0;
        float e0 = as[(size_t)s0 * 8 + head];
        float e1 = as[(size_t)s1 * 8 + head];
        float e2 = as[(size_t)s2 * 8 + head];
        float4 h0v = ld_half4(h + (size_t)s0 * 128 + lane * 4);
        float4 h1v = ld_half4(h + (size_t)s1 * 128 + lane * 4);
        float4 h2v = ld_half4(h + (size_t)s2 * 128 + lane * 4);
        float w0 = leaky_exp(e0 + adv);
        float w1 = (rem > 1) ? leaky_exp(e1 + adv) : 0.f;
        float w2 = (rem > 2) ? leaky_exp(e2 + adv) : 0.f;
        den += w0 + w1 + w2;
        ax += w0 * h0v.x + w1 * h1v.x + w2 * h2v.x;
        ay += w0 * h0v.y + w1 * h1v.y + w2 * h2v.y;
        az += w0 * h0v.z + w1 * h1v.z + w2 * h2v.z;
        aw += w0 * h0v.w + w1 * h1v.w + w2 * h2v.w;
    }
    float inv = __fdividef(1.f, den + 1e-16f);
    st_half4(o + (size_t)d * 128 + lane * 4,
             fmaxf(ax * inv, 0.f), fmaxf(ay * inv, 0.f),
             fmaxf(az * inv, 0.f), fmaxf(aw * inv, 0.f));
}

// ---------------- K7: WMMA semantic GEMM + tanh colsums + la ----------------
#define SEMW_SMEM_BYTES (69632 + 512 + 1024)
__global__ __launch_bounds__(256) void k_semw(
        const __half* __restrict__ o0, const __half* __restrict__ o1,
        const __half* __restrict__ wkh, const float* __restrict__ bk,
        const float* __restrict__ Wl,
        float* __restrict__ wpart, float* __restrict__ la, int N) {
    extern __shared__ char smw[];
    __half* sA = (__half*)smw;            // 128 x 136
    __half* sB = (__half*)(smw + 34816);  // 128 x 136
    float* sC = (float*)smw;               // 128 x 132 (reuse)
    float* colacc = (float*)(smw + 69632);
    float* Wls = (float*)(smw + 69632 + 512);
    const __half* obf = blockIdx.y ? o1 : o0;
    float* lap = la + (size_t)blockIdx.y * NA_MAX * 2;
    int tid = threadIdx.x;
    int base = blockIdx.x * 128;
    if (tid < 128) colacc[tid] = 0.f;
    if (tid >= 128 && tid < 256) {
        int c = tid - 128;
        Wls[c * 2] = Wl[c * 2];
        Wls[c * 2 + 1] = Wl[c * 2 + 1];
    }
    #pragma unroll
    for (int it = 0; it < 8; it++) {
        int chunk = tid + it * 256;
        int k = chunk >> 4, n8 = (chunk & 15) * 8;
        *(uint4*)&sB[k * 136 + n8] = *(const uint4*)&wkh[k * 128 + n8];
    }
    #pragma unroll
    for (int it = 0; it < 8; it++) {
        int chunk = tid + it * 256;
        int r = chunk >> 4, c8 = (chunk & 15) * 8;
        uint4 v = make_uint4(0u, 0u, 0u, 0u);
        if (base + r < N) v = *(const uint4*)&obf[(size_t)(base + r) * 128 + c8];
        *(uint4*)&sA[r * 136 + c8] = v;
    }
    __syncthreads();
    int w = tid >> 5;
    wmma::fragment<wmma::accumulator, 16, 16, 16, float> acc[8];
    #pragma unroll
    for (int c = 0; c < 8; c++) wmma::fill_fragment(acc[c], 0.f);
    #pragma unroll
    for (int k = 0; k < 8; k++) {
        wmma::fragment<wmma::matrix_a, 16, 16, 16, __half, wmma::row_major> af;
        wmma::load_matrix_sync(af, &sA[(w * 16) * 136 + k * 16], 136);
        #pragma unroll
        for (int c = 0; c < 8; c++) {
            wmma::fragment<wmma::matrix_b, 16, 16, 16, __half, wmma::row_major> bf;
            wmma::load_matrix_sync(bf, &sB[(k * 16) * 136 + c * 16], 136);
            wmma::mma_sync(acc[c], af, bf, acc[c]);
        }
    }
    __syncthreads();
    {
        int r = tid >> 1, half = tid & 1;
        float s0 = 0.f, s1 = 0.f;
        int c0 = half * 64;
        #pragma unroll 16
        for (int c = c0; c < c0 + 64; c++) {
            float a = __half2float(sA[r * 136 + c]);
            s0 += a * Wls[c * 2];
            s1 += a * Wls[c * 2 + 1];
        }
        s0 += __shfl_xor_sync(0xffffffffu, s0, 1);
        s1 += __shfl_xor_sync(0xffffffffu, s1, 1);
        if (half == 0 && base + r < N) {
            lap[(size_t)(base + r) * 2]     = s0;
            lap[(size_t)(base + r) * 2 + 1] = s1;
        }
    }
    __syncthreads();
    #pragma unroll
    for (int c = 0; c < 8; c++)
        wmma::store_matrix_sync(&sC[(w * 16) * 132 + c * 16], acc[c], 132, wmma::mem_row_major);
    __syncthreads();
    int col = tid & 127;
    int rs = (tid >> 7) * 64;
    int valid = N - base; if (valid > 128) valid = 128;
    float bkv = bk[col];
    float sum = 0.f;
    int rend = rs + 64; if (rend > valid) rend = valid;
    for (int r = rs; r < rend; r++)
        sum += tanh_f(sC[r * 132 + col] + bkv);
    atomicAdd(&colacc[col], sum);
    __syncthreads();
    if (tid < 128) atomicAdd(&wpart[blockIdx.y * 128 + tid], colacc[tid]);
}

// ---------------- K8: beta ----------------
__global__ void k_beta(const float* __restrict__ wpart, const float* __restrict__ q,
                       float invN, float* __restrict__ beta) {
    __shared__ float sh[8];
    int tid = threadIdx.x;
    float qv = q[tid];
    float v0 = wpart[tid] * invN * qv;
    float v1 = wpart[128 + tid] * invN * qv;
    #pragma unroll
    for (int o = 16; o; o >>= 1) {
        v0 += __shfl_xor_sync(0xffffffffu, v0, o);
        v1 += __shfl_xor_sync(0xffffffffu, v1, o);
    }
    int w = tid >> 5;
    if ((tid & 31) == 0) { sh[w] = v0; sh[4 + w] = v1; }
    __syncthreads();
    if (tid == 0) {
        float s0 = sh[0] + sh[1] + sh[2] + sh[3];
        float s1 = sh[4] + sh[5] + sh[6] + sh[7];
        float m = fmaxf(s0, s1);
        float e0 = __expf(s0 - m), e1 = __expf(s1 - m);
        float inv = 1.f / (e0 + e1);
        beta[0] = e0 * inv;
        beta[1] = e1 * inv;
    }
}

// ---------------- K9: final ----------------
__global__ __launch_bounds__(256) void k_final(
        const float* __restrict__ la, const float* __restrict__ bl,
        const float* __restrict__ beta, float* __restrict__ out, int N) {
    int n = blockIdx.x * 256 + threadIdx.x;
    if (n >= N) return;
    float b0 = beta[0], b1 = beta[1];
    float2 lp = *(const float2*)(la + (size_t)n * 2);
    float2 ld = *(const float2*)(la + (size_t)NA_MAX * 2 + (size_t)n * 2);
    float l0 = b0 * lp.x + b1 * ld.x + bl[0];
    float l1 = b0 * lp.y + b1 * ld.y + bl[1];
    float m = fmaxf(l0, l1);
    float e0 = __expf(l0 - m), e1 = __expf(l1 - m);
    float inv = 1.f / (e0 + e1);
    out[(size_t)n * 2]     = e0 * inv;
    out[(size_t)n * 2 + 1] = e1 * inv;
}

// ---------------- launch ----------------
extern "C" void kernel_launch(void* const* d_in, const int* in_sizes, int n_in,
                              void* d_out, int out_size) {
    const float* x_adm  = (const float*)d_in[0];
    const float* x_pat  = (const float*)d_in[1];
    const float* x_diag = (const float*)d_in[2];
    const int* e_pa_src = (const int*)d_in[3];
    const int* e_pa_dst = (const int*)d_in[4];
    const int* e_da_src = (const int*)d_in[5];
    const int* e_da_dst = (const int*)d_in[6];
    const float* Wa = (const float*)d_in[7];
    const float* ba = (const float*)d_in[8];
    const float* Wp = (const float*)d_in[9];
    const float* bp = (const float*)d_in[10];
    const float* Wd = (const float*)d_in[11];
    const float* bd = (const float*)d_in[12];
    const float* ats_pa = (const float*)d_in[13];
    const float* atd_pa = (const float*)d_in[14];
    const float* ats_da = (const float*)d_in[15];
    const float* atd_da = (const float*)d_in[16];
    const float* Wk = (const float*)d_in[17];
    const float* bk = (const float*)d_in[18];
    const float* q  = (const float*)d_in[19];
    const float* Wl = (const float*)d_in[20];
    const float* bl = (const float*)d_in[21];
    float* out = (float*)d_out;

    int Na = in_sizes[0] / 128;
    int Np = in_sizes[1] / 64;
    int Nd = in_sizes[2] / 64;
    int E1 = in_sizes[3];
    int E2 = in_sizes[5];

    void *p_hp, *p_hd, *p_as_pa, *p_as_da, *p_ad, *p_o_pa, *p_o_da, *p_wpart, *p_beta;
    void *p_wk_h, *p_wp_h, *p_wd_h, *p_la;
    void *p_weff_ah, *p_boff_a;
    void *p_deg, *p_part, *p_csum, *p_off, *p_cur, *p_csr;
    cudaGetSymbolAddress(&p_hp, g_hp);
    cudaGetSymbolAddress(&p_hd, g_hd);
    cudaGetSymbolAddress(&p_as_pa, g_as_pa);
    cudaGetSymbolAddress(&p_as_da, g_as_da);
    cudaGetSymbolAddress(&p_ad, g_ad);
    cudaGetSymbolAddress(&p_o_pa, g_o_pa);
    cudaGetSymbolAddress(&p_o_da, g_o_da);
    cudaGetSymbolAddress(&p_wk_h, g_wk_h);
    cudaGetSymbolAddress(&p_wp_h, g_wp_h);
    cudaGetSymbolAddress(&p_wd_h, g_wd_h);
    cudaGetSymbolAddress(&p_la, g_la);
    cudaGetSymbolAddress(&p_wpart, g_wpart);
    cudaGetSymbolAddress(&p_beta, g_beta);
    cudaGetSymbolAddress(&p_weff_ah, g_weff_ah);
    cudaGetSymbolAddress(&p_boff_a, g_boff_a);
    cudaGetSymbolAddress(&p_deg, g_deg);
    cudaGetSymbolAddress(&p_part, g_part);
    cudaGetSymbolAddress(&p_csum, g_csum);
    cudaGetSymbolAddress(&p_off, g_off);
    cudaGetSymbolAddress(&p_cur, g_cur);
    cudaGetSymbolAddress(&p_csr, g_csr);

    int nchunks = (Na + 1023) / 1024;
    int maxPD = (Np > Nd) ? Np : Nd;

    cudaMemsetAsync(p_wpart, 0, 256 * sizeof(float));
    cudaMemsetAsync(p_deg, 0, (size_t)2 * NA_MAX * sizeof(int));

    // weights
    k_weff2<<<9, 256>>>(Wa, ba, atd_pa, atd_da);
    k_wprep<<<128, 256>>>(Wk, Wp, Wd);

    // adm attention scalars (WMMA)
    cudaFuncSetAttribute(k_adw, cudaFuncAttributeMaxDynamicSharedMemorySize, ADW_SMEM);
    k_adw<<<(Na + 127) / 128, 256, ADW_SMEM>>>(x_adm,
        (const __half*)p_weff_ah, (const float*)p_boff_a, (float*)p_ad, Na);

    // WMMA projections + fused a_s
    {
        cudaFuncSetAttribute(k_projw, cudaFuncAttributeMaxDynamicSharedMemorySize, PROJW_SMEM);
        dim3 gP((maxPD + 63) / 64, 2);
        k_projw<<<gP, 256, PROJW_SMEM>>>(x_pat, x_diag,
            (const __half*)p_wp_h, (const __half*)p_wd_h, bp, bd, ats_pa, ats_da,
            (__half*)p_hp, (__half*)p_hd,
            (float*)p_as_pa, (float*)p_as_da, Np, Nd);
    }

    // CSR build
    k_hist<<<(E1 + E2 + 255) / 256, 256>>>(e_pa_dst, e_da_dst, (int*)p_deg, E1, E2);
    {
        dim3 gs(nchunks, 2);
        k_scan_a<<<gs, 256>>>((const int*)p_deg, (int*)p_part, (int*)p_csum, Na);
        k_scan_b<<<2, 512>>>((int*)p_csum, nchunks);
        dim3 gc((Na + 255) / 256, 2);
        k_scan_c<<<gc, 256>>>((const int*)p_part, (const int*)p_csum,
                              (int*)p_off, (int*)p_cur, Na);
    }
    k_scatter<<<(E1 + E2 + 255) / 256, 256>>>(e_pa_src, e_pa_dst, e_da_src, e_da_dst,
                                              (int*)p_cur, (int*)p_csr, E1, E2);

    // fused aggregation
    {
        dim3 ga((Na * 32 + 255) / 256, 2);
        k_agg<<<ga, 256>>>((const int*)p_csr, (const int*)p_off, (const int*)p_deg,
            (const float*)p_as_pa, (const float*)p_as_da, (const float*)p_ad,
            (const __half*)p_hp, (const __half*)p_hd,
            (__half*)p_o_pa, (__half*)p_o_da, Na);
    }

    // semantic GEMM + la projection
    cudaFuncSetAttribute(k_semw, cudaFuncAttributeMaxDynamicSharedMemorySize, SEMW_SMEM_BYTES);
    dim3 semgrid((Na + 127) / 128, 2);
    k_semw<<<semgrid, 256, SEMW_SMEM_BYTES>>>((const __half*)p_o_pa,
        (const __half*)p_o_da, (const __half*)p_wk_h, bk, Wl,
        (float*)p_wpart, (float*)p_la, Na);

    // beta + final
    k_beta<<<1, 128>>>((const float*)p_wpart, q, 1.0f / (float)Na, (float*)p_beta);
    k_final<<<(Na + 255) / 256, 256>>>((const float*)p_la, bl,
        (const float*)p_beta, out, Na);
}